// round 12
// baseline (speedup 1.0000x reference)
#include <cuda_runtime.h>
#include <cstdint>
#include <cstddef>

#define NPT    4096
#define BBATCH 4
#define NPTS   (BBATCH*NPT)
#define KNB    20
#define NEGINF (-3.4e38f)
#define KCAP   256
#define KNN_WPB 16

// ------------------------- device scratch -------------------------
__device__ float  g_pd[(size_t)BBATCH*NPT*NPT];   // pairwise (64-dim KNNs)
__device__ int    g_idx[NPTS*KNB];
__device__ float4 g_pts4[NPTS];
__device__ float4 g_p4[NPTS];
__device__ float  g_sq[NPTS];
__device__ float  g_aA[NPTS*64];
__device__ float  g_aB[NPTS*64];
__device__ float  g_t[(size_t)NPTS*128];
__device__ float  g_cat192[(size_t)NPTS*192];     // x1|x2|x3
__device__ float  g_c2[(size_t)NPTS*512];
__device__ float  g_c3[(size_t)NPTS*256];
__device__ float  g_tvec[BBATCH*1024];
__device__ float  g_gvec[BBATCH*1024];
__device__ float  g_fc1[BBATCH*512];
__device__ float  g_fc2[BBATCH*256];
__device__ float  g_xf[BBATCH*9];
__device__ float  g_gterm[BBATCH*512];

// ------------------------- small kernels -------------------------
__global__ void k_zero() {
    int t = blockIdx.x*blockDim.x + threadIdx.x;
    if (t < BBATCH*1024) { g_tvec[t] = 0.f; g_gvec[t] = 0.f; }
}

__global__ void k_pts_sq(const float* __restrict__ x) {
    int i = blockIdx.x*blockDim.x + threadIdx.x;
    if (i >= NPTS) return;
    float a = x[i*6+0], b = x[i*6+1], c = x[i*6+2];
    g_pts4[i] = make_float4(a, b, c, a*a + b*b + c*c);
}

__global__ void k_transform() {
    int n = blockIdx.x*blockDim.x + threadIdx.x;
    if (n >= NPTS) return;
    int b = n >> 12;
    float4 q = g_pts4[n];
    const float* f = g_xf + b*9;
    float p0 = q.x*f[0] + q.y*f[3] + q.z*f[6];
    float p1 = q.x*f[1] + q.y*f[4] + q.z*f[7];
    float p2 = q.x*f[2] + q.y*f[5] + q.z*f[8];
    g_p4[n] = make_float4(p0, p1, p2, p0*p0 + p1*p1 + p2*p2);
}

__global__ void k_sq64(const float* __restrict__ src, int ld) {
    int gt = blockIdx.x*blockDim.x + threadIdx.x;
    int w = gt >> 5, lane = gt & 31;
    if (w >= NPTS) return;
    const float* r = src + (size_t)w*ld;
    float s = r[lane]*r[lane] + r[lane+32]*r[lane+32];
    #pragma unroll
    for (int off = 16; off; off >>= 1) s += __shfl_down_sync(0xffffffffu, s, off);
    if (lane == 0) g_sq[w] = s;
}

// ------------------------- fast exact KNN (K=20) -------------------------
template<bool PD>
__global__ void __launch_bounds__(512) k_knn(const float4* __restrict__ P4) {
    extern __shared__ float dyn[];
    int w = threadIdx.x >> 5, lane = threadIdx.x & 31;
    int row = blockIdx.x*KNN_WPB + w;
    int b = row >> 12, i = row & (NPT-1);

    float4* stash = (float4*)dyn;
    float*  bufv;
    int*    bufj;
    if (PD) { bufv = dyn + w*2*KCAP; }
    else    { bufv = dyn + NPT*4 + w*2*KCAP; }
    bufj = (int*)(bufv + KCAP);

    float xi2 = 0.f, yi2 = 0.f, zi2 = 0.f, ci = 0.f;
    const float4* pr = nullptr;
    if (!PD) {
        const float4* src = P4 + (size_t)b*NPT;
        for (int t = threadIdx.x; t < NPT; t += 512) stash[t] = src[t];
        __syncthreads();
        float4 pi = stash[i];
        xi2 = 2.f*pi.x; yi2 = 2.f*pi.y; zi2 = 2.f*pi.z; ci = -pi.w;
    } else {
        pr = (const float4*)(g_pd + (size_t)row*NPT);
    }

    float mx = NEGINF;
    if (!PD) {
        for (int t = 0; t < 128; t++) {
            float4 pj = stash[lane + t*32];
            float d = fmaf(xi2, pj.x, fmaf(yi2, pj.y, fmaf(zi2, pj.z, ci - pj.w)));
            mx = fmaxf(mx, d);
        }
    } else {
        for (int t = 0; t < 32; t++) {
            float4 v = pr[lane + t*32];
            mx = fmaxf(mx, fmaxf(fmaxf(v.x, v.y), fmaxf(v.z, v.w)));
        }
    }

    float tau = NEGINF;
    float tv = mx;
    #pragma unroll
    for (int r = 0; r < 20; r++) {
        float bv = tv;
        #pragma unroll
        for (int off = 16; off; off >>= 1)
            bv = fmaxf(bv, __shfl_xor_sync(0xffffffffu, bv, off));
        unsigned m = __ballot_sync(0xffffffffu, tv == bv);
        if (lane == (__ffs(m) - 1)) tv = NEGINF;
        tau = bv;
    }

    unsigned lmask = (1u << lane) - 1u;
    int total = 0;
    if (!PD) {
        for (int t = 0; t < 128; t++) {
            int j = lane + t*32;
            float4 pj = stash[j];
            float d = fmaf(xi2, pj.x, fmaf(yi2, pj.y, fmaf(zi2, pj.z, ci - pj.w)));
            bool keep = (d >= tau);
            unsigned mk = __ballot_sync(0xffffffffu, keep);
            if (keep) {
                int pos = total + __popc(mk & lmask);
                if (pos < KCAP) { bufv[pos] = d; bufj[pos] = j; }
            }
            total += __popc(mk);
        }
    } else {
        for (int t = 0; t < 32; t++) {
            int c = lane + t*32;
            float4 v = pr[c];
            float vals[4] = {v.x, v.y, v.z, v.w};
            #pragma unroll
            for (int e = 0; e < 4; e++) {
                bool keep = (vals[e] >= tau);
                unsigned mk = __ballot_sync(0xffffffffu, keep);
                if (keep) {
                    int pos = total + __popc(mk & lmask);
                    if (pos < KCAP) { bufv[pos] = vals[e]; bufj[pos] = c*4 + e; }
                }
                total += __popc(mk);
            }
        }
    }

    int* orow = g_idx + row*KNB;

    if (total <= KCAP) {
        int nq = (total + 31) >> 5;
        for (int r = 0; r < KNB; r++) {
            float bv = NEGINF; int bj = 0x7fffffff; int bs = -1;
            for (int q = 0; q < nq; q++) {
                int idx = lane + (q << 5);
                if (idx < total) {
                    float v = bufv[idx]; int j = bufj[idx];
                    if (v > bv || (v == bv && j < bj)) { bv = v; bj = j; bs = idx; }
                }
            }
            float lv0 = bv; int lj0 = bj;
            #pragma unroll
            for (int off = 16; off; off >>= 1) {
                float ov = __shfl_xor_sync(0xffffffffu, bv, off);
                int   oj = __shfl_xor_sync(0xffffffffu, bj, off);
                if (ov > bv || (ov == bv && oj < bj)) { bv = ov; bj = oj; }
            }
            if (lj0 == bj && lv0 == bv && bs >= 0) bufv[bs] = NEGINF;
            if (lane == 0) orow[r] = bj + (b << 12);
        }
    } else {
        float lv[KNB]; int li[KNB];
        #pragma unroll
        for (int q = 0; q < KNB; q++) { lv[q] = NEGINF; li[q] = 0x7fffffff; }
        if (!PD) {
            for (int t = 0; t < 128; t++) {
                int j = lane + t*32;
                float4 pj = stash[j];
                float val = fmaf(xi2, pj.x, fmaf(yi2, pj.y, fmaf(zi2, pj.z, ci - pj.w)));
                if (val > lv[KNB-1]) {
                    #pragma unroll
                    for (int p = KNB-1; p > 0; --p) {
                        bool below = (lv[p] >= val);
                        bool shift = (lv[p-1] < val);
                        float nl = below ? lv[p] : (shift ? lv[p-1] : val);
                        int   ni = below ? li[p] : (shift ? li[p-1] : j);
                        lv[p] = nl; li[p] = ni;
                    }
                    if (lv[0] < val) { lv[0] = val; li[0] = j; }
                }
            }
        } else {
            for (int t = 0; t < 32; t++) {
                int c = lane + t*32;
                float4 v = pr[c];
                float vals[4] = {v.x, v.y, v.z, v.w};
                #pragma unroll
                for (int e = 0; e < 4; e++) {
                    float val = vals[e]; int j = c*4 + e;
                    if (val > lv[KNB-1]) {
                        #pragma unroll
                        for (int p = KNB-1; p > 0; --p) {
                            bool below = (lv[p] >= val);
                            bool shift = (lv[p-1] < val);
                            float nl = below ? lv[p] : (shift ? lv[p-1] : val);
                            int   ni = below ? li[p] : (shift ? li[p-1] : j);
                            lv[p] = nl; li[p] = ni;
                        }
                        if (lv[0] < val) { lv[0] = val; li[0] = j; }
                    }
                }
            }
        }
        for (int r = 0; r < KNB; r++) {
            float bv = lv[0]; int bj = li[0];
            float lv0 = bv; int lj0 = bj;
            #pragma unroll
            for (int off = 16; off; off >>= 1) {
                float ov = __shfl_xor_sync(0xffffffffu, bv, off);
                int   oj = __shfl_xor_sync(0xffffffffu, bj, off);
                if (ov > bv || (ov == bv && oj < bj)) { bv = ov; bj = oj; }
            }
            if (lj0 == bj && lv0 == bv) {
                #pragma unroll
                for (int p = 0; p < KNB-1; p++) { lv[p] = lv[p+1]; li[p] = li[p+1]; }
                lv[KNB-1] = NEGINF; li[KNB-1] = 0x7fffffff;
            }
            if (lane == 0) orow[r] = bj + (b << 12);
        }
    }
}

// ------------------------- edge-conv prep -------------------------
template<int C>
__global__ void k_prep_ab(const float* __restrict__ src, int ld,
                          const float* __restrict__ W, const float* __restrict__ bias) {
    __shared__ float Ws[2*C*64];
    for (int e = threadIdx.x; e < 2*C*64; e += blockDim.x) Ws[e] = W[e];
    __syncthreads();
    int t = blockIdx.x*blockDim.x + threadIdx.x;
    int d = t & 63, n = t >> 6;
    if (n >= NPTS) return;
    const float* xr = src + (size_t)n*ld;
    float a = bias[d], bb = 0.f;
    #pragma unroll
    for (int c = 0; c < C; c++) {
        float xv = xr[c];
        float wt = Ws[c*64+d], wb = Ws[(C+c)*64+d];
        a  += xv*(wt - wb);
        bb += xv*wb;
    }
    g_aA[(size_t)n*64+d] = a;
    g_aB[(size_t)n*64+d] = bb;
}

// e3: out[n,d] = max_k relu(a[n,d] + bnb[idx[n,k],d])
__global__ void k_edge_e3(float* __restrict__ out, int ldo) {
    int t = blockIdx.x*blockDim.x + threadIdx.x;
    int d = t & 63, n = t >> 6;
    if (n >= NPTS) return;
    float a = g_aA[(size_t)n*64+d];
    const int* ir = g_idx + n*KNB;
    float m = 0.f;
    #pragma unroll
    for (int k = 0; k < KNB; k++) m = fmaxf(m, a + g_aB[(size_t)ir[k]*64 + d]);
    out[(size_t)n*ldo + d] = m;
}

// ------------------------- TF32 tensor-core GEMM -------------------------
__device__ __forceinline__ float to_tf32(float x) {
    uint32_t u;
    asm("cvt.rna.tf32.f32 %0, %1;" : "=r"(u) : "f"(x));
    return __uint_as_float(u);
}

__device__ __forceinline__ void mma_tf32(float* c, const uint32_t* a, const uint32_t* b) {
    asm volatile(
        "mma.sync.aligned.m16n8k8.row.col.f32.tf32.tf32.f32 "
        "{%0,%1,%2,%3}, {%4,%5,%6,%7}, {%8,%9}, {%0,%1,%2,%3};\n"
        : "+f"(c[0]), "+f"(c[1]), "+f"(c[2]), "+f"(c[3])
        : "r"(a[0]), "r"(a[1]), "r"(a[2]), "r"(a[3]), "r"(b[0]), "r"(b[1]));
}

#define SM_BUF   4608
#define SM_MMA3  (4*SM_BUF*4)
#define SM_MMA1  (2*SM_BUF*4)

// Block tile 128x128, 8 warps (2M x 4N), warp tile 64x32, k-stage 32.
// Register-prefetch double buffering.
// SPLIT=3: 3xTF32; smem holds (big,small) float2 pairs -> one LDS.64 per fragment pair.
//          A/row-B stride 36 float2; weight-B stride 140 float2 (conflict-free).
// SPLIT=1: single-pass tf32, plain float layout.
// GATHER: A rows are edge rows relu(g_aA[n] + g_aB[g_idx[row]]) (K=64).
// EPI: 0 = bias(+rowadd)+ReLU store; 1 = bias+ReLU+per-batch col max (atomicMax);
//      2 = SYMMETRIC pairwise (triangular grid, z = batch), mirrored tile via smem;
//      3 = gather edge: bias+ReLU, per-point (row/20) atomicMax into out (stride Nd).
template<int EPI, int SPLIT, bool GATHER>
__global__ void __launch_bounds__(256) k_mma(const float* __restrict__ A, int lda,
                                             const float* __restrict__ B, int ldb,
                                             const float* __restrict__ bias,
                                             const float* __restrict__ rowadd,
                                             float* __restrict__ out,
                                             int Kd, int Nd) {
    extern __shared__ float dynsm[];
    float2* A2 = (float2*)dynsm;                 // [128][36] float2
    float2* B2 = (float2*)dynsm + 4608;          // row: [128][36] f2 | weight: [32][140] f2
    float* Ab1 = dynsm;                          // SPLIT==1
    float* Bb1 = dynsm + SM_BUF;                 // SPLIT==1 weight [32][136]
    int m0, n0;
    bool diag = false;
    if (EPI == 2) {
        int tb = blockIdx.x;
        int by = (int)((sqrtf(8.f*tb + 1.f) - 1.f)*0.5f);
        while ((by + 1)*(by + 2)/2 <= tb) by++;
        while (by*(by + 1)/2 > tb) by--;
        int bx = tb - by*(by + 1)/2;
        m0 = by*128; n0 = bx*128;
        diag = (bx == by);
    } else {
        m0 = blockIdx.y*128; n0 = blockIdx.x*128;
    }
    int tid = threadIdx.x;
    int w = tid >> 5, lane = tid & 31;
    int wm = w & 1, wn = w >> 1;
    int g = lane >> 2, t = lane & 3;
    size_t rowbase = (EPI == 2) ? (size_t)blockIdx.z*NPT : 0;

    int a_r  = tid >> 3, a_c4 = (tid & 7)*4;
    int bw_r = tid >> 5, bw_c4 = (tid & 31)*4;

    float4 pA[4], pB[4];

    auto loadA = [&](int kk) {
        #pragma unroll
        for (int i = 0; i < 4; i++) {
            int r = a_r + i*32;
            if (GATHER) {
                unsigned gr = m0 + r;
                unsigned n = gr / 20u;
                int j = g_idx[gr];
                float4 va = *(const float4*)(g_aA + (size_t)n*64 + kk + a_c4);
                float4 vb = *(const float4*)(g_aB + (size_t)j*64 + kk + a_c4);
                pA[i].x = fmaxf(va.x + vb.x, 0.f);
                pA[i].y = fmaxf(va.y + vb.y, 0.f);
                pA[i].z = fmaxf(va.z + vb.z, 0.f);
                pA[i].w = fmaxf(va.w + vb.w, 0.f);
            } else {
                pA[i] = *(const float4*)(A + (rowbase + m0 + r)*lda + kk + a_c4);
            }
        }
    };
    auto loadB = [&](int kk) {
        #pragma unroll
        for (int i = 0; i < 4; i++) {
            if (EPI == 2) {
                int r = a_r + i*32;
                pB[i] = *(const float4*)(B + (rowbase + n0 + r)*ldb + kk + a_c4);
            } else {
                int r = bw_r + i*8;
                pB[i] = *(const float4*)(B + (size_t)(kk + r)*ldb + n0 + bw_c4);
            }
        }
    };

    float acc[4][4][4];
    #pragma unroll
    for (int mt = 0; mt < 4; mt++)
        #pragma unroll
        for (int nt = 0; nt < 4; nt++)
            #pragma unroll
            for (int r = 0; r < 4; r++) acc[mt][nt][r] = 0.f;

    loadA(0);
    loadB(0);

    for (int kk = 0; kk < Kd; kk += 32) {
        // stage prefetched A
        #pragma unroll
        for (int i = 0; i < 4; i++) {
            int r = a_r + i*32;
            float4 v = pA[i];
            float bx = to_tf32(v.x), by = to_tf32(v.y), bz = to_tf32(v.z), bw = to_tf32(v.w);
            if (SPLIT == 3) {
                float sx = to_tf32(v.x - bx), sy = to_tf32(v.y - by);
                float sz = to_tf32(v.z - bz), sw = to_tf32(v.w - bw);
                float2* d = &A2[r*36 + a_c4];
                *(float4*)(d)     = make_float4(bx, sx, by, sy);
                *(float4*)(d + 2) = make_float4(bz, sz, bw, sw);
            } else {
                float* db = &Ab1[r*36 + a_c4];
                db[0] = bx; db[1] = by; db[2] = bz; db[3] = bw;
            }
        }
        // stage prefetched B
        #pragma unroll
        for (int i = 0; i < 4; i++) {
            float4 v = pB[i];
            float bx = to_tf32(v.x), by = to_tf32(v.y), bz = to_tf32(v.z), bw = to_tf32(v.w);
            if (SPLIT == 3) {
                float sx = to_tf32(v.x - bx), sy = to_tf32(v.y - by);
                float sz = to_tf32(v.z - bz), sw = to_tf32(v.w - bw);
                float2* d;
                if (EPI == 2) d = &B2[(a_r + i*32)*36 + a_c4];
                else          d = &B2[(bw_r + i*8)*140 + bw_c4];
                *(float4*)(d)     = make_float4(bx, sx, by, sy);
                *(float4*)(d + 2) = make_float4(bz, sz, bw, sw);
            } else {
                float* db = &Bb1[(bw_r + i*8)*136 + bw_c4];
                db[0] = bx; db[1] = by; db[2] = bz; db[3] = bw;
            }
        }
        __syncthreads();
        if (kk + 32 < Kd) { loadA(kk + 32); loadB(kk + 32); }

        #pragma unroll
        for (int k8 = 0; k8 < 4; k8++) {
            uint32_t afb[4][4], afl[4][4];
            #pragma unroll
            for (int mt = 0; mt < 4; mt++) {
                int off = (wm*64 + mt*16 + g)*36 + k8*8 + t;
                if (SPLIT == 3) {
                    float2 q0 = A2[off];
                    float2 q1 = A2[off + 8*36];
                    float2 q2 = A2[off + 4];
                    float2 q3 = A2[off + 8*36 + 4];
                    afb[mt][0] = __float_as_uint(q0.x); afl[mt][0] = __float_as_uint(q0.y);
                    afb[mt][1] = __float_as_uint(q1.x); afl[mt][1] = __float_as_uint(q1.y);
                    afb[mt][2] = __float_as_uint(q2.x); afl[mt][2] = __float_as_uint(q2.y);
                    afb[mt][3] = __float_as_uint(q3.x); afl[mt][3] = __float_as_uint(q3.y);
                } else {
                    afb[mt][0] = __float_as_uint(Ab1[off]);
                    afb[mt][1] = __float_as_uint(Ab1[off + 8*36]);
                    afb[mt][2] = __float_as_uint(Ab1[off + 4]);
                    afb[mt][3] = __float_as_uint(Ab1[off + 8*36 + 4]);
                }
            }
            uint32_t bfb[4][2], bfl[4][2];
            #pragma unroll
            for (int nt = 0; nt < 4; nt++) {
                if (SPLIT == 3) {
                    float2 q0, q1;
                    if (EPI == 2) {
                        int off = (wn*32 + nt*8 + g)*36 + k8*8 + t;
                        q0 = B2[off]; q1 = B2[off + 4];
                    } else {
                        int off = (k8*8 + t)*140 + wn*32 + nt*8 + g;
                        q0 = B2[off]; q1 = B2[off + 4*140];
                    }
                    bfb[nt][0] = __float_as_uint(q0.x); bfl[nt][0] = __float_as_uint(q0.y);
                    bfb[nt][1] = __float_as_uint(q1.x); bfl[nt][1] = __float_as_uint(q1.y);
                } else {
                    int off = (k8*8 + t)*136 + wn*32 + nt*8 + g;
                    bfb[nt][0] = __float_as_uint(Bb1[off]);
                    bfb[nt][1] = __float_as_uint(Bb1[off + 4*136]);
                }
            }
            #pragma unroll
            for (int mt = 0; mt < 4; mt++)
                #pragma unroll
                for (int nt = 0; nt < 4; nt++) {
                    if (SPLIT == 3) {
                        mma_tf32(acc[mt][nt], afb[mt], bfl[nt]);
                        mma_tf32(acc[mt][nt], afl[mt], bfb[nt]);
                    }
                    mma_tf32(acc[mt][nt], afb[mt], bfb[nt]);
                }
        }
        __syncthreads();
    }

    if (EPI == 2) {
        int b = blockIdx.z;
        float* tile = dynsm;   // reuse: 128 x 132 transpose stage
        #pragma unroll
        for (int mt = 0; mt < 4; mt++) {
            int mA = wm*64 + mt*16 + g;
            int mB = mA + 8;
            float sqm  = g_sq[(size_t)b*NPT + m0 + mA];
            float sqm8 = g_sq[(size_t)b*NPT + m0 + mB];
            float* r0 = g_pd + ((size_t)b*NPT + m0 + mA)*NPT;
            float* r1 = g_pd + ((size_t)b*NPT + m0 + mB)*NPT;
            #pragma unroll
            for (int nt = 0; nt < 4; nt++) {
                int nl = wn*32 + nt*8 + t*2;
                float sqn  = g_sq[(size_t)b*NPT + n0 + nl];
                float sqn1 = g_sq[(size_t)b*NPT + n0 + nl + 1];
                float d00 = 2.f*acc[mt][nt][0] - sqm  - sqn;
                float d01 = 2.f*acc[mt][nt][1] - sqm  - sqn1;
                float d10 = 2.f*acc[mt][nt][2] - sqm8 - sqn;
                float d11 = 2.f*acc[mt][nt][3] - sqm8 - sqn1;
                *(float2*)(r0 + n0 + nl) = make_float2(d00, d01);
                *(float2*)(r1 + n0 + nl) = make_float2(d10, d11);
                if (!diag) {
                    tile[(nl  )*132 + mA] = d00;
                    tile[(nl+1)*132 + mA] = d01;
                    tile[(nl  )*132 + mB] = d10;
                    tile[(nl+1)*132 + mB] = d11;
                }
            }
        }
        if (!diag) {
            __syncthreads();
            #pragma unroll
            for (int i = 0; i < 16; i++) {
                int idx = tid + i*256;
                int r = idx >> 5, c4 = (idx & 31)*4;
                float4 v = *(float4*)&tile[r*132 + c4];
                *(float4*)(g_pd + ((size_t)b*NPT + n0 + r)*NPT + m0 + c4) = v;
            }
        }
    } else if (EPI == 0) {
        int b = m0 >> 12;
        #pragma unroll
        for (int mt = 0; mt < 4; mt++) {
            int m = m0 + wm*64 + mt*16 + g;
            #pragma unroll
            for (int nt = 0; nt < 4; nt++) {
                int n = n0 + wn*32 + nt*8 + t*2;
                float add0 = 0.f, add1 = 0.f;
                if (bias)   { add0 += bias[n]; add1 += bias[n+1]; }
                if (rowadd) { add0 += rowadd[b*Nd + n]; add1 += rowadd[b*Nd + n + 1]; }
                float2 v0, v1;
                v0.x = fmaxf(acc[mt][nt][0] + add0, 0.f);
                v0.y = fmaxf(acc[mt][nt][1] + add1, 0.f);
                v1.x = fmaxf(acc[mt][nt][2] + add0, 0.f);
                v1.y = fmaxf(acc[mt][nt][3] + add1, 0.f);
                *(float2*)(out + (size_t)m*Nd + n) = v0;
                *(float2*)(out + (size_t)(m+8)*Nd + n) = v1;
            }
        }
    } else if (EPI == 1) {
        int b = m0 >> 12;
        #pragma unroll
        for (int nt = 0; nt < 4; nt++) {
            int n = n0 + wn*32 + nt*8 + t*2;
            float m0v = NEGINF, m1v = NEGINF;
            #pragma unroll
            for (int mt = 0; mt < 4; mt++) {
                m0v = fmaxf(m0v, fmaxf(acc[mt][nt][0], acc[mt][nt][2]));
                m1v = fmaxf(m1v, fmaxf(acc[mt][nt][1], acc[mt][nt][3]));
            }
            m0v = fmaxf(m0v + bias[n], 0.f);
            m1v = fmaxf(m1v + bias[n+1], 0.f);
            #pragma unroll
            for (int off = 4; off < 32; off <<= 1) {
                m0v = fmaxf(m0v, __shfl_xor_sync(0xffffffffu, m0v, off));
                m1v = fmaxf(m1v, __shfl_xor_sync(0xffffffffu, m1v, off));
            }
            if (g == 0) {
                atomicMax((int*)out + (size_t)b*Nd + n,     __float_as_int(m0v));
                atomicMax((int*)out + (size_t)b*Nd + n + 1, __float_as_int(m1v));
            }
        }
    } else {
        // EPI == 3: gather-edge fused k-max. out stride = Nd, point = row/20.
        #pragma unroll
        for (int mt = 0; mt < 4; mt++) {
            int m = m0 + wm*64 + mt*16 + g;
            unsigned p0 = (unsigned)m / 20u;
            unsigned p1 = (unsigned)(m + 8) / 20u;
            #pragma unroll
            for (int nt = 0; nt < 4; nt++) {
                int n = n0 + wn*32 + nt*8 + t*2;
                float b0 = bias[n], b1 = bias[n+1];
                float v00 = fmaxf(acc[mt][nt][0] + b0, 0.f);
                float v01 = fmaxf(acc[mt][nt][1] + b1, 0.f);
                float v10 = fmaxf(acc[mt][nt][2] + b0, 0.f);
                float v11 = fmaxf(acc[mt][nt][3] + b1, 0.f);
                if (p0 == p1) {
                    atomicMax((int*)out + (size_t)p0*Nd + n,     __float_as_int(fmaxf(v00, v10)));
                    atomicMax((int*)out + (size_t)p0*Nd + n + 1, __float_as_int(fmaxf(v01, v11)));
                } else {
                    atomicMax((int*)out + (size_t)p0*Nd + n,     __float_as_int(v00));
                    atomicMax((int*)out + (size_t)p0*Nd + n + 1, __float_as_int(v01));
                    atomicMax((int*)out + (size_t)p1*Nd + n,     __float_as_int(v10));
                    atomicMax((int*)out + (size_t)p1*Nd + n + 1, __float_as_int(v11));
                }
            }
        }
    }
}

// ------------- edge GEMM, N=64 tile (gathered A, 3xTF32, fused k-max) -------------
// float2 (big,small) layout: A stride 36 f2, B stride 76 f2.
#define SM_E64 ((4608 + 2432)*8)
__global__ void __launch_bounds__(256) k_mma_e64(const float* __restrict__ W,
                                                 const float* __restrict__ bias,
                                                 float* __restrict__ out, int ldo) {
    extern __shared__ float dynsm[];
    float2* A2 = (float2*)dynsm;          // [128][36] f2
    float2* B2 = (float2*)dynsm + 4608;   // [32][76] f2
    int m0 = blockIdx.y*128;
    int tid = threadIdx.x;
    int w = tid >> 5, lane = tid & 31;
    int wm = w & 3, wn = w >> 2;
    int g = lane >> 2, t = lane & 3;

    int a_r  = tid >> 3, a_c4 = (tid & 7)*4;
    int bw_r = tid >> 4, bw_c4 = (tid & 15)*4;

    float4 pA[4], pB[2];

    auto loadA = [&](int kk) {
        #pragma unroll
        for (int i = 0; i < 4; i++) {
            int r = a_r + i*32;
            unsigned gr = m0 + r;
            unsigned n = gr / 20u;
            int j = g_idx[gr];
            float4 va = *(const float4*)(g_aA + (size_t)n*64 + kk + a_c4);
            float4 vb = *(const float4*)(g_aB + (size_t)j*64 + kk + a_c4);
            pA[i].x = fmaxf(va.x + vb.x, 0.f);
            pA[i].y = fmaxf(va.y + vb.y, 0.f);
            pA[i].z = fmaxf(va.z + vb.z, 0.f);
            pA[i].w = fmaxf(va.w + vb.w, 0.f);
        }
    };
    auto loadB = [&](int kk) {
        #pragma unroll
        for (int i = 0; i < 2; i++) {
            int r = bw_r + i*16;
            pB[i] = *(const float4*)(W + (size_t)(kk + r)*64 + bw_c4);
        }
    };

    float acc[2][4][4];
    #pragma unroll
    for (int mt = 0; mt < 2; mt++)
        #pragma unroll
        for (int nt = 0; nt < 4; nt++)
            #pragma unroll
            for (int r = 0; r < 4; r++) acc[mt][nt][r] = 0.f;

    loadA(0);
    loadB(0);

    for (int kk = 0; kk < 64; kk += 32) {
        #pragma unroll
        for (int i = 0; i < 4; i++) {
            int r = a_r + i*32;
            float4 v = pA[i];
            float bx = to_tf32(v.x), by = to_tf32(v.y), bz = to_tf32(v.z), bw = to_tf32(v.w);
            float sx = to_tf32(v.x - bx), sy = to_tf32(v.y - by);
            float sz = to_tf32(v.z - bz), sw = to_tf32(v.w - bw);
            float2* d = &A2[r*36 + a_c4];
            *(float4*)(d)     = make_float4(bx, sx, by, sy);
            *(float4*)(d + 2) = make_float4(bz, sz, bw, sw);
        }
        #pragma unroll
        for (int i = 0; i < 2; i++) {
            int r = bw_r + i*16;
            float4 v = pB[i];
            float bx = to_tf32(v.x), by = to_tf32(v.y), bz = to_tf32(v.z), bw = to_tf32(v.w);
            float sx = to_tf32(v.x - bx), sy = to_tf32(v.y - by);
            float sz = to_tf32(v.z - bz), sw = to_tf32(v.w - bw);
            float2* d = &B2[r*76 + bw_c4];
            *(float4*)(d)     = make_float4(bx, sx, by, sy);
            *(float4*)(d + 2) = make_float4(bz, sz, bw, sw);
        }
        __syncthreads();
        if (kk + 32 < 64) { loadA(kk + 32); loadB(kk + 32); }

        #pragma unroll
        for (int k8 = 0; k8 < 4; k8++) {
            uint32_t afb[2][4], afl[2][4];
            #pragma unroll
            for (int mt = 0; mt < 2; mt++) {
                int off = (wm*32 + mt*16 + g)*36 + k8*8 + t;
                float2 q0 = A2[off];
                float2 q1 = A2[off + 8*36];
                float2 q2 = A2[off + 4];
                float2 q3 = A2[off + 8*36 + 4];
                afb[mt][0] = __float_as_uint(q0.x); afl[mt][0] = __float_as_uint(q0.y);
                afb[mt][1] = __float_as_uint(q1.x); afl[mt][1] = __float_as_uint(q1.y);
                afb[mt][2] = __float_as_uint(q2.x); afl[mt][2] = __float_as_uint(q2.y);
                afb[mt][3] = __float_as_uint(q3.x); afl[mt][3] = __float_as_uint(q3.y);
            }
            uint32_t bfb[4][2], bfl[4][2];
            #pragma unroll
            for (int nt = 0; nt < 4; nt++) {
                int off = (k8*8 + t)*76 + wn*32 + nt*8 + g;
                float2 q0 = B2[off];
                float2 q1 = B2[off + 4*76];
                bfb[nt][0] = __float_as_uint(q0.x); bfl[nt][0] = __float_as_uint(q0.y);
                bfb[nt][1] = __float_as_uint(q1.x); bfl[nt][1] = __float_as_uint(q1.y);
            }
            #pragma unroll
            for (int mt = 0; mt < 2; mt++)
                #pragma unroll
                for (int nt = 0; nt < 4; nt++) {
                    mma_tf32(acc[mt][nt], afb[mt], bfl[nt]);
                    mma_tf32(acc[mt][nt], afl[mt], bfb[nt]);
                    mma_tf32(acc[mt][nt], afb[mt], bfb[nt]);
                }
        }
        __syncthreads();
    }

    #pragma unroll
    for (int mt = 0; mt < 2; mt++) {
        int m = m0 + wm*32 + mt*16 + g;
        unsigned p0 = (unsigned)m / 20u;
        unsigned p1 = (unsigned)(m + 8) / 20u;
        #pragma unroll
        for (int nt = 0; nt < 4; nt++) {
            int c = wn*32 + nt*8 + t*2;
            float b0 = bias[c], b1 = bias[c+1];
            float v00 = fmaxf(acc[mt][nt][0] + b0, 0.f);
            float v01 = fmaxf(acc[mt][nt][1] + b1, 0.f);
            float v10 = fmaxf(acc[mt][nt][2] + b0, 0.f);
            float v11 = fmaxf(acc[mt][nt][3] + b1, 0.f);
            if (p0 == p1) {
                atomicMax((int*)out + (size_t)p0*ldo + c,     __float_as_int(fmaxf(v00, v10)));
                atomicMax((int*)out + (size_t)p0*ldo + c + 1, __float_as_int(fmaxf(v01, v11)));
            } else {
                atomicMax((int*)out + (size_t)p0*ldo + c,     __float_as_int(v00));
                atomicMax((int*)out + (size_t)p0*ldo + c + 1, __float_as_int(v01));
                atomicMax((int*)out + (size_t)p1*ldo + c,     __float_as_int(v10));
                atomicMax((int*)out + (size_t)p1*ldo + c + 1, __float_as_int(v11));
            }
        }
    }
}

// ------------------------- small FC (M=4) -------------------------
__global__ void k_fc(const float* __restrict__ A, const float* __restrict__ W, int ldw,
                     const float* __restrict__ bias, float* __restrict__ out,
                     int Kd, int Nd, int relu) {
    int t = blockIdx.x*blockDim.x + threadIdx.x;
    if (t >= BBATCH*Nd) return;
    int b = t / Nd, d = t - b*Nd;
    const float* ar = A + (size_t)b*Kd;
    float s0 = 0.f, s1 = 0.f, s2 = 0.f, s3 = 0.f;
    for (int c = 0; c < Kd; c += 4) {
        s0 += ar[c+0]*W[(size_t)(c+0)*ldw + d];
        s1 += ar[c+1]*W[(size_t)(c+1)*ldw + d];
        s2 += ar[c+2]*W[(size_t)(c+2)*ldw + d];
        s3 += ar[c+3]*W[(size_t)(c+3)*ldw + d];
    }
    float acc = bias[d] + (s0+s1) + (s2+s3);
    if (relu) acc = fmaxf(acc, 0.f);
    out[(size_t)b*Nd + d] = acc;
}

// ------------------------- final 256->2 -------------------------
__global__ void k_c4(const float* __restrict__ W, const float* __restrict__ bias,
                     float* __restrict__ out) {
    int gt = blockIdx.x*blockDim.x + threadIdx.x;
    int w = gt >> 5, lane = gt & 31;
    if (w >= NPTS) return;
    const float* a = g_c3 + (size_t)w*256;
    float s0 = 0.f, s1 = 0.f;
    #pragma unroll
    for (int t = 0; t < 8; t++) {
        int c = lane + 32*t;
        float v = a[c];
        s0 += v*W[c*2+0];
        s1 += v*W[c*2+1];
    }
    #pragma unroll
    for (int off = 16; off; off >>= 1) {
        s0 += __shfl_down_sync(0xffffffffu, s0, off);
        s1 += __shfl_down_sync(0xffffffffu, s1, off);
    }
    if (lane == 0) { out[w*2+0] = s0 + bias[0]; out[w*2+1] = s1 + bias[1]; }
}

// ------------------------- host orchestration -------------------------
static float* symaddr(const void* sym) {
    void* p = nullptr;
    cudaGetSymbolAddress(&p, sym);
    return (float*)p;
}

extern "C" void kernel_launch(void* const* d_in, const int* in_sizes, int n_in,
                              void* d_out, int out_size) {
    const float* x    = (const float*)d_in[0];
    const float* tw1  = (const float*)d_in[1];
    const float* tb1  = (const float*)d_in[2];
    const float* tw2  = (const float*)d_in[3];
    const float* tb2  = (const float*)d_in[4];
    const float* tw3  = (const float*)d_in[5];
    const float* tb3  = (const float*)d_in[6];
    const float* tfw1 = (const float*)d_in[7];
    const float* tfb1 = (const float*)d_in[8];
    const float* tfw2 = (const float*)d_in[9];
    const float* tfb2 = (const float*)d_in[10];
    const float* txw  = (const float*)d_in[11];
    const float* txb  = (const float*)d_in[12];
    const float* e1w1 = (const float*)d_in[13];
    const float* e1b1 = (const float*)d_in[14];
    const float* e1w2 = (const float*)d_in[15];
    const float* e1b2 = (const float*)d_in[16];
    const float* e2w1 = (const float*)d_in[17];
    const float* e2b1 = (const float*)d_in[18];
    const float* e2w2 = (const float*)d_in[19];
    const float* e2b2 = (const float*)d_in[20];
    const float* e3w1 = (const float*)d_in[21];
    const float* e3b1 = (const float*)d_in[22];
    const float* c1w  = (const float*)d_in[23];
    const float* c1b  = (const float*)d_in[24];
    const float* c2w  = (const float*)d_in[25];
    const float* c2b  = (const float*)d_in[26];
    const float* c3w  = (const float*)d_in[27];
    const float* c3b  = (const float*)d_in[28];
    const float* c4w  = (const float*)d_in[29];
    const float* c4b  = (const float*)d_in[30];
    float* out = (float*)d_out;

    float4* p_pts4  = (float4*)symaddr(g_pts4);
    float4* p_p4    = (float4*)symaddr(g_p4);
    float*  p_t     = symaddr(g_t);
    float*  p_cat   = symaddr(g_cat192);
    float*  p_c2    = symaddr(g_c2);
    float*  p_c3    = symaddr(g_c3);
    float*  p_tvec  = symaddr(g_tvec);
    float*  p_gvec  = symaddr(g_gvec);
    float*  p_fc1   = symaddr(g_fc1);
    float*  p_fc2   = symaddr(g_fc2);
    float*  p_xf    = symaddr(g_xf);
    float*  p_gterm = symaddr(g_gterm);

    const int SM3D = NPT*16 + KNN_WPB*KCAP*8;   // 98304
    const int SMPD = KNN_WPB*KCAP*8;            // 32768
    cudaFuncSetAttribute(k_knn<false>, cudaFuncAttributeMaxDynamicSharedMemorySize, SM3D);
    cudaFuncSetAttribute(k_knn<true>,  cudaFuncAttributeMaxDynamicSharedMemorySize, SMPD);
    cudaFuncSetAttribute((const void*)k_mma<3,3,true>,  cudaFuncAttributeMaxDynamicSharedMemorySize, SM_MMA3);
    cudaFuncSetAttribute((const void*)k_mma<1,3,false>, cudaFuncAttributeMaxDynamicSharedMemorySize, SM_MMA3);
    cudaFuncSetAttribute((const void*)k_mma<2,3,false>, cudaFuncAttributeMaxDynamicSharedMemorySize, SM_MMA3);
    cudaFuncSetAttribute((const void*)k_mma_e64,        cudaFuncAttributeMaxDynamicSharedMemorySize, SM_E64);

    const int NTRI = (NPT/128)*((NPT/128) + 1)/2;   // 528 triangle blocks
    dim3 pwgrid(NTRI, 1, BBATCH);
    const int EDGE_GY = NPTS*KNB/128;   // 2560

    k_zero<<<(BBATCH*1024 + 255)/256, 256>>>();
    cudaMemsetAsync(p_t,   0, (size_t)NPTS*128*sizeof(float));
    cudaMemsetAsync(p_cat, 0, (size_t)NPTS*192*sizeof(float));
    k_pts_sq<<<NPTS/256, 256>>>(x);

    // ---- knn(pts) + tnet ----
    k_knn<false><<<NPTS/KNN_WPB, 512, SM3D>>>(p_pts4);
    k_prep_ab<3><<<NPTS*64/256, 256>>>((const float*)p_pts4, 4, tw1, tb1);
    k_mma<3,3,true><<<dim3(1, EDGE_GY), 256, SM_MMA3>>>(nullptr, 0, tw2, 128, tb2, nullptr, p_t, 64, 128);
    k_mma<1,3,false><<<dim3(1024/128, NPTS/128), 256, SM_MMA3>>>(p_t, 128, tw3, 1024, tb3, nullptr, p_tvec, 128, 1024);
    k_fc<<<(BBATCH*512 + 127)/128, 128>>>(p_tvec, tfw1, 512, tfb1, p_fc1, 1024, 512, 1);
    k_fc<<<(BBATCH*256 + 127)/128, 128>>>(p_fc1, tfw2, 256, tfb2, p_fc2, 512, 256, 1);
    k_fc<<<1, 128>>>(p_fc2, txw, 9, txb, p_xf, 256, 9, 0);
    k_transform<<<NPTS/256, 256>>>();

    // ---- knn(p) + e1 -> x1 ----
    k_knn<false><<<NPTS/KNN_WPB, 512, SM3D>>>(p_p4);
    k_prep_ab<3><<<NPTS*64/256, 256>>>((const float*)p_p4, 4, e1w1, e1b1);
    k_mma_e64<<<dim3(1, EDGE_GY), 256, SM_E64>>>(e1w2, e1b2, p_cat + 0, 192);

    // ---- knn(x1) + e2 -> x2 ----
    k_sq64<<<NPTS*32/256, 256>>>(p_cat + 0, 192);
    k_mma<2,3,false><<<pwgrid, 256, SM_MMA3>>>(p_cat + 0, 192, p_cat + 0, 192, nullptr, nullptr, nullptr, 64, NPT);
    k_knn<true><<<NPTS/KNN_WPB, 512, SMPD>>>(nullptr);
    k_prep_ab<64><<<NPTS*64/256, 256>>>(p_cat + 0, 192, e2w1, e2b1);
    k_mma_e64<<<dim3(1, EDGE_GY), 256, SM_E64>>>(e2w2, e2b2, p_cat + 64, 192);

    // ---- knn(x2) + e3 -> x3 ----
    k_sq64<<<NPTS*32/256, 256>>>(p_cat + 64, 192);
    k_mma<2,3,false><<<pwgrid, 256, SM_MMA3>>>(p_cat + 64, 192, p_cat + 64, 192, nullptr, nullptr, nullptr, 64, NPT);
    k_knn<true><<<NPTS/KNN_WPB, 512, SMPD>>>(nullptr);
    k_prep_ab<64><<<NPTS*64/256, 256>>>(p_cat + 64, 192, e3w1, e3b1);
    k_edge_e3<<<NPTS*64/256, 256>>>(p_cat + 128, 192);

    // ---- classifier (no knn downstream -> 1xTF32) ----
    k_mma<1,1,false><<<dim3(1024/128, NPTS/128), 256, SM_MMA1>>>(p_cat, 192, c1w, 1024, c1b, nullptr, p_gvec, 192, 1024);
    k_fc<<<(BBATCH*512 + 127)/128, 128>>>(p_gvec, c2w, 512, c2b, p_gterm, 1024, 512, 0);
    k_mma<0,1,false><<<dim3(512/128, NPTS/128), 256, SM_MMA1>>>(p_cat, 192, c2w + (size_t)1024*512, 512, nullptr, p_gterm, p_c2, 192, 512);
    k_mma<0,1,false><<<dim3(256/128, NPTS/128), 256, SM_MMA1>>>(p_c2, 512, c3w, 256, c3b, nullptr, p_c3, 512, 256);
    k_c4<<<NPTS*32/256, 256>>>(c4w, c4b, out);
}

// round 13
// speedup vs baseline: 1.0492x; 1.0492x over previous
#include <cuda_runtime.h>
#include <cstdint>
#include <cstddef>

#define NPT    4096
#define BBATCH 4
#define NPTS   (BBATCH*NPT)
#define KNB    20
#define NEGINF (-3.4e38f)
#define KCAP   256
#define KNN_WPB 16

// ------------------------- device scratch -------------------------
__device__ float  g_pd[(size_t)BBATCH*NPT*NPT];   // pairwise (64-dim KNNs)
__device__ int    g_idx[NPTS*KNB];
__device__ float4 g_pts4[NPTS];
__device__ float4 g_p4[NPTS];
__device__ float  g_sq[NPTS];
__device__ float  g_aA[NPTS*64];
__device__ float  g_aB[NPTS*64];
__device__ float  g_t[(size_t)NPTS*128];
__device__ float  g_cat192[(size_t)NPTS*192];     // x1|x2|x3
__device__ float  g_c2[(size_t)NPTS*512];
__device__ float  g_c3[(size_t)NPTS*256];
__device__ float  g_tvec[BBATCH*1024];
__device__ float  g_gvec[BBATCH*1024];
__device__ float  g_fc1[BBATCH*512];
__device__ float  g_fc2[BBATCH*256];
__device__ float  g_xf[BBATCH*9];
__device__ float  g_gterm[BBATCH*512];

// ------------------------- small kernels -------------------------
__global__ void k_zero() {
    int t = blockIdx.x*blockDim.x + threadIdx.x;
    if (t < BBATCH*1024) { g_tvec[t] = 0.f; g_gvec[t] = 0.f; }
}

__global__ void k_pts_sq(const float* __restrict__ x) {
    int i = blockIdx.x*blockDim.x + threadIdx.x;
    if (i >= NPTS) return;
    float a = x[i*6+0], b = x[i*6+1], c = x[i*6+2];
    g_pts4[i] = make_float4(a, b, c, a*a + b*b + c*c);
}

__global__ void k_transform() {
    int n = blockIdx.x*blockDim.x + threadIdx.x;
    if (n >= NPTS) return;
    int b = n >> 12;
    float4 q = g_pts4[n];
    const float* f = g_xf + b*9;
    float p0 = q.x*f[0] + q.y*f[3] + q.z*f[6];
    float p1 = q.x*f[1] + q.y*f[4] + q.z*f[7];
    float p2 = q.x*f[2] + q.y*f[5] + q.z*f[8];
    g_p4[n] = make_float4(p0, p1, p2, p0*p0 + p1*p1 + p2*p2);
}

__global__ void k_sq64(const float* __restrict__ src, int ld) {
    int gt = blockIdx.x*blockDim.x + threadIdx.x;
    int w = gt >> 5, lane = gt & 31;
    if (w >= NPTS) return;
    const float* r = src + (size_t)w*ld;
    float s = r[lane]*r[lane] + r[lane+32]*r[lane+32];
    #pragma unroll
    for (int off = 16; off; off >>= 1) s += __shfl_down_sync(0xffffffffu, s, off);
    if (lane == 0) g_sq[w] = s;
}

// ------------------------- fast exact KNN (K=20) -------------------------
template<bool PD>
__global__ void __launch_bounds__(512) k_knn(const float4* __restrict__ P4) {
    extern __shared__ float dyn[];
    int w = threadIdx.x >> 5, lane = threadIdx.x & 31;
    int row = blockIdx.x*KNN_WPB + w;
    int b = row >> 12, i = row & (NPT-1);

    float4* stash = (float4*)dyn;
    float*  bufv;
    int*    bufj;
    if (PD) { bufv = dyn + w*2*KCAP; }
    else    { bufv = dyn + NPT*4 + w*2*KCAP; }
    bufj = (int*)(bufv + KCAP);

    float xi2 = 0.f, yi2 = 0.f, zi2 = 0.f, ci = 0.f;
    const float4* pr = nullptr;
    if (!PD) {
        const float4* src = P4 + (size_t)b*NPT;
        for (int t = threadIdx.x; t < NPT; t += 512) stash[t] = src[t];
        __syncthreads();
        float4 pi = stash[i];
        xi2 = 2.f*pi.x; yi2 = 2.f*pi.y; zi2 = 2.f*pi.z; ci = -pi.w;
    } else {
        pr = (const float4*)(g_pd + (size_t)row*NPT);
    }

    float mx = NEGINF;
    if (!PD) {
        for (int t = 0; t < 128; t++) {
            float4 pj = stash[lane + t*32];
            float d = fmaf(xi2, pj.x, fmaf(yi2, pj.y, fmaf(zi2, pj.z, ci - pj.w)));
            mx = fmaxf(mx, d);
        }
    } else {
        for (int t = 0; t < 32; t++) {
            float4 v = pr[lane + t*32];
            mx = fmaxf(mx, fmaxf(fmaxf(v.x, v.y), fmaxf(v.z, v.w)));
        }
    }

    float tau = NEGINF;
    float tv = mx;
    #pragma unroll
    for (int r = 0; r < 20; r++) {
        float bv = tv;
        #pragma unroll
        for (int off = 16; off; off >>= 1)
            bv = fmaxf(bv, __shfl_xor_sync(0xffffffffu, bv, off));
        unsigned m = __ballot_sync(0xffffffffu, tv == bv);
        if (lane == (__ffs(m) - 1)) tv = NEGINF;
        tau = bv;
    }

    unsigned lmask = (1u << lane) - 1u;
    int total = 0;
    if (!PD) {
        for (int t = 0; t < 128; t++) {
            int j = lane + t*32;
            float4 pj = stash[j];
            float d = fmaf(xi2, pj.x, fmaf(yi2, pj.y, fmaf(zi2, pj.z, ci - pj.w)));
            bool keep = (d >= tau);
            unsigned mk = __ballot_sync(0xffffffffu, keep);
            if (keep) {
                int pos = total + __popc(mk & lmask);
                if (pos < KCAP) { bufv[pos] = d; bufj[pos] = j; }
            }
            total += __popc(mk);
        }
    } else {
        for (int t = 0; t < 32; t++) {
            int c = lane + t*32;
            float4 v = pr[c];
            float vals[4] = {v.x, v.y, v.z, v.w};
            #pragma unroll
            for (int e = 0; e < 4; e++) {
                bool keep = (vals[e] >= tau);
                unsigned mk = __ballot_sync(0xffffffffu, keep);
                if (keep) {
                    int pos = total + __popc(mk & lmask);
                    if (pos < KCAP) { bufv[pos] = vals[e]; bufj[pos] = c*4 + e; }
                }
                total += __popc(mk);
            }
        }
    }

    int* orow = g_idx + row*KNB;

    if (total <= KCAP) {
        int nq = (total + 31) >> 5;
        for (int r = 0; r < KNB; r++) {
            float bv = NEGINF; int bj = 0x7fffffff; int bs = -1;
            for (int q = 0; q < nq; q++) {
                int idx = lane + (q << 5);
                if (idx < total) {
                    float v = bufv[idx]; int j = bufj[idx];
                    if (v > bv || (v == bv && j < bj)) { bv = v; bj = j; bs = idx; }
                }
            }
            float lv0 = bv; int lj0 = bj;
            #pragma unroll
            for (int off = 16; off; off >>= 1) {
                float ov = __shfl_xor_sync(0xffffffffu, bv, off);
                int   oj = __shfl_xor_sync(0xffffffffu, bj, off);
                if (ov > bv || (ov == bv && oj < bj)) { bv = ov; bj = oj; }
            }
            if (lj0 == bj && lv0 == bv && bs >= 0) bufv[bs] = NEGINF;
            if (lane == 0) orow[r] = bj + (b << 12);
        }
    } else {
        float lv[KNB]; int li[KNB];
        #pragma unroll
        for (int q = 0; q < KNB; q++) { lv[q] = NEGINF; li[q] = 0x7fffffff; }
        if (!PD) {
            for (int t = 0; t < 128; t++) {
                int j = lane + t*32;
                float4 pj = stash[j];
                float val = fmaf(xi2, pj.x, fmaf(yi2, pj.y, fmaf(zi2, pj.z, ci - pj.w)));
                if (val > lv[KNB-1]) {
                    #pragma unroll
                    for (int p = KNB-1; p > 0; --p) {
                        bool below = (lv[p] >= val);
                        bool shift = (lv[p-1] < val);
                        float nl = below ? lv[p] : (shift ? lv[p-1] : val);
                        int   ni = below ? li[p] : (shift ? li[p-1] : j);
                        lv[p] = nl; li[p] = ni;
                    }
                    if (lv[0] < val) { lv[0] = val; li[0] = j; }
                }
            }
        } else {
            for (int t = 0; t < 32; t++) {
                int c = lane + t*32;
                float4 v = pr[c];
                float vals[4] = {v.x, v.y, v.z, v.w};
                #pragma unroll
                for (int e = 0; e < 4; e++) {
                    float val = vals[e]; int j = c*4 + e;
                    if (val > lv[KNB-1]) {
                        #pragma unroll
                        for (int p = KNB-1; p > 0; --p) {
                            bool below = (lv[p] >= val);
                            bool shift = (lv[p-1] < val);
                            float nl = below ? lv[p] : (shift ? lv[p-1] : val);
                            int   ni = below ? li[p] : (shift ? li[p-1] : j);
                            lv[p] = nl; li[p] = ni;
                        }
                        if (lv[0] < val) { lv[0] = val; li[0] = j; }
                    }
                }
            }
        }
        for (int r = 0; r < KNB; r++) {
            float bv = lv[0]; int bj = li[0];
            float lv0 = bv; int lj0 = bj;
            #pragma unroll
            for (int off = 16; off; off >>= 1) {
                float ov = __shfl_xor_sync(0xffffffffu, bv, off);
                int   oj = __shfl_xor_sync(0xffffffffu, bj, off);
                if (ov > bv || (ov == bv && oj < bj)) { bv = ov; bj = oj; }
            }
            if (lj0 == bj && lv0 == bv) {
                #pragma unroll
                for (int p = 0; p < KNB-1; p++) { lv[p] = lv[p+1]; li[p] = li[p+1]; }
                lv[KNB-1] = NEGINF; li[KNB-1] = 0x7fffffff;
            }
            if (lane == 0) orow[r] = bj + (b << 12);
        }
    }
}

// ------------------------- edge-conv prep -------------------------
template<int C>
__global__ void k_prep_ab(const float* __restrict__ src, int ld,
                          const float* __restrict__ W, const float* __restrict__ bias) {
    __shared__ float Ws[2*C*64];
    for (int e = threadIdx.x; e < 2*C*64; e += blockDim.x) Ws[e] = W[e];
    __syncthreads();
    int t = blockIdx.x*blockDim.x + threadIdx.x;
    int d = t & 63, n = t >> 6;
    if (n >= NPTS) return;
    const float* xr = src + (size_t)n*ld;
    float a = bias[d], bb = 0.f;
    #pragma unroll
    for (int c = 0; c < C; c++) {
        float xv = xr[c];
        float wt = Ws[c*64+d], wb = Ws[(C+c)*64+d];
        a  += xv*(wt - wb);
        bb += xv*wb;
    }
    g_aA[(size_t)n*64+d] = a;
    g_aB[(size_t)n*64+d] = bb;
}

// e3: out[n,d] = max_k relu(a[n,d] + bnb[idx[n,k],d])
__global__ void k_edge_e3(float* __restrict__ out, int ldo) {
    int t = blockIdx.x*blockDim.x + threadIdx.x;
    int d = t & 63, n = t >> 6;
    if (n >= NPTS) return;
    float a = g_aA[(size_t)n*64+d];
    const int* ir = g_idx + n*KNB;
    float m = 0.f;
    #pragma unroll
    for (int k = 0; k < KNB; k++) m = fmaxf(m, a + g_aB[(size_t)ir[k]*64 + d]);
    out[(size_t)n*ldo + d] = m;
}

// ------------------------- TF32 tensor-core GEMM -------------------------
__device__ __forceinline__ float to_tf32(float x) {
    uint32_t u;
    asm("cvt.rna.tf32.f32 %0, %1;" : "=r"(u) : "f"(x));
    return __uint_as_float(u);
}

__device__ __forceinline__ void mma_tf32(float* c, const uint32_t* a, const uint32_t* b) {
    asm volatile(
        "mma.sync.aligned.m16n8k8.row.col.f32.tf32.tf32.f32 "
        "{%0,%1,%2,%3}, {%4,%5,%6,%7}, {%8,%9}, {%0,%1,%2,%3};\n"
        : "+f"(c[0]), "+f"(c[1]), "+f"(c[2]), "+f"(c[3])
        : "r"(a[0]), "r"(a[1]), "r"(a[2]), "r"(a[3]), "r"(b[0]), "r"(b[1]));
}

#define SM_BUF   4608
#define SM_MMA3  (4*SM_BUF*4)
#define SM_MMA1  (2*SM_BUF*4)

// Block tile 128x128, 8 warps (2M x 4N), warp tile 64x32, k-stage 32.
// Register-prefetch double buffering.
// SPLIT=3: 3xTF32 (~fp32); SPLIT=1: single-pass tf32.
// GATHER: A rows are edge rows relu(g_aA[n] + g_aB[g_idx[row]]) (K=64).
// EPI: 0 = bias(+rowadd)+ReLU store; 1 = bias+ReLU+per-batch col max (atomicMax);
//      2 = SYMMETRIC pairwise: triangular grid, mirrored tile via smem transpose;
//      3 = gather edge: bias+ReLU, per-point (row/20) atomicMax into out (stride Nd).
template<int EPI, int SPLIT, bool GATHER>
__global__ void __launch_bounds__(256) k_mma(const float* __restrict__ A, int lda,
                                             const float* __restrict__ B, int ldb,
                                             const float* __restrict__ bias,
                                             const float* __restrict__ rowadd,
                                             float* __restrict__ out,
                                             int Kd, int Nd) {
    extern __shared__ float dynsm[];
    float* Ab = dynsm;
    float* Al = dynsm + SM_BUF;                          // SPLIT==3 only
    float* Bb = dynsm + (SPLIT == 3 ? 2 : 1)*SM_BUF;
    float* Bl = dynsm + 3*SM_BUF;                        // SPLIT==3 only
    int m0, n0;
    bool diag = false;
    if (EPI == 2) {
        int tb = blockIdx.x;
        int by = (int)((sqrtf(8.f*tb + 1.f) - 1.f)*0.5f);
        while ((by + 1)*(by + 2)/2 <= tb) by++;
        while (by*(by + 1)/2 > tb) by--;
        int bx = tb - by*(by + 1)/2;
        m0 = by*128; n0 = bx*128;
        diag = (bx == by);
    } else {
        m0 = blockIdx.y*128; n0 = blockIdx.x*128;
    }
    int tid = threadIdx.x;
    int w = tid >> 5, lane = tid & 31;
    int wm = w & 1, wn = w >> 1;
    int g = lane >> 2, t = lane & 3;
    size_t rowbase = (EPI == 2) ? (size_t)blockIdx.z*NPT : 0;

    int a_r  = tid >> 3, a_c4 = (tid & 7)*4;
    int bw_r = tid >> 5, bw_c4 = (tid & 31)*4;

    float4 pA[4], pB[4];

    auto loadA = [&](int kk) {
        #pragma unroll
        for (int i = 0; i < 4; i++) {
            int r = a_r + i*32;
            if (GATHER) {
                unsigned gr = m0 + r;
                unsigned n = gr / 20u;
                int j = g_idx[gr];
                float4 va = *(const float4*)(g_aA + (size_t)n*64 + kk + a_c4);
                float4 vb = *(const float4*)(g_aB + (size_t)j*64 + kk + a_c4);
                pA[i].x = fmaxf(va.x + vb.x, 0.f);
                pA[i].y = fmaxf(va.y + vb.y, 0.f);
                pA[i].z = fmaxf(va.z + vb.z, 0.f);
                pA[i].w = fmaxf(va.w + vb.w, 0.f);
            } else {
                pA[i] = *(const float4*)(A + (rowbase + m0 + r)*lda + kk + a_c4);
            }
        }
    };
    auto loadB = [&](int kk) {
        #pragma unroll
        for (int i = 0; i < 4; i++) {
            if (EPI == 2) {
                int r = a_r + i*32;
                pB[i] = *(const float4*)(B + (rowbase + n0 + r)*ldb + kk + a_c4);
            } else {
                int r = bw_r + i*8;
                pB[i] = *(const float4*)(B + (size_t)(kk + r)*ldb + n0 + bw_c4);
            }
        }
    };

    float acc[4][4][4];
    #pragma unroll
    for (int mt = 0; mt < 4; mt++)
        #pragma unroll
        for (int nt = 0; nt < 4; nt++)
            #pragma unroll
            for (int r = 0; r < 4; r++) acc[mt][nt][r] = 0.f;

    loadA(0);
    loadB(0);

    for (int kk = 0; kk < Kd; kk += 32) {
        // stage prefetched A
        #pragma unroll
        for (int i = 0; i < 4; i++) {
            int r = a_r + i*32;
            float4 v = pA[i];
            float bx = to_tf32(v.x), by = to_tf32(v.y), bz = to_tf32(v.z), bw = to_tf32(v.w);
            float* db = &Ab[r*36 + a_c4];
            db[0] = bx; db[1] = by; db[2] = bz; db[3] = bw;
            if (SPLIT == 3) {
                float* dl = &Al[r*36 + a_c4];
                dl[0] = to_tf32(v.x - bx); dl[1] = to_tf32(v.y - by);
                dl[2] = to_tf32(v.z - bz); dl[3] = to_tf32(v.w - bw);
            }
        }
        // stage prefetched B
        #pragma unroll
        for (int i = 0; i < 4; i++) {
            float4 v = pB[i];
            float bx = to_tf32(v.x), by = to_tf32(v.y), bz = to_tf32(v.z), bw = to_tf32(v.w);
            if (EPI == 2) {
                int r = a_r + i*32;
                float* db = &Bb[r*36 + a_c4];
                db[0] = bx; db[1] = by; db[2] = bz; db[3] = bw;
                if (SPLIT == 3) {
                    float* dl = &Bl[r*36 + a_c4];
                    dl[0] = to_tf32(v.x - bx); dl[1] = to_tf32(v.y - by);
                    dl[2] = to_tf32(v.z - bz); dl[3] = to_tf32(v.w - bw);
                }
            } else {
                int r = bw_r + i*8;
                float* db = &Bb[r*136 + bw_c4];
                db[0] = bx; db[1] = by; db[2] = bz; db[3] = bw;
                if (SPLIT == 3) {
                    float* dl = &Bl[r*136 + bw_c4];
                    dl[0] = to_tf32(v.x - bx); dl[1] = to_tf32(v.y - by);
                    dl[2] = to_tf32(v.z - bz); dl[3] = to_tf32(v.w - bw);
                }
            }
        }
        __syncthreads();
        // prefetch next tile (overlaps with MMA below)
        if (kk + 32 < Kd) { loadA(kk + 32); loadB(kk + 32); }

        #pragma unroll
        for (int k8 = 0; k8 < 4; k8++) {
            uint32_t afb[4][4], afl[4][4];
            #pragma unroll
            for (int mt = 0; mt < 4; mt++) {
                int off = (wm*64 + mt*16 + g)*36 + k8*8 + t;
                afb[mt][0] = __float_as_uint(Ab[off]);
                afb[mt][1] = __float_as_uint(Ab[off + 8*36]);
                afb[mt][2] = __float_as_uint(Ab[off + 4]);
                afb[mt][3] = __float_as_uint(Ab[off + 8*36 + 4]);
                if (SPLIT == 3) {
                    afl[mt][0] = __float_as_uint(Al[off]);
                    afl[mt][1] = __float_as_uint(Al[off + 8*36]);
                    afl[mt][2] = __float_as_uint(Al[off + 4]);
                    afl[mt][3] = __float_as_uint(Al[off + 8*36 + 4]);
                }
            }
            uint32_t bfb[4][2], bfl[4][2];
            #pragma unroll
            for (int nt = 0; nt < 4; nt++) {
                if (EPI == 2) {
                    int off = (wn*32 + nt*8 + g)*36 + k8*8 + t;
                    bfb[nt][0] = __float_as_uint(Bb[off]);
                    bfb[nt][1] = __float_as_uint(Bb[off + 4]);
                    if (SPLIT == 3) {
                        bfl[nt][0] = __float_as_uint(Bl[off]);
                        bfl[nt][1] = __float_as_uint(Bl[off + 4]);
                    }
                } else {
                    int off = (k8*8 + t)*136 + wn*32 + nt*8 + g;
                    bfb[nt][0] = __float_as_uint(Bb[off]);
                    bfb[nt][1] = __float_as_uint(Bb[off + 4*136]);
                    if (SPLIT == 3) {
                        bfl[nt][0] = __float_as_uint(Bl[off]);
                        bfl[nt][1] = __float_as_uint(Bl[off + 4*136]);
                    }
                }
            }
            #pragma unroll
            for (int mt = 0; mt < 4; mt++)
                #pragma unroll
                for (int nt = 0; nt < 4; nt++) {
                    if (SPLIT == 3) {
                        mma_tf32(acc[mt][nt], afb[mt], bfl[nt]);
                        mma_tf32(acc[mt][nt], afl[mt], bfb[nt]);
                    }
                    mma_tf32(acc[mt][nt], afb[mt], bfb[nt]);
                }
        }
        __syncthreads();
    }

    if (EPI == 2) {
        int b = blockIdx.z;
        float* tile = dynsm;   // reuse: 128 x 132 transpose stage
        #pragma unroll
        for (int mt = 0; mt < 4; mt++) {
            int mA = wm*64 + mt*16 + g;
            int mB = mA + 8;
            float sqm  = g_sq[(size_t)b*NPT + m0 + mA];
            float sqm8 = g_sq[(size_t)b*NPT + m0 + mB];
            float* r0 = g_pd + ((size_t)b*NPT + m0 + mA)*NPT;
            float* r1 = g_pd + ((size_t)b*NPT + m0 + mB)*NPT;
            #pragma unroll
            for (int nt = 0; nt < 4; nt++) {
                int nl = wn*32 + nt*8 + t*2;
                float sqn  = g_sq[(size_t)b*NPT + n0 + nl];
                float sqn1 = g_sq[(size_t)b*NPT + n0 + nl + 1];
                float d00 = 2.f*acc[mt][nt][0] - sqm  - sqn;
                float d01 = 2.f*acc[mt][nt][1] - sqm  - sqn1;
                float d10 = 2.f*acc[mt][nt][2] - sqm8 - sqn;
                float d11 = 2.f*acc[mt][nt][3] - sqm8 - sqn1;
                *(float2*)(r0 + n0 + nl) = make_float2(d00, d01);
                *(float2*)(r1 + n0 + nl) = make_float2(d10, d11);
                if (!diag) {
                    tile[(nl  )*132 + mA] = d00;
                    tile[(nl+1)*132 + mA] = d01;
                    tile[(nl  )*132 + mB] = d10;
                    tile[(nl+1)*132 + mB] = d11;
                }
            }
        }
        if (!diag) {
            __syncthreads();
            #pragma unroll
            for (int i = 0; i < 16; i++) {
                int idx = tid + i*256;
                int r = idx >> 5, c4 = (idx & 31)*4;
                float4 v = *(float4*)&tile[r*132 + c4];
                *(float4*)(g_pd + ((size_t)b*NPT + n0 + r)*NPT + m0 + c4) = v;
            }
        }
    } else if (EPI == 0) {
        int b = m0 >> 12;
        #pragma unroll
        for (int mt = 0; mt < 4; mt++) {
            int m = m0 + wm*64 + mt*16 + g;
            #pragma unroll
            for (int nt = 0; nt < 4; nt++) {
                int n = n0 + wn*32 + nt*8 + t*2;
                float add0 = 0.f, add1 = 0.f;
                if (bias)   { add0 += bias[n]; add1 += bias[n+1]; }
                if (rowadd) { add0 += rowadd[b*Nd + n]; add1 += rowadd[b*Nd + n + 1]; }
                float2 v0, v1;
                v0.x = fmaxf(acc[mt][nt][0] + add0, 0.f);
                v0.y = fmaxf(acc[mt][nt][1] + add1, 0.f);
                v1.x = fmaxf(acc[mt][nt][2] + add0, 0.f);
                v1.y = fmaxf(acc[mt][nt][3] + add1, 0.f);
                *(float2*)(out + (size_t)m*Nd + n) = v0;
                *(float2*)(out + (size_t)(m+8)*Nd + n) = v1;
            }
        }
    } else if (EPI == 1) {
        int b = m0 >> 12;
        #pragma unroll
        for (int nt = 0; nt < 4; nt++) {
            int n = n0 + wn*32 + nt*8 + t*2;
            float m0v = NEGINF, m1v = NEGINF;
            #pragma unroll
            for (int mt = 0; mt < 4; mt++) {
                m0v = fmaxf(m0v, fmaxf(acc[mt][nt][0], acc[mt][nt][2]));
                m1v = fmaxf(m1v, fmaxf(acc[mt][nt][1], acc[mt][nt][3]));
            }
            m0v = fmaxf(m0v + bias[n], 0.f);
            m1v = fmaxf(m1v + bias[n+1], 0.f);
            #pragma unroll
            for (int off = 4; off < 32; off <<= 1) {
                m0v = fmaxf(m0v, __shfl_xor_sync(0xffffffffu, m0v, off));
                m1v = fmaxf(m1v, __shfl_xor_sync(0xffffffffu, m1v, off));
            }
            if (g == 0) {
                atomicMax((int*)out + (size_t)b*Nd + n,     __float_as_int(m0v));
                atomicMax((int*)out + (size_t)b*Nd + n + 1, __float_as_int(m1v));
            }
        }
    } else {
        // EPI == 3: gather-edge fused k-max. out stride = Nd, point = row/20.
        #pragma unroll
        for (int mt = 0; mt < 4; mt++) {
            int m = m0 + wm*64 + mt*16 + g;
            unsigned p0 = (unsigned)m / 20u;
            unsigned p1 = (unsigned)(m + 8) / 20u;
            #pragma unroll
            for (int nt = 0; nt < 4; nt++) {
                int n = n0 + wn*32 + nt*8 + t*2;
                float b0 = bias[n], b1 = bias[n+1];
                float v00 = fmaxf(acc[mt][nt][0] + b0, 0.f);
                float v01 = fmaxf(acc[mt][nt][1] + b1, 0.f);
                float v10 = fmaxf(acc[mt][nt][2] + b0, 0.f);
                float v11 = fmaxf(acc[mt][nt][3] + b1, 0.f);
                if (p0 == p1) {
                    atomicMax((int*)out + (size_t)p0*Nd + n,     __float_as_int(fmaxf(v00, v10)));
                    atomicMax((int*)out + (size_t)p0*Nd + n + 1, __float_as_int(fmaxf(v01, v11)));
                } else {
                    atomicMax((int*)out + (size_t)p0*Nd + n,     __float_as_int(v00));
                    atomicMax((int*)out + (size_t)p0*Nd + n + 1, __float_as_int(v01));
                    atomicMax((int*)out + (size_t)p1*Nd + n,     __float_as_int(v10));
                    atomicMax((int*)out + (size_t)p1*Nd + n + 1, __float_as_int(v11));
                }
            }
        }
    }
}

// ------------- edge GEMM, N=64 tile (gathered A, 3xTF32, fused k-max) -------------
#define SM_E64 ((2*4608 + 2*2304)*4)
__global__ void __launch_bounds__(256) k_mma_e64(const float* __restrict__ W,
                                                 const float* __restrict__ bias,
                                                 float* __restrict__ out, int ldo) {
    extern __shared__ float dynsm[];
    float* Ab = dynsm;                 // [128][36]
    float* Al = dynsm + 4608;
    float* Bb = dynsm + 2*4608;        // [32][72]
    float* Bl = dynsm + 2*4608 + 2304;
    int m0 = blockIdx.y*128;
    int tid = threadIdx.x;
    int w = tid >> 5, lane = tid & 31;
    int wm = w & 3, wn = w >> 2;
    int g = lane >> 2, t = lane & 3;

    int a_r  = tid >> 3, a_c4 = (tid & 7)*4;
    int bw_r = tid >> 4, bw_c4 = (tid & 15)*4;

    float4 pA[4], pB[2];

    auto loadA = [&](int kk) {
        #pragma unroll
        for (int i = 0; i < 4; i++) {
            int r = a_r + i*32;
            unsigned gr = m0 + r;
            unsigned n = gr / 20u;
            int j = g_idx[gr];
            float4 va = *(const float4*)(g_aA + (size_t)n*64 + kk + a_c4);
            float4 vb = *(const float4*)(g_aB + (size_t)j*64 + kk + a_c4);
            pA[i].x = fmaxf(va.x + vb.x, 0.f);
            pA[i].y = fmaxf(va.y + vb.y, 0.f);
            pA[i].z = fmaxf(va.z + vb.z, 0.f);
            pA[i].w = fmaxf(va.w + vb.w, 0.f);
        }
    };
    auto loadB = [&](int kk) {
        #pragma unroll
        for (int i = 0; i < 2; i++) {
            int r = bw_r + i*16;
            pB[i] = *(const float4*)(W + (size_t)(kk + r)*64 + bw_c4);
        }
    };

    float acc[2][4][4];
    #pragma unroll
    for (int mt = 0; mt < 2; mt++)
        #pragma unroll
        for (int nt = 0; nt < 4; nt++)
            #pragma unroll
            for (int r = 0; r < 4; r++) acc[mt][nt][r] = 0.f;

    loadA(0);
    loadB(0);

    for (int kk = 0; kk < 64; kk += 32) {
        #pragma unroll
        for (int i = 0; i < 4; i++) {
            int r = a_r + i*32;
            float4 v = pA[i];
            float bx = to_tf32(v.x), by = to_tf32(v.y), bz = to_tf32(v.z), bw = to_tf32(v.w);
            float* db = &Ab[r*36 + a_c4];
            float* dl = &Al[r*36 + a_c4];
            db[0] = bx; db[1] = by; db[2] = bz; db[3] = bw;
            dl[0] = to_tf32(v.x - bx); dl[1] = to_tf32(v.y - by);
            dl[2] = to_tf32(v.z - bz); dl[3] = to_tf32(v.w - bw);
        }
        #pragma unroll
        for (int i = 0; i < 2; i++) {
            int r = bw_r + i*16;
            float4 v = pB[i];
            float bx = to_tf32(v.x), by = to_tf32(v.y), bz = to_tf32(v.z), bw = to_tf32(v.w);
            float* db = &Bb[r*72 + bw_c4];
            float* dl = &Bl[r*72 + bw_c4];
            db[0] = bx; db[1] = by; db[2] = bz; db[3] = bw;
            dl[0] = to_tf32(v.x - bx); dl[1] = to_tf32(v.y - by);
            dl[2] = to_tf32(v.z - bz); dl[3] = to_tf32(v.w - bw);
        }
        __syncthreads();
        if (kk + 32 < 64) { loadA(kk + 32); loadB(kk + 32); }

        #pragma unroll
        for (int k8 = 0; k8 < 4; k8++) {
            uint32_t afb[2][4], afl[2][4];
            #pragma unroll
            for (int mt = 0; mt < 2; mt++) {
                int off = (wm*32 + mt*16 + g)*36 + k8*8 + t;
                afb[mt][0] = __float_as_uint(Ab[off]);
                afb[mt][1] = __float_as_uint(Ab[off + 8*36]);
                afb[mt][2] = __float_as_uint(Ab[off + 4]);
                afb[mt][3] = __float_as_uint(Ab[off + 8*36 + 4]);
                afl[mt][0] = __float_as_uint(Al[off]);
                afl[mt][1] = __float_as_uint(Al[off + 8*36]);
                afl[mt][2] = __float_as_uint(Al[off + 4]);
                afl[mt][3] = __float_as_uint(Al[off + 8*36 + 4]);
            }
            uint32_t bfb[4][2], bfl[4][2];
            #pragma unroll
            for (int nt = 0; nt < 4; nt++) {
                int off = (k8*8 + t)*72 + wn*32 + nt*8 + g;
                bfb[nt][0] = __float_as_uint(Bb[off]);
                bfb[nt][1] = __float_as_uint(Bb[off + 4*72]);
                bfl[nt][0] = __float_as_uint(Bl[off]);
                bfl[nt][1] = __float_as_uint(Bl[off + 4*72]);
            }
            #pragma unroll
            for (int mt = 0; mt < 2; mt++)
                #pragma unroll
                for (int nt = 0; nt < 4; nt++) {
                    mma_tf32(acc[mt][nt], afb[mt], bfl[nt]);
                    mma_tf32(acc[mt][nt], afl[mt], bfb[nt]);
                    mma_tf32(acc[mt][nt], afb[mt], bfb[nt]);
                }
        }
        __syncthreads();
    }

    #pragma unroll
    for (int mt = 0; mt < 2; mt++) {
        int m = m0 + wm*32 + mt*16 + g;
        unsigned p0 = (unsigned)m / 20u;
        unsigned p1 = (unsigned)(m + 8) / 20u;
        #pragma unroll
        for (int nt = 0; nt < 4; nt++) {
            int c = wn*32 + nt*8 + t*2;
            float b0 = bias[c], b1 = bias[c+1];
            float v00 = fmaxf(acc[mt][nt][0] + b0, 0.f);
            float v01 = fmaxf(acc[mt][nt][1] + b1, 0.f);
            float v10 = fmaxf(acc[mt][nt][2] + b0, 0.f);
            float v11 = fmaxf(acc[mt][nt][3] + b1, 0.f);
            if (p0 == p1) {
                atomicMax((int*)out + (size_t)p0*ldo + c,     __float_as_int(fmaxf(v00, v10)));
                atomicMax((int*)out + (size_t)p0*ldo + c + 1, __float_as_int(fmaxf(v01, v11)));
            } else {
                atomicMax((int*)out + (size_t)p0*ldo + c,     __float_as_int(v00));
                atomicMax((int*)out + (size_t)p0*ldo + c + 1, __float_as_int(v01));
                atomicMax((int*)out + (size_t)p1*ldo + c,     __float_as_int(v10));
                atomicMax((int*)out + (size_t)p1*ldo + c + 1, __float_as_int(v11));
            }
        }
    }
}

// ------------------------- small FC (M=4) -------------------------
__global__ void k_fc(const float* __restrict__ A, const float* __restrict__ W, int ldw,
                     const float* __restrict__ bias, float* __restrict__ out,
                     int Kd, int Nd, int relu) {
    int t = blockIdx.x*blockDim.x + threadIdx.x;
    if (t >= BBATCH*Nd) return;
    int b = t / Nd, d = t - b*Nd;
    const float* ar = A + (size_t)b*Kd;
    float s0 = 0.f, s1 = 0.f, s2 = 0.f, s3 = 0.f;
    for (int c = 0; c < Kd; c += 4) {
        s0 += ar[c+0]*W[(size_t)(c+0)*ldw + d];
        s1 += ar[c+1]*W[(size_t)(c+1)*ldw + d];
        s2 += ar[c+2]*W[(size_t)(c+2)*ldw + d];
        s3 += ar[c+3]*W[(size_t)(c+3)*ldw + d];
    }
    float acc = bias[d] + (s0+s1) + (s2+s3);
    if (relu) acc = fmaxf(acc, 0.f);
    out[(size_t)b*Nd + d] = acc;
}

// ------------------------- final 256->2 -------------------------
__global__ void k_c4(const float* __restrict__ W, const float* __restrict__ bias,
                     float* __restrict__ out) {
    int gt = blockIdx.x*blockDim.x + threadIdx.x;
    int w = gt >> 5, lane = gt & 31;
    if (w >= NPTS) return;
    const float* a = g_c3 + (size_t)w*256;
    float s0 = 0.f, s1 = 0.f;
    #pragma unroll
    for (int t = 0; t < 8; t++) {
        int c = lane + 32*t;
        float v = a[c];
        s0 += v*W[c*2+0];
        s1 += v*W[c*2+1];
    }
    #pragma unroll
    for (int off = 16; off; off >>= 1) {
        s0 += __shfl_down_sync(0xffffffffu, s0, off);
        s1 += __shfl_down_sync(0xffffffffu, s1, off);
    }
    if (lane == 0) { out[w*2+0] = s0 + bias[0]; out[w*2+1] = s1 + bias[1]; }
}

// ------------------------- host orchestration -------------------------
static float* symaddr(const void* sym) {
    void* p = nullptr;
    cudaGetSymbolAddress(&p, sym);
    return (float*)p;
}

extern "C" void kernel_launch(void* const* d_in, const int* in_sizes, int n_in,
                              void* d_out, int out_size) {
    const float* x    = (const float*)d_in[0];
    const float* tw1  = (const float*)d_in[1];
    const float* tb1  = (const float*)d_in[2];
    const float* tw2  = (const float*)d_in[3];
    const float* tb2  = (const float*)d_in[4];
    const float* tw3  = (const float*)d_in[5];
    const float* tb3  = (const float*)d_in[6];
    const float* tfw1 = (const float*)d_in[7];
    const float* tfb1 = (const float*)d_in[8];
    const float* tfw2 = (const float*)d_in[9];
    const float* tfb2 = (const float*)d_in[10];
    const float* txw  = (const float*)d_in[11];
    const float* txb  = (const float*)d_in[12];
    const float* e1w1 = (const float*)d_in[13];
    const float* e1b1 = (const float*)d_in[14];
    const float* e1w2 = (const float*)d_in[15];
    const float* e1b2 = (const float*)d_in[16];
    const float* e2w1 = (const float*)d_in[17];
    const float* e2b1 = (const float*)d_in[18];
    const float* e2w2 = (const float*)d_in[19];
    const float* e2b2 = (const float*)d_in[20];
    const float* e3w1 = (const float*)d_in[21];
    const float* e3b1 = (const float*)d_in[22];
    const float* c1w  = (const float*)d_in[23];
    const float* c1b  = (const float*)d_in[24];
    const float* c2w  = (const float*)d_in[25];
    const float* c2b  = (const float*)d_in[26];
    const float* c3w  = (const float*)d_in[27];
    const float* c3b  = (const float*)d_in[28];
    const float* c4w  = (const float*)d_in[29];
    const float* c4b  = (const float*)d_in[30];
    float* out = (float*)d_out;

    float4* p_pts4  = (float4*)symaddr(g_pts4);
    float4* p_p4    = (float4*)symaddr(g_p4);
    float*  p_t     = symaddr(g_t);
    float*  p_cat   = symaddr(g_cat192);
    float*  p_c2    = symaddr(g_c2);
    float*  p_c3    = symaddr(g_c3);
    float*  p_tvec  = symaddr(g_tvec);
    float*  p_gvec  = symaddr(g_gvec);
    float*  p_fc1   = symaddr(g_fc1);
    float*  p_fc2   = symaddr(g_fc2);
    float*  p_xf    = symaddr(g_xf);
    float*  p_gterm = symaddr(g_gterm);

    const int SM3D = NPT*16 + KNN_WPB*KCAP*8;   // 98304
    const int SMPD = KNN_WPB*KCAP*8;            // 32768
    cudaFuncSetAttribute(k_knn<false>, cudaFuncAttributeMaxDynamicSharedMemorySize, SM3D);
    cudaFuncSetAttribute(k_knn<true>,  cudaFuncAttributeMaxDynamicSharedMemorySize, SMPD);
    cudaFuncSetAttribute((const void*)k_mma<3,3,true>,  cudaFuncAttributeMaxDynamicSharedMemorySize, SM_MMA3);
    cudaFuncSetAttribute((const void*)k_mma<1,3,false>, cudaFuncAttributeMaxDynamicSharedMemorySize, SM_MMA3);
    cudaFuncSetAttribute((const void*)k_mma<2,3,false>, cudaFuncAttributeMaxDynamicSharedMemorySize, SM_MMA3);
    cudaFuncSetAttribute((const void*)k_mma_e64,        cudaFuncAttributeMaxDynamicSharedMemorySize, SM_E64);

    const int NTRI = (NPT/128)*((NPT/128) + 1)/2;   // 528 triangle blocks
    dim3 pwgrid(NTRI, 1, BBATCH);
    const int EDGE_GY = NPTS*KNB/128;   // 2560

    // ---- knn(pts) + tnet ----
    k_pts_sq<<<NPTS/256, 256>>>(x);
    k_knn<false><<<NPTS/KNN_WPB, 512, SM3D>>>(p_pts4);
    k_prep_ab<3><<<NPTS*64/256, 256>>>((const float*)p_pts4, 4, tw1, tb1);
    cudaMemsetAsync(p_t, 0, (size_t)NPTS*128*sizeof(float));
    k_zero<<<(BBATCH*1024 + 255)/256, 256>>>();
    k_mma<3,3,true><<<dim3(1, EDGE_GY), 256, SM_MMA3>>>(nullptr, 0, tw2, 128, tb2, nullptr, p_t, 64, 128);
    k_mma<1,3,false><<<dim3(1024/128, NPTS/128), 256, SM_MMA3>>>(p_t, 128, tw3, 1024, tb3, nullptr, p_tvec, 128, 1024);
    k_fc<<<(BBATCH*512 + 127)/128, 128>>>(p_tvec, tfw1, 512, tfb1, p_fc1, 1024, 512, 1);
    k_fc<<<(BBATCH*256 + 127)/128, 128>>>(p_fc1, tfw2, 256, tfb2, p_fc2, 512, 256, 1);
    k_fc<<<1, 128>>>(p_fc2, txw, 9, txb, p_xf, 256, 9, 0);
    k_transform<<<NPTS/256, 256>>>();

    // ---- knn(p) + e1 -> x1 ----
    k_knn<false><<<NPTS/KNN_WPB, 512, SM3D>>>(p_p4);
    k_prep_ab<3><<<NPTS*64/256, 256>>>((const float*)p_p4, 4, e1w1, e1b1);
    cudaMemsetAsync(p_cat, 0, (size_t)NPTS*192*sizeof(float));
    k_mma_e64<<<dim3(1, EDGE_GY), 256, SM_E64>>>(e1w2, e1b2, p_cat + 0, 192);

    // ---- knn(x1) + e2 -> x2 ----
    k_sq64<<<NPTS*32/256, 256>>>(p_cat + 0, 192);
    k_mma<2,3,false><<<pwgrid, 256, SM_MMA3>>>(p_cat + 0, 192, p_cat + 0, 192, nullptr, nullptr, nullptr, 64, NPT);
    k_knn<true><<<NPTS/KNN_WPB, 512, SMPD>>>(nullptr);
    k_prep_ab<64><<<NPTS*64/256, 256>>>(p_cat + 0, 192, e2w1, e2b1);
    k_mma_e64<<<dim3(1, EDGE_GY), 256, SM_E64>>>(e2w2, e2b2, p_cat + 64, 192);

    // ---- knn(x2) + e3 -> x3 ----
    k_sq64<<<NPTS*32/256, 256>>>(p_cat + 64, 192);
    k_mma<2,3,false><<<pwgrid, 256, SM_MMA3>>>(p_cat + 64, 192, p_cat + 64, 192, nullptr, nullptr, nullptr, 64, NPT);
    k_knn<true><<<NPTS/KNN_WPB, 512, SMPD>>>(nullptr);
    k_prep_ab<64><<<NPTS*64/256, 256>>>(p_cat + 64, 192, e3w1, e3b1);
    k_edge_e3<<<NPTS*64/256, 256>>>(p_cat + 128, 192);

    // ---- classifier (no knn downstream -> 1xTF32) ----
    k_mma<1,1,false><<<dim3(1024/128, NPTS/128), 256, SM_MMA1>>>(p_cat, 192, c1w, 1024, c1b, nullptr, p_gvec, 192, 1024);
    k_fc<<<(BBATCH*512 + 127)/128, 128>>>(p_gvec, c2w, 512, c2b, p_gterm, 1024, 512, 0);
    k_mma<0,1,false><<<dim3(512/128, NPTS/128), 256, SM_MMA1>>>(p_cat, 192, c2w + (size_t)1024*512, 512, nullptr, p_gterm, p_c2, 192, 512);
    k_mma<0,1,false><<<dim3(256/128, NPTS/128), 256, SM_MMA1>>>(p_c2, 512, c3w, 256, c3b, nullptr, p_c3, 512, 256);
    k_c4<<<NPTS*32/256, 256>>>(c4w, c4b, out);
}

// round 14
// speedup vs baseline: 1.1095x; 1.0574x over previous
#include <cuda_runtime.h>
#include <cstdint>
#include <cstddef>

#define NPT    4096
#define BBATCH 4
#define NPTS   (BBATCH*NPT)
#define KNB    20
#define NEGINF (-3.4e38f)
#define KCAP   256
#define KNN_WPB 16

// ------------------------- device scratch -------------------------
__device__ float  g_pd[(size_t)BBATCH*NPT*NPT];   // pairwise (64-dim KNNs)
__device__ int    g_idx[NPTS*KNB];
__device__ float4 g_pts4[NPTS];
__device__ float4 g_p4[NPTS];
__device__ float  g_sq[NPTS];
__device__ float  g_aA[NPTS*64];
__device__ float  g_aB[NPTS*64];
__device__ float  g_t[(size_t)NPTS*128];
__device__ float  g_cat192[(size_t)NPTS*192];     // x1|x2|x3
__device__ float  g_c2[(size_t)NPTS*512];
__device__ float  g_c3[(size_t)NPTS*256];
__device__ float  g_tvec[BBATCH*1024];
__device__ float  g_gvec[BBATCH*1024];
__device__ float  g_fc1[BBATCH*512];
__device__ float  g_fc2[BBATCH*256];
__device__ float  g_xf[BBATCH*9];
__device__ float  g_gterm[BBATCH*512];

// ------------------------- small kernels -------------------------
__global__ void k_pts_sq(const float* __restrict__ x) {
    int i = blockIdx.x*blockDim.x + threadIdx.x;
    if (i >= NPTS) return;
    float a = x[i*6+0], b = x[i*6+1], c = x[i*6+2];
    g_pts4[i] = make_float4(a, b, c, a*a + b*b + c*c);
}

__global__ void k_transform() {
    int n = blockIdx.x*blockDim.x + threadIdx.x;
    if (n >= NPTS) return;
    int b = n >> 12;
    float4 q = g_pts4[n];
    const float* f = g_xf + b*9;
    float p0 = q.x*f[0] + q.y*f[3] + q.z*f[6];
    float p1 = q.x*f[1] + q.y*f[4] + q.z*f[7];
    float p2 = q.x*f[2] + q.y*f[5] + q.z*f[8];
    g_p4[n] = make_float4(p0, p1, p2, p0*p0 + p1*p1 + p2*p2);
}

__global__ void k_sq64(const float* __restrict__ src, int ld) {
    int gt = blockIdx.x*blockDim.x + threadIdx.x;
    int w = gt >> 5, lane = gt & 31;
    if (w >= NPTS) return;
    const float* r = src + (size_t)w*ld;
    float s = r[lane]*r[lane] + r[lane+32]*r[lane+32];
    #pragma unroll
    for (int off = 16; off; off >>= 1) s += __shfl_down_sync(0xffffffffu, s, off);
    if (lane == 0) g_sq[w] = s;
}

// ------------------------- fast exact KNN (K=20) -------------------------
template<bool PD>
__global__ void __launch_bounds__(512) k_knn(const float4* __restrict__ P4) {
    extern __shared__ float dyn[];
    int w = threadIdx.x >> 5, lane = threadIdx.x & 31;
    int row = blockIdx.x*KNN_WPB + w;
    int b = row >> 12, i = row & (NPT-1);

    float4* stash = (float4*)dyn;
    float*  bufv;
    int*    bufj;
    if (PD) { bufv = dyn + w*2*KCAP; }
    else    { bufv = dyn + NPT*4 + w*2*KCAP; }
    bufj = (int*)(bufv + KCAP);

    float xi2 = 0.f, yi2 = 0.f, zi2 = 0.f, ci = 0.f;
    const float4* pr = nullptr;
    if (!PD) {
        const float4* src = P4 + (size_t)b*NPT;
        for (int t = threadIdx.x; t < NPT; t += 512) stash[t] = src[t];
        __syncthreads();
        float4 pi = stash[i];
        xi2 = 2.f*pi.x; yi2 = 2.f*pi.y; zi2 = 2.f*pi.z; ci = -pi.w;
    } else {
        pr = (const float4*)(g_pd + (size_t)row*NPT);
    }

    float mx = NEGINF;
    if (!PD) {
        for (int t = 0; t < 128; t++) {
            float4 pj = stash[lane + t*32];
            float d = fmaf(xi2, pj.x, fmaf(yi2, pj.y, fmaf(zi2, pj.z, ci - pj.w)));
            mx = fmaxf(mx, d);
        }
    } else {
        for (int t = 0; t < 32; t++) {
            float4 v = pr[lane + t*32];
            mx = fmaxf(mx, fmaxf(fmaxf(v.x, v.y), fmaxf(v.z, v.w)));
        }
    }

    float tau = NEGINF;
    float tv = mx;
    #pragma unroll
    for (int r = 0; r < 20; r++) {
        float bv = tv;
        #pragma unroll
        for (int off = 16; off; off >>= 1)
            bv = fmaxf(bv, __shfl_xor_sync(0xffffffffu, bv, off));
        unsigned m = __ballot_sync(0xffffffffu, tv == bv);
        if (lane == (__ffs(m) - 1)) tv = NEGINF;
        tau = bv;
    }

    unsigned lmask = (1u << lane) - 1u;
    int total = 0;
    if (!PD) {
        for (int t = 0; t < 128; t++) {
            int j = lane + t*32;
            float4 pj = stash[j];
            float d = fmaf(xi2, pj.x, fmaf(yi2, pj.y, fmaf(zi2, pj.z, ci - pj.w)));
            bool keep = (d >= tau);
            unsigned mk = __ballot_sync(0xffffffffu, keep);
            if (keep) {
                int pos = total + __popc(mk & lmask);
                if (pos < KCAP) { bufv[pos] = d; bufj[pos] = j; }
            }
            total += __popc(mk);
        }
    } else {
        for (int t = 0; t < 32; t++) {
            int c = lane + t*32;
            float4 v = pr[c];
            float vals[4] = {v.x, v.y, v.z, v.w};
            #pragma unroll
            for (int e = 0; e < 4; e++) {
                bool keep = (vals[e] >= tau);
                unsigned mk = __ballot_sync(0xffffffffu, keep);
                if (keep) {
                    int pos = total + __popc(mk & lmask);
                    if (pos < KCAP) { bufv[pos] = vals[e]; bufj[pos] = c*4 + e; }
                }
                total += __popc(mk);
            }
        }
    }

    int* orow = g_idx + row*KNB;

    if (total <= KCAP) {
        int nq = (total + 31) >> 5;
        for (int r = 0; r < KNB; r++) {
            float bv = NEGINF; int bj = 0x7fffffff; int bs = -1;
            for (int q = 0; q < nq; q++) {
                int idx = lane + (q << 5);
                if (idx < total) {
                    float v = bufv[idx]; int j = bufj[idx];
                    if (v > bv || (v == bv && j < bj)) { bv = v; bj = j; bs = idx; }
                }
            }
            float lv0 = bv; int lj0 = bj;
            #pragma unroll
            for (int off = 16; off; off >>= 1) {
                float ov = __shfl_xor_sync(0xffffffffu, bv, off);
                int   oj = __shfl_xor_sync(0xffffffffu, bj, off);
                if (ov > bv || (ov == bv && oj < bj)) { bv = ov; bj = oj; }
            }
            if (lj0 == bj && lv0 == bv && bs >= 0) bufv[bs] = NEGINF;
            if (lane == 0) orow[r] = bj + (b << 12);
        }
    } else {
        float lv[KNB]; int li[KNB];
        #pragma unroll
        for (int q = 0; q < KNB; q++) { lv[q] = NEGINF; li[q] = 0x7fffffff; }
        if (!PD) {
            for (int t = 0; t < 128; t++) {
                int j = lane + t*32;
                float4 pj = stash[j];
                float val = fmaf(xi2, pj.x, fmaf(yi2, pj.y, fmaf(zi2, pj.z, ci - pj.w)));
                if (val > lv[KNB-1]) {
                    #pragma unroll
                    for (int p = KNB-1; p > 0; --p) {
                        bool below = (lv[p] >= val);
                        bool shift = (lv[p-1] < val);
                        float nl = below ? lv[p] : (shift ? lv[p-1] : val);
                        int   ni = below ? li[p] : (shift ? li[p-1] : j);
                        lv[p] = nl; li[p] = ni;
                    }
                    if (lv[0] < val) { lv[0] = val; li[0] = j; }
                }
            }
        } else {
            for (int t = 0; t < 32; t++) {
                int c = lane + t*32;
                float4 v = pr[c];
                float vals[4] = {v.x, v.y, v.z, v.w};
                #pragma unroll
                for (int e = 0; e < 4; e++) {
                    float val = vals[e]; int j = c*4 + e;
                    if (val > lv[KNB-1]) {
                        #pragma unroll
                        for (int p = KNB-1; p > 0; --p) {
                            bool below = (lv[p] >= val);
                            bool shift = (lv[p-1] < val);
                            float nl = below ? lv[p] : (shift ? lv[p-1] : val);
                            int   ni = below ? li[p] : (shift ? li[p-1] : j);
                            lv[p] = nl; li[p] = ni;
                        }
                        if (lv[0] < val) { lv[0] = val; li[0] = j; }
                    }
                }
            }
        }
        for (int r = 0; r < KNB; r++) {
            float bv = lv[0]; int bj = li[0];
            float lv0 = bv; int lj0 = bj;
            #pragma unroll
            for (int off = 16; off; off >>= 1) {
                float ov = __shfl_xor_sync(0xffffffffu, bv, off);
                int   oj = __shfl_xor_sync(0xffffffffu, bj, off);
                if (ov > bv || (ov == bv && oj < bj)) { bv = ov; bj = oj; }
            }
            if (lj0 == bj && lv0 == bv) {
                #pragma unroll
                for (int p = 0; p < KNB-1; p++) { lv[p] = lv[p+1]; li[p] = li[p+1]; }
                lv[KNB-1] = NEGINF; li[KNB-1] = 0x7fffffff;
            }
            if (lane == 0) orow[r] = bj + (b << 12);
        }
    }
}

// ------------------------- edge-conv prep -------------------------
template<int C>
__global__ void k_prep_ab(const float* __restrict__ src, int ld,
                          const float* __restrict__ W, const float* __restrict__ bias) {
    __shared__ float Ws[2*C*64];
    for (int e = threadIdx.x; e < 2*C*64; e += blockDim.x) Ws[e] = W[e];
    __syncthreads();
    int t = blockIdx.x*blockDim.x + threadIdx.x;
    int d = t & 63, n = t >> 6;
    if (n >= NPTS) return;
    const float* xr = src + (size_t)n*ld;
    float a = bias[d], bb = 0.f;
    #pragma unroll
    for (int c = 0; c < C; c++) {
        float xv = xr[c];
        float wt = Ws[c*64+d], wb = Ws[(C+c)*64+d];
        a  += xv*(wt - wb);
        bb += xv*wb;
    }
    g_aA[(size_t)n*64+d] = a;
    g_aB[(size_t)n*64+d] = bb;
}

// e3: out[n,d] = max_k relu(a[n,d] + bnb[idx[n,k],d])
__global__ void k_edge_e3(float* __restrict__ out, int ldo) {
    int t = blockIdx.x*blockDim.x + threadIdx.x;
    int d = t & 63, n = t >> 6;
    if (n >= NPTS) return;
    float a = g_aA[(size_t)n*64+d];
    const int* ir = g_idx + n*KNB;
    float m = 0.f;
    #pragma unroll
    for (int k = 0; k < KNB; k++) m = fmaxf(m, a + g_aB[(size_t)ir[k]*64 + d]);
    out[(size_t)n*ldo + d] = m;
}

// ------------------------- TF32 tensor-core GEMM -------------------------
__device__ __forceinline__ float to_tf32(float x) {
    uint32_t u;
    asm("cvt.rna.tf32.f32 %0, %1;" : "=r"(u) : "f"(x));
    return __uint_as_float(u);
}

__device__ __forceinline__ void mma_tf32(float* c, const uint32_t* a, const uint32_t* b) {
    asm volatile(
        "mma.sync.aligned.m16n8k8.row.col.f32.tf32.tf32.f32 "
        "{%0,%1,%2,%3}, {%4,%5,%6,%7}, {%8,%9}, {%0,%1,%2,%3};\n"
        : "+f"(c[0]), "+f"(c[1]), "+f"(c[2]), "+f"(c[3])
        : "r"(a[0]), "r"(a[1]), "r"(a[2]), "r"(a[3]), "r"(b[0]), "r"(b[1]));
}

#define SM_BUF   4608
#define SM_MMA3  (4*SM_BUF*4)
#define SM_MMA1  (2*SM_BUF*4)

// Block tile 128x128, 8 warps (2M x 4N), warp tile 64x32, k-stage 32.
// Register-prefetch double buffering.
// SPLIT=3: 3xTF32 (~fp32); SPLIT=1: single-pass tf32.
// GATHER: A rows are edge rows relu(g_aA[n] + g_aB[g_idx[row]]) (K=64).
// EPI: 0 = bias(+rowadd)+ReLU store; 1 = bias+ReLU+per-batch col max (atomicMax);
//      2 = SYMMETRIC pairwise: triangular grid, mirrored tile via smem transpose;
//      3 = gather edge: bias+ReLU, per-point (row/20) atomicMax into out (stride Nd).
template<int EPI, int SPLIT, bool GATHER>
__global__ void __launch_bounds__(256) k_mma(const float* __restrict__ A, int lda,
                                             const float* __restrict__ B, int ldb,
                                             const float* __restrict__ bias,
                                             const float* __restrict__ rowadd,
                                             float* __restrict__ out,
                                             int Kd, int Nd) {
    extern __shared__ float dynsm[];
    float* Ab = dynsm;
    float* Al = dynsm + SM_BUF;                          // SPLIT==3 only
    float* Bb = dynsm + (SPLIT == 3 ? 2 : 1)*SM_BUF;
    float* Bl = dynsm + 3*SM_BUF;                        // SPLIT==3 only
    int m0, n0;
    bool diag = false;
    if (EPI == 2) {
        int tb = blockIdx.x;
        int by = (int)((sqrtf(8.f*tb + 1.f) - 1.f)*0.5f);
        while ((by + 1)*(by + 2)/2 <= tb) by++;
        while (by*(by + 1)/2 > tb) by--;
        int bx = tb - by*(by + 1)/2;
        m0 = by*128; n0 = bx*128;
        diag = (bx == by);
    } else {
        m0 = blockIdx.y*128; n0 = blockIdx.x*128;
    }
    int tid = threadIdx.x;
    int w = tid >> 5, lane = tid & 31;
    int wm = w & 1, wn = w >> 1;
    int g = lane >> 2, t = lane & 3;
    size_t rowbase = (EPI == 2) ? (size_t)blockIdx.z*NPT : 0;

    int a_r  = tid >> 3, a_c4 = (tid & 7)*4;
    int bw_r = tid >> 5, bw_c4 = (tid & 31)*4;

    float4 pA[4], pB[4];

    auto loadA = [&](int kk) {
        #pragma unroll
        for (int i = 0; i < 4; i++) {
            int r = a_r + i*32;
            if (GATHER) {
                unsigned gr = m0 + r;
                unsigned n = gr / 20u;
                int j = g_idx[gr];
                float4 va = *(const float4*)(g_aA + (size_t)n*64 + kk + a_c4);
                float4 vb = *(const float4*)(g_aB + (size_t)j*64 + kk + a_c4);
                pA[i].x = fmaxf(va.x + vb.x, 0.f);
                pA[i].y = fmaxf(va.y + vb.y, 0.f);
                pA[i].z = fmaxf(va.z + vb.z, 0.f);
                pA[i].w = fmaxf(va.w + vb.w, 0.f);
            } else {
                pA[i] = *(const float4*)(A + (rowbase + m0 + r)*lda + kk + a_c4);
            }
        }
    };
    auto loadB = [&](int kk) {
        #pragma unroll
        for (int i = 0; i < 4; i++) {
            if (EPI == 2) {
                int r = a_r + i*32;
                pB[i] = *(const float4*)(B + (rowbase + n0 + r)*ldb + kk + a_c4);
            } else {
                int r = bw_r + i*8;
                pB[i] = *(const float4*)(B + (size_t)(kk + r)*ldb + n0 + bw_c4);
            }
        }
    };

    float acc[4][4][4];
    #pragma unroll
    for (int mt = 0; mt < 4; mt++)
        #pragma unroll
        for (int nt = 0; nt < 4; nt++)
            #pragma unroll
            for (int r = 0; r < 4; r++) acc[mt][nt][r] = 0.f;

    loadA(0);
    loadB(0);

    for (int kk = 0; kk < Kd; kk += 32) {
        // stage prefetched A
        #pragma unroll
        for (int i = 0; i < 4; i++) {
            int r = a_r + i*32;
            float4 v = pA[i];
            float bx = to_tf32(v.x), by = to_tf32(v.y), bz = to_tf32(v.z), bw = to_tf32(v.w);
            float* db = &Ab[r*36 + a_c4];
            db[0] = bx; db[1] = by; db[2] = bz; db[3] = bw;
            if (SPLIT == 3) {
                float* dl = &Al[r*36 + a_c4];
                dl[0] = to_tf32(v.x - bx); dl[1] = to_tf32(v.y - by);
                dl[2] = to_tf32(v.z - bz); dl[3] = to_tf32(v.w - bw);
            }
        }
        // stage prefetched B
        #pragma unroll
        for (int i = 0; i < 4; i++) {
            float4 v = pB[i];
            float bx = to_tf32(v.x), by = to_tf32(v.y), bz = to_tf32(v.z), bw = to_tf32(v.w);
            if (EPI == 2) {
                int r = a_r + i*32;
                float* db = &Bb[r*36 + a_c4];
                db[0] = bx; db[1] = by; db[2] = bz; db[3] = bw;
                if (SPLIT == 3) {
                    float* dl = &Bl[r*36 + a_c4];
                    dl[0] = to_tf32(v.x - bx); dl[1] = to_tf32(v.y - by);
                    dl[2] = to_tf32(v.z - bz); dl[3] = to_tf32(v.w - bw);
                }
            } else {
                int r = bw_r + i*8;
                float* db = &Bb[r*136 + bw_c4];
                db[0] = bx; db[1] = by; db[2] = bz; db[3] = bw;
                if (SPLIT == 3) {
                    float* dl = &Bl[r*136 + bw_c4];
                    dl[0] = to_tf32(v.x - bx); dl[1] = to_tf32(v.y - by);
                    dl[2] = to_tf32(v.z - bz); dl[3] = to_tf32(v.w - bw);
                }
            }
        }
        __syncthreads();
        // prefetch next tile (overlaps with MMA below)
        if (kk + 32 < Kd) { loadA(kk + 32); loadB(kk + 32); }

        #pragma unroll
        for (int k8 = 0; k8 < 4; k8++) {
            uint32_t afb[4][4], afl[4][4];
            #pragma unroll
            for (int mt = 0; mt < 4; mt++) {
                int off = (wm*64 + mt*16 + g)*36 + k8*8 + t;
                afb[mt][0] = __float_as_uint(Ab[off]);
                afb[mt][1] = __float_as_uint(Ab[off + 8*36]);
                afb[mt][2] = __float_as_uint(Ab[off + 4]);
                afb[mt][3] = __float_as_uint(Ab[off + 8*36 + 4]);
                if (SPLIT == 3) {
                    afl[mt][0] = __float_as_uint(Al[off]);
                    afl[mt][1] = __float_as_uint(Al[off + 8*36]);
                    afl[mt][2] = __float_as_uint(Al[off + 4]);
                    afl[mt][3] = __float_as_uint(Al[off + 8*36 + 4]);
                }
            }
            uint32_t bfb[4][2], bfl[4][2];
            #pragma unroll
            for (int nt = 0; nt < 4; nt++) {
                if (EPI == 2) {
                    int off = (wn*32 + nt*8 + g)*36 + k8*8 + t;
                    bfb[nt][0] = __float_as_uint(Bb[off]);
                    bfb[nt][1] = __float_as_uint(Bb[off + 4]);
                    if (SPLIT == 3) {
                        bfl[nt][0] = __float_as_uint(Bl[off]);
                        bfl[nt][1] = __float_as_uint(Bl[off + 4]);
                    }
                } else {
                    int off = (k8*8 + t)*136 + wn*32 + nt*8 + g;
                    bfb[nt][0] = __float_as_uint(Bb[off]);
                    bfb[nt][1] = __float_as_uint(Bb[off + 4*136]);
                    if (SPLIT == 3) {
                        bfl[nt][0] = __float_as_uint(Bl[off]);
                        bfl[nt][1] = __float_as_uint(Bl[off + 4*136]);
                    }
                }
            }
            #pragma unroll
            for (int mt = 0; mt < 4; mt++)
                #pragma unroll
                for (int nt = 0; nt < 4; nt++) {
                    if (SPLIT == 3) {
                        mma_tf32(acc[mt][nt], afb[mt], bfl[nt]);
                        mma_tf32(acc[mt][nt], afl[mt], bfb[nt]);
                    }
                    mma_tf32(acc[mt][nt], afb[mt], bfb[nt]);
                }
        }
        __syncthreads();
    }

    if (EPI == 2) {
        int b = blockIdx.z;
        float* tile = dynsm;   // reuse: 128 x 132 transpose stage
        #pragma unroll
        for (int mt = 0; mt < 4; mt++) {
            int mA = wm*64 + mt*16 + g;
            int mB = mA + 8;
            float sqm  = g_sq[(size_t)b*NPT + m0 + mA];
            float sqm8 = g_sq[(size_t)b*NPT + m0 + mB];
            float* r0 = g_pd + ((size_t)b*NPT + m0 + mA)*NPT;
            float* r1 = g_pd + ((size_t)b*NPT + m0 + mB)*NPT;
            #pragma unroll
            for (int nt = 0; nt < 4; nt++) {
                int nl = wn*32 + nt*8 + t*2;
                float sqn  = g_sq[(size_t)b*NPT + n0 + nl];
                float sqn1 = g_sq[(size_t)b*NPT + n0 + nl + 1];
                float d00 = 2.f*acc[mt][nt][0] - sqm  - sqn;
                float d01 = 2.f*acc[mt][nt][1] - sqm  - sqn1;
                float d10 = 2.f*acc[mt][nt][2] - sqm8 - sqn;
                float d11 = 2.f*acc[mt][nt][3] - sqm8 - sqn1;
                *(float2*)(r0 + n0 + nl) = make_float2(d00, d01);
                *(float2*)(r1 + n0 + nl) = make_float2(d10, d11);
                if (!diag) {
                    tile[(nl  )*132 + mA] = d00;
                    tile[(nl+1)*132 + mA] = d01;
                    tile[(nl  )*132 + mB] = d10;
                    tile[(nl+1)*132 + mB] = d11;
                }
            }
        }
        if (!diag) {
            __syncthreads();
            #pragma unroll
            for (int i = 0; i < 16; i++) {
                int idx = tid + i*256;
                int r = idx >> 5, c4 = (idx & 31)*4;
                float4 v = *(float4*)&tile[r*132 + c4];
                *(float4*)(g_pd + ((size_t)b*NPT + n0 + r)*NPT + m0 + c4) = v;
            }
        }
    } else if (EPI == 0) {
        int b = m0 >> 12;
        #pragma unroll
        for (int mt = 0; mt < 4; mt++) {
            int m = m0 + wm*64 + mt*16 + g;
            #pragma unroll
            for (int nt = 0; nt < 4; nt++) {
                int n = n0 + wn*32 + nt*8 + t*2;
                float add0 = 0.f, add1 = 0.f;
                if (bias)   { add0 += bias[n]; add1 += bias[n+1]; }
                if (rowadd) { add0 += rowadd[b*Nd + n]; add1 += rowadd[b*Nd + n + 1]; }
                float2 v0, v1;
                v0.x = fmaxf(acc[mt][nt][0] + add0, 0.f);
                v0.y = fmaxf(acc[mt][nt][1] + add1, 0.f);
                v1.x = fmaxf(acc[mt][nt][2] + add0, 0.f);
                v1.y = fmaxf(acc[mt][nt][3] + add1, 0.f);
                *(float2*)(out + (size_t)m*Nd + n) = v0;
                *(float2*)(out + (size_t)(m+8)*Nd + n) = v1;
            }
        }
    } else if (EPI == 1) {
        int b = m0 >> 12;
        #pragma unroll
        for (int nt = 0; nt < 4; nt++) {
            int n = n0 + wn*32 + nt*8 + t*2;
            float m0v = NEGINF, m1v = NEGINF;
            #pragma unroll
            for (int mt = 0; mt < 4; mt++) {
                m0v = fmaxf(m0v, fmaxf(acc[mt][nt][0], acc[mt][nt][2]));
                m1v = fmaxf(m1v, fmaxf(acc[mt][nt][1], acc[mt][nt][3]));
            }
            m0v = fmaxf(m0v + bias[n], 0.f);
            m1v = fmaxf(m1v + bias[n+1], 0.f);
            #pragma unroll
            for (int off = 4; off < 32; off <<= 1) {
                m0v = fmaxf(m0v, __shfl_xor_sync(0xffffffffu, m0v, off));
                m1v = fmaxf(m1v, __shfl_xor_sync(0xffffffffu, m1v, off));
            }
            if (g == 0) {
                atomicMax((int*)out + (size_t)b*Nd + n,     __float_as_int(m0v));
                atomicMax((int*)out + (size_t)b*Nd + n + 1, __float_as_int(m1v));
            }
        }
    } else {
        // EPI == 3: gather-edge fused k-max. out stride = Nd, point = row/20.
        #pragma unroll
        for (int mt = 0; mt < 4; mt++) {
            int m = m0 + wm*64 + mt*16 + g;
            unsigned p0 = (unsigned)m / 20u;
            unsigned p1 = (unsigned)(m + 8) / 20u;
            #pragma unroll
            for (int nt = 0; nt < 4; nt++) {
                int n = n0 + wn*32 + nt*8 + t*2;
                float b0 = bias[n], b1 = bias[n+1];
                float v00 = fmaxf(acc[mt][nt][0] + b0, 0.f);
                float v01 = fmaxf(acc[mt][nt][1] + b1, 0.f);
                float v10 = fmaxf(acc[mt][nt][2] + b0, 0.f);
                float v11 = fmaxf(acc[mt][nt][3] + b1, 0.f);
                if (p0 == p1) {
                    atomicMax((int*)out + (size_t)p0*Nd + n,     __float_as_int(fmaxf(v00, v10)));
                    atomicMax((int*)out + (size_t)p0*Nd + n + 1, __float_as_int(fmaxf(v01, v11)));
                } else {
                    atomicMax((int*)out + (size_t)p0*Nd + n,     __float_as_int(v00));
                    atomicMax((int*)out + (size_t)p0*Nd + n + 1, __float_as_int(v01));
                    atomicMax((int*)out + (size_t)p1*Nd + n,     __float_as_int(v10));
                    atomicMax((int*)out + (size_t)p1*Nd + n + 1, __float_as_int(v11));
                }
            }
        }
    }
}

// ------------- edge GEMM, N=64 tile (gathered A, 3xTF32, fused k-max) -------------
#define SM_E64 ((2*4608 + 2*2304)*4)
__global__ void __launch_bounds__(256) k_mma_e64(const float* __restrict__ W,
                                                 const float* __restrict__ bias,
                                                 float* __restrict__ out, int ldo) {
    extern __shared__ float dynsm[];
    float* Ab = dynsm;                 // [128][36]
    float* Al = dynsm + 4608;
    float* Bb = dynsm + 2*4608;        // [32][72]
    float* Bl = dynsm + 2*4608 + 2304;
    int m0 = blockIdx.y*128;
    int tid = threadIdx.x;
    int w = tid >> 5, lane = tid & 31;
    int wm = w & 3, wn = w >> 2;
    int g = lane >> 2, t = lane & 3;

    int a_r  = tid >> 3, a_c4 = (tid & 7)*4;
    int bw_r = tid >> 4, bw_c4 = (tid & 15)*4;

    float4 pA[4], pB[2];

    auto loadA = [&](int kk) {
        #pragma unroll
        for (int i = 0; i < 4; i++) {
            int r = a_r + i*32;
            unsigned gr = m0 + r;
            unsigned n = gr / 20u;
            int j = g_idx[gr];
            float4 va = *(const float4*)(g_aA + (size_t)n*64 + kk + a_c4);
            float4 vb = *(const float4*)(g_aB + (size_t)j*64 + kk + a_c4);
            pA[i].x = fmaxf(va.x + vb.x, 0.f);
            pA[i].y = fmaxf(va.y + vb.y, 0.f);
            pA[i].z = fmaxf(va.z + vb.z, 0.f);
            pA[i].w = fmaxf(va.w + vb.w, 0.f);
        }
    };
    auto loadB = [&](int kk) {
        #pragma unroll
        for (int i = 0; i < 2; i++) {
            int r = bw_r + i*16;
            pB[i] = *(const float4*)(W + (size_t)(kk + r)*64 + bw_c4);
        }
    };

    float acc[2][4][4];
    #pragma unroll
    for (int mt = 0; mt < 2; mt++)
        #pragma unroll
        for (int nt = 0; nt < 4; nt++)
            #pragma unroll
            for (int r = 0; r < 4; r++) acc[mt][nt][r] = 0.f;

    loadA(0);
    loadB(0);

    for (int kk = 0; kk < 64; kk += 32) {
        #pragma unroll
        for (int i = 0; i < 4; i++) {
            int r = a_r + i*32;
            float4 v = pA[i];
            float bx = to_tf32(v.x), by = to_tf32(v.y), bz = to_tf32(v.z), bw = to_tf32(v.w);
            float* db = &Ab[r*36 + a_c4];
            float* dl = &Al[r*36 + a_c4];
            db[0] = bx; db[1] = by; db[2] = bz; db[3] = bw;
            dl[0] = to_tf32(v.x - bx); dl[1] = to_tf32(v.y - by);
            dl[2] = to_tf32(v.z - bz); dl[3] = to_tf32(v.w - bw);
        }
        #pragma unroll
        for (int i = 0; i < 2; i++) {
            int r = bw_r + i*16;
            float4 v = pB[i];
            float bx = to_tf32(v.x), by = to_tf32(v.y), bz = to_tf32(v.z), bw = to_tf32(v.w);
            float* db = &Bb[r*72 + bw_c4];
            float* dl = &Bl[r*72 + bw_c4];
            db[0] = bx; db[1] = by; db[2] = bz; db[3] = bw;
            dl[0] = to_tf32(v.x - bx); dl[1] = to_tf32(v.y - by);
            dl[2] = to_tf32(v.z - bz); dl[3] = to_tf32(v.w - bw);
        }
        __syncthreads();
        if (kk + 32 < 64) { loadA(kk + 32); loadB(kk + 32); }

        #pragma unroll
        for (int k8 = 0; k8 < 4; k8++) {
            uint32_t afb[2][4], afl[2][4];
            #pragma unroll
            for (int mt = 0; mt < 2; mt++) {
                int off = (wm*32 + mt*16 + g)*36 + k8*8 + t;
                afb[mt][0] = __float_as_uint(Ab[off]);
                afb[mt][1] = __float_as_uint(Ab[off + 8*36]);
                afb[mt][2] = __float_as_uint(Ab[off + 4]);
                afb[mt][3] = __float_as_uint(Ab[off + 8*36 + 4]);
                afl[mt][0] = __float_as_uint(Al[off]);
                afl[mt][1] = __float_as_uint(Al[off + 8*36]);
                afl[mt][2] = __float_as_uint(Al[off + 4]);
                afl[mt][3] = __float_as_uint(Al[off + 8*36 + 4]);
            }
            uint32_t bfb[4][2], bfl[4][2];
            #pragma unroll
            for (int nt = 0; nt < 4; nt++) {
                int off = (k8*8 + t)*72 + wn*32 + nt*8 + g;
                bfb[nt][0] = __float_as_uint(Bb[off]);
                bfb[nt][1] = __float_as_uint(Bb[off + 4*72]);
                bfl[nt][0] = __float_as_uint(Bl[off]);
                bfl[nt][1] = __float_as_uint(Bl[off + 4*72]);
            }
            #pragma unroll
            for (int mt = 0; mt < 2; mt++)
                #pragma unroll
                for (int nt = 0; nt < 4; nt++) {
                    mma_tf32(acc[mt][nt], afb[mt], bfl[nt]);
                    mma_tf32(acc[mt][nt], afl[mt], bfb[nt]);
                    mma_tf32(acc[mt][nt], afb[mt], bfb[nt]);
                }
        }
        __syncthreads();
    }

    #pragma unroll
    for (int mt = 0; mt < 2; mt++) {
        int m = m0 + wm*32 + mt*16 + g;
        unsigned p0 = (unsigned)m / 20u;
        unsigned p1 = (unsigned)(m + 8) / 20u;
        #pragma unroll
        for (int nt = 0; nt < 4; nt++) {
            int c = wn*32 + nt*8 + t*2;
            float b0 = bias[c], b1 = bias[c+1];
            float v00 = fmaxf(acc[mt][nt][0] + b0, 0.f);
            float v01 = fmaxf(acc[mt][nt][1] + b1, 0.f);
            float v10 = fmaxf(acc[mt][nt][2] + b0, 0.f);
            float v11 = fmaxf(acc[mt][nt][3] + b1, 0.f);
            if (p0 == p1) {
                atomicMax((int*)out + (size_t)p0*ldo + c,     __float_as_int(fmaxf(v00, v10)));
                atomicMax((int*)out + (size_t)p0*ldo + c + 1, __float_as_int(fmaxf(v01, v11)));
            } else {
                atomicMax((int*)out + (size_t)p0*ldo + c,     __float_as_int(v00));
                atomicMax((int*)out + (size_t)p0*ldo + c + 1, __float_as_int(v01));
                atomicMax((int*)out + (size_t)p1*ldo + c,     __float_as_int(v10));
                atomicMax((int*)out + (size_t)p1*ldo + c + 1, __float_as_int(v11));
            }
        }
    }
}

// ------------------------- small FC (M=4) -------------------------
__global__ void k_fc(const float* __restrict__ A, const float* __restrict__ W, int ldw,
                     const float* __restrict__ bias, float* __restrict__ out,
                     int Kd, int Nd, int relu) {
    int t = blockIdx.x*blockDim.x + threadIdx.x;
    if (t >= BBATCH*Nd) return;
    int b = t / Nd, d = t - b*Nd;
    const float* ar = A + (size_t)b*Kd;
    float s0 = 0.f, s1 = 0.f, s2 = 0.f, s3 = 0.f;
    for (int c = 0; c < Kd; c += 4) {
        s0 += ar[c+0]*W[(size_t)(c+0)*ldw + d];
        s1 += ar[c+1]*W[(size_t)(c+1)*ldw + d];
        s2 += ar[c+2]*W[(size_t)(c+2)*ldw + d];
        s3 += ar[c+3]*W[(size_t)(c+3)*ldw + d];
    }
    float acc = bias[d] + (s0+s1) + (s2+s3);
    if (relu) acc = fmaxf(acc, 0.f);
    out[(size_t)b*Nd + d] = acc;
}

// ------------------------- final 256->2 -------------------------
__global__ void k_c4(const float* __restrict__ W, const float* __restrict__ bias,
                     float* __restrict__ out) {
    int gt = blockIdx.x*blockDim.x + threadIdx.x;
    int w = gt >> 5, lane = gt & 31;
    if (w >= NPTS) return;
    const float* a = g_c3 + (size_t)w*256;
    float s0 = 0.f, s1 = 0.f;
    #pragma unroll
    for (int t = 0; t < 8; t++) {
        int c = lane + 32*t;
        float v = a[c];
        s0 += v*W[c*2+0];
        s1 += v*W[c*2+1];
    }
    #pragma unroll
    for (int off = 16; off; off >>= 1) {
        s0 += __shfl_down_sync(0xffffffffu, s0, off);
        s1 += __shfl_down_sync(0xffffffffu, s1, off);
    }
    if (lane == 0) { out[w*2+0] = s0 + bias[0]; out[w*2+1] = s1 + bias[1]; }
}

// ------------------------- host orchestration -------------------------
static float* symaddr(const void* sym) {
    void* p = nullptr;
    cudaGetSymbolAddress(&p, sym);
    return (float*)p;
}

extern "C" void kernel_launch(void* const* d_in, const int* in_sizes, int n_in,
                              void* d_out, int out_size) {
    const float* x    = (const float*)d_in[0];
    const float* tw1  = (const float*)d_in[1];
    const float* tb1  = (const float*)d_in[2];
    const float* tw2  = (const float*)d_in[3];
    const float* tb2  = (const float*)d_in[4];
    const float* tw3  = (const float*)d_in[5];
    const float* tb3  = (const float*)d_in[6];
    const float* tfw1 = (const float*)d_in[7];
    const float* tfb1 = (const float*)d_in[8];
    const float* tfw2 = (const float*)d_in[9];
    const float* tfb2 = (const float*)d_in[10];
    const float* txw  = (const float*)d_in[11];
    const float* txb  = (const float*)d_in[12];
    const float* e1w1 = (const float*)d_in[13];
    const float* e1b1 = (const float*)d_in[14];
    const float* e1w2 = (const float*)d_in[15];
    const float* e1b2 = (const float*)d_in[16];
    const float* e2w1 = (const float*)d_in[17];
    const float* e2b1 = (const float*)d_in[18];
    const float* e2w2 = (const float*)d_in[19];
    const float* e2b2 = (const float*)d_in[20];
    const float* e3w1 = (const float*)d_in[21];
    const float* e3b1 = (const float*)d_in[22];
    const float* c1w  = (const float*)d_in[23];
    const float* c1b  = (const float*)d_in[24];
    const float* c2w  = (const float*)d_in[25];
    const float* c2b  = (const float*)d_in[26];
    const float* c3w  = (const float*)d_in[27];
    const float* c3b  = (const float*)d_in[28];
    const float* c4w  = (const float*)d_in[29];
    const float* c4b  = (const float*)d_in[30];
    float* out = (float*)d_out;

    float4* p_pts4  = (float4*)symaddr(g_pts4);
    float4* p_p4    = (float4*)symaddr(g_p4);
    float*  p_t     = symaddr(g_t);
    float*  p_cat   = symaddr(g_cat192);
    float*  p_c2    = symaddr(g_c2);
    float*  p_c3    = symaddr(g_c3);
    float*  p_tvec  = symaddr(g_tvec);
    float*  p_gvec  = symaddr(g_gvec);
    float*  p_fc1   = symaddr(g_fc1);
    float*  p_fc2   = symaddr(g_fc2);
    float*  p_xf    = symaddr(g_xf);
    float*  p_gterm = symaddr(g_gterm);

    const int SM3D = NPT*16 + KNN_WPB*KCAP*8;   // 98304
    const int SMPD = KNN_WPB*KCAP*8;            // 32768
    cudaFuncSetAttribute(k_knn<false>, cudaFuncAttributeMaxDynamicSharedMemorySize, SM3D);
    cudaFuncSetAttribute(k_knn<true>,  cudaFuncAttributeMaxDynamicSharedMemorySize, SMPD);
    cudaFuncSetAttribute((const void*)k_mma<3,1,true>,  cudaFuncAttributeMaxDynamicSharedMemorySize, SM_MMA1);
    cudaFuncSetAttribute((const void*)k_mma<2,3,false>, cudaFuncAttributeMaxDynamicSharedMemorySize, SM_MMA3);
    cudaFuncSetAttribute((const void*)k_mma_e64,        cudaFuncAttributeMaxDynamicSharedMemorySize, SM_E64);

    const int NTRI = (NPT/128)*((NPT/128) + 1)/2;   // 528 triangle blocks
    dim3 pwgrid(NTRI, 1, BBATCH);
    const int EDGE_GY = NPTS*KNB/128;   // 2560

    // ---- knn(pts) + tnet (tnet GEMMs 1xTF32: output only enters via near-identity xf) ----
    k_pts_sq<<<NPTS/256, 256>>>(x);
    k_knn<false><<<NPTS/KNN_WPB, 512, SM3D>>>(p_pts4);
    k_prep_ab<3><<<NPTS*64/256, 256>>>((const float*)p_pts4, 4, tw1, tb1);
    cudaMemsetAsync(p_t,    0, (size_t)NPTS*128*sizeof(float));
    cudaMemsetAsync(p_tvec, 0, (size_t)BBATCH*1024*sizeof(float));
    cudaMemsetAsync(p_gvec, 0, (size_t)BBATCH*1024*sizeof(float));
    k_mma<3,1,true><<<dim3(1, EDGE_GY), 256, SM_MMA1>>>(nullptr, 0, tw2, 128, tb2, nullptr, p_t, 64, 128);
    k_mma<1,1,false><<<dim3(1024/128, NPTS/128), 256, SM_MMA1>>>(p_t, 128, tw3, 1024, tb3, nullptr, p_tvec, 128, 1024);
    k_fc<<<(BBATCH*512 + 127)/128, 128>>>(p_tvec, tfw1, 512, tfb1, p_fc1, 1024, 512, 1);
    k_fc<<<(BBATCH*256 + 127)/128, 128>>>(p_fc1, tfw2, 256, tfb2, p_fc2, 512, 256, 1);
    k_fc<<<1, 128>>>(p_fc2, txw, 9, txb, p_xf, 256, 9, 0);
    k_transform<<<NPTS/256, 256>>>();

    // ---- knn(p) + e1 -> x1 ----
    k_knn<false><<<NPTS/KNN_WPB, 512, SM3D>>>(p_p4);
    k_prep_ab<3><<<NPTS*64/256, 256>>>((const float*)p_p4, 4, e1w1, e1b1);
    cudaMemsetAsync(p_cat, 0, (size_t)NPTS*192*sizeof(float));
    k_mma_e64<<<dim3(1, EDGE_GY), 256, SM_E64>>>(e1w2, e1b2, p_cat + 0, 192);

    // ---- knn(x1) + e2 -> x2 ----
    k_sq64<<<NPTS*32/256, 256>>>(p_cat + 0, 192);
    k_mma<2,3,false><<<pwgrid, 256, SM_MMA3>>>(p_cat + 0, 192, p_cat + 0, 192, nullptr, nullptr, nullptr, 64, NPT);
    k_knn<true><<<NPTS/KNN_WPB, 512, SMPD>>>(nullptr);
    k_prep_ab<64><<<NPTS*64/256, 256>>>(p_cat + 0, 192, e2w1, e2b1);
    k_mma_e64<<<dim3(1, EDGE_GY), 256, SM_E64>>>(e2w2, e2b2, p_cat + 64, 192);

    // ---- knn(x2) + e3 -> x3 ----
    k_sq64<<<NPTS*32/256, 256>>>(p_cat + 64, 192);
    k_mma<2,3,false><<<pwgrid, 256, SM_MMA3>>>(p_cat + 64, 192, p_cat + 64, 192, nullptr, nullptr, nullptr, 64, NPT);
    k_knn<true><<<NPTS/KNN_WPB, 512, SMPD>>>(nullptr);
    k_prep_ab<64><<<NPTS*64/256, 256>>>(p_cat + 64, 192, e3w1, e3b1);
    k_edge_e3<<<NPTS*64/256, 256>>>(p_cat + 128, 192);

    // ---- classifier (no knn downstream -> 1xTF32) ----
    k_mma<1,1,false><<<dim3(1024/128, NPTS/128), 256, SM_MMA1>>>(p_cat, 192, c1w, 1024, c1b, nullptr, p_gvec, 192, 1024);
    k_fc<<<(BBATCH*512 + 127)/128, 128>>>(p_gvec, c2w, 512, c2b, p_gterm, 1024, 512, 0);
    k_mma<0,1,false><<<dim3(512/128, NPTS/128), 256, SM_MMA1>>>(p_cat, 192, c2w + (size_t)1024*512, 512, nullptr, p_gterm, p_c2, 192, 512);
    k_mma<0,1,false><<<dim3(256/128, NPTS/128), 256, SM_MMA1>>>(p_c2, 512, c3w, 256, c3b, nullptr, p_c3, 512, 256);
    k_c4<<<NPTS*32/256, 256>>>(c4w, c4b, out);
}

// round 15
// speedup vs baseline: 1.1117x; 1.0020x over previous
#include <cuda_runtime.h>
#include <cstdint>
#include <cstddef>

#define NPT    4096
#define BBATCH 4
#define NPTS   (BBATCH*NPT)
#define KNB    20
#define NEGINF (-3.4e38f)
#define KCAP   256
#define KNN_WPB 16

// ------------------------- device scratch -------------------------
__device__ float  g_pd[(size_t)BBATCH*NPT*NPT];   // pairwise (64-dim KNNs)
__device__ int    g_idx[NPTS*KNB];
__device__ float4 g_pts4[NPTS];
__device__ float4 g_p4[NPTS];
__device__ float  g_sq[NPTS];
__device__ float  g_aA[NPTS*64];
__device__ float  g_aB[NPTS*64];
__device__ float  g_t[(size_t)NPTS*128];
__device__ float  g_cat192[(size_t)NPTS*192];     // x1|x2|x3
__device__ float  g_c2[(size_t)NPTS*512];
__device__ float  g_c3[(size_t)NPTS*256];
__device__ float  g_tvec[BBATCH*1024];
__device__ float  g_gvec[BBATCH*1024];
__device__ float  g_fc1[BBATCH*512];
__device__ float  g_fc2[BBATCH*256];
__device__ float  g_xf[BBATCH*9];
__device__ float  g_gterm[BBATCH*512];

// ------------------------- small kernels -------------------------
__global__ void k_pts_sq(const float* __restrict__ x) {
    int i = blockIdx.x*blockDim.x + threadIdx.x;
    if (i >= NPTS) return;
    float a = x[i*6+0], b = x[i*6+1], c = x[i*6+2];
    g_pts4[i] = make_float4(a, b, c, a*a + b*b + c*c);
}

__global__ void k_transform() {
    int n = blockIdx.x*blockDim.x + threadIdx.x;
    if (n >= NPTS) return;
    int b = n >> 12;
    float4 q = g_pts4[n];
    const float* f = g_xf + b*9;
    float p0 = q.x*f[0] + q.y*f[3] + q.z*f[6];
    float p1 = q.x*f[1] + q.y*f[4] + q.z*f[7];
    float p2 = q.x*f[2] + q.y*f[5] + q.z*f[8];
    g_p4[n] = make_float4(p0, p1, p2, p0*p0 + p1*p1 + p2*p2);
}

__global__ void k_sq64(const float* __restrict__ src, int ld) {
    int gt = blockIdx.x*blockDim.x + threadIdx.x;
    int w = gt >> 5, lane = gt & 31;
    if (w >= NPTS) return;
    const float* r = src + (size_t)w*ld;
    float s = r[lane]*r[lane] + r[lane+32]*r[lane+32];
    #pragma unroll
    for (int off = 16; off; off >>= 1) s += __shfl_down_sync(0xffffffffu, s, off);
    if (lane == 0) g_sq[w] = s;
}

// ------------------------- fast exact KNN (K=20) -------------------------
template<bool PD>
__global__ void __launch_bounds__(512) k_knn(const float4* __restrict__ P4) {
    extern __shared__ float dyn[];
    int w = threadIdx.x >> 5, lane = threadIdx.x & 31;
    int row = blockIdx.x*KNN_WPB + w;
    int b = row >> 12, i = row & (NPT-1);

    float4* stash = (float4*)dyn;
    float*  bufv;
    int*    bufj;
    if (PD) { bufv = dyn + w*2*KCAP; }
    else    { bufv = dyn + NPT*4 + w*2*KCAP; }
    bufj = (int*)(bufv + KCAP);

    float xi2 = 0.f, yi2 = 0.f, zi2 = 0.f, ci = 0.f;
    const float4* pr = nullptr;
    if (!PD) {
        const float4* src = P4 + (size_t)b*NPT;
        for (int t = threadIdx.x; t < NPT; t += 512) stash[t] = src[t];
        __syncthreads();
        float4 pi = stash[i];
        xi2 = 2.f*pi.x; yi2 = 2.f*pi.y; zi2 = 2.f*pi.z; ci = -pi.w;
    } else {
        pr = (const float4*)(g_pd + (size_t)row*NPT);
    }

    float mx = NEGINF;
    if (!PD) {
        for (int t = 0; t < 128; t++) {
            float4 pj = stash[lane + t*32];
            float d = fmaf(xi2, pj.x, fmaf(yi2, pj.y, fmaf(zi2, pj.z, ci - pj.w)));
            mx = fmaxf(mx, d);
        }
    } else {
        for (int t = 0; t < 32; t++) {
            float4 v = pr[lane + t*32];
            mx = fmaxf(mx, fmaxf(fmaxf(v.x, v.y), fmaxf(v.z, v.w)));
        }
    }

    float tau = NEGINF;
    float tv = mx;
    #pragma unroll
    for (int r = 0; r < 20; r++) {
        float bv = tv;
        #pragma unroll
        for (int off = 16; off; off >>= 1)
            bv = fmaxf(bv, __shfl_xor_sync(0xffffffffu, bv, off));
        unsigned m = __ballot_sync(0xffffffffu, tv == bv);
        if (lane == (__ffs(m) - 1)) tv = NEGINF;
        tau = bv;
    }

    unsigned lmask = (1u << lane) - 1u;
    int total = 0;
    if (!PD) {
        for (int t = 0; t < 128; t++) {
            int j = lane + t*32;
            float4 pj = stash[j];
            float d = fmaf(xi2, pj.x, fmaf(yi2, pj.y, fmaf(zi2, pj.z, ci - pj.w)));
            bool keep = (d >= tau);
            unsigned mk = __ballot_sync(0xffffffffu, keep);
            if (keep) {
                int pos = total + __popc(mk & lmask);
                if (pos < KCAP) { bufv[pos] = d; bufj[pos] = j; }
            }
            total += __popc(mk);
        }
    } else {
        for (int t = 0; t < 32; t++) {
            int c = lane + t*32;
            float4 v = pr[c];
            float vals[4] = {v.x, v.y, v.z, v.w};
            #pragma unroll
            for (int e = 0; e < 4; e++) {
                bool keep = (vals[e] >= tau);
                unsigned mk = __ballot_sync(0xffffffffu, keep);
                if (keep) {
                    int pos = total + __popc(mk & lmask);
                    if (pos < KCAP) { bufv[pos] = vals[e]; bufj[pos] = c*4 + e; }
                }
                total += __popc(mk);
            }
        }
    }

    int* orow = g_idx + row*KNB;

    if (total <= KCAP) {
        int nq = (total + 31) >> 5;
        for (int r = 0; r < KNB; r++) {
            float bv = NEGINF; int bj = 0x7fffffff; int bs = -1;
            for (int q = 0; q < nq; q++) {
                int idx = lane + (q << 5);
                if (idx < total) {
                    float v = bufv[idx]; int j = bufj[idx];
                    if (v > bv || (v == bv && j < bj)) { bv = v; bj = j; bs = idx; }
                }
            }
            float lv0 = bv; int lj0 = bj;
            #pragma unroll
            for (int off = 16; off; off >>= 1) {
                float ov = __shfl_xor_sync(0xffffffffu, bv, off);
                int   oj = __shfl_xor_sync(0xffffffffu, bj, off);
                if (ov > bv || (ov == bv && oj < bj)) { bv = ov; bj = oj; }
            }
            if (lj0 == bj && lv0 == bv && bs >= 0) bufv[bs] = NEGINF;
            if (lane == 0) orow[r] = bj + (b << 12);
        }
    } else {
        float lv[KNB]; int li[KNB];
        #pragma unroll
        for (int q = 0; q < KNB; q++) { lv[q] = NEGINF; li[q] = 0x7fffffff; }
        if (!PD) {
            for (int t = 0; t < 128; t++) {
                int j = lane + t*32;
                float4 pj = stash[j];
                float val = fmaf(xi2, pj.x, fmaf(yi2, pj.y, fmaf(zi2, pj.z, ci - pj.w)));
                if (val > lv[KNB-1]) {
                    #pragma unroll
                    for (int p = KNB-1; p > 0; --p) {
                        bool below = (lv[p] >= val);
                        bool shift = (lv[p-1] < val);
                        float nl = below ? lv[p] : (shift ? lv[p-1] : val);
                        int   ni = below ? li[p] : (shift ? li[p-1] : j);
                        lv[p] = nl; li[p] = ni;
                    }
                    if (lv[0] < val) { lv[0] = val; li[0] = j; }
                }
            }
        } else {
            for (int t = 0; t < 32; t++) {
                int c = lane + t*32;
                float4 v = pr[c];
                float vals[4] = {v.x, v.y, v.z, v.w};
                #pragma unroll
                for (int e = 0; e < 4; e++) {
                    float val = vals[e]; int j = c*4 + e;
                    if (val > lv[KNB-1]) {
                        #pragma unroll
                        for (int p = KNB-1; p > 0; --p) {
                            bool below = (lv[p] >= val);
                            bool shift = (lv[p-1] < val);
                            float nl = below ? lv[p] : (shift ? lv[p-1] : val);
                            int   ni = below ? li[p] : (shift ? li[p-1] : j);
                            lv[p] = nl; li[p] = ni;
                        }
                        if (lv[0] < val) { lv[0] = val; li[0] = j; }
                    }
                }
            }
        }
        for (int r = 0; r < KNB; r++) {
            float bv = lv[0]; int bj = li[0];
            float lv0 = bv; int lj0 = bj;
            #pragma unroll
            for (int off = 16; off; off >>= 1) {
                float ov = __shfl_xor_sync(0xffffffffu, bv, off);
                int   oj = __shfl_xor_sync(0xffffffffu, bj, off);
                if (ov > bv || (ov == bv && oj < bj)) { bv = ov; bj = oj; }
            }
            if (lj0 == bj && lv0 == bv) {
                #pragma unroll
                for (int p = 0; p < KNB-1; p++) { lv[p] = lv[p+1]; li[p] = li[p+1]; }
                lv[KNB-1] = NEGINF; li[KNB-1] = 0x7fffffff;
            }
            if (lane == 0) orow[r] = bj + (b << 12);
        }
    }
}

// ------------------------- edge-conv prep -------------------------
template<int C>
__global__ void k_prep_ab(const float* __restrict__ src, int ld,
                          const float* __restrict__ W, const float* __restrict__ bias) {
    __shared__ float Ws[2*C*64];
    for (int e = threadIdx.x; e < 2*C*64; e += blockDim.x) Ws[e] = W[e];
    __syncthreads();
    int t = blockIdx.x*blockDim.x + threadIdx.x;
    int d = t & 63, n = t >> 6;
    if (n >= NPTS) return;
    const float* xr = src + (size_t)n*ld;
    float a = bias[d], bb = 0.f;
    #pragma unroll
    for (int c = 0; c < C; c++) {
        float xv = xr[c];
        float wt = Ws[c*64+d], wb = Ws[(C+c)*64+d];
        a  += xv*(wt - wb);
        bb += xv*wb;
    }
    g_aA[(size_t)n*64+d] = a;
    g_aB[(size_t)n*64+d] = bb;
}

// e3: out[n,d] = max_k relu(a[n,d] + bnb[idx[n,k],d])
__global__ void k_edge_e3(float* __restrict__ out, int ldo) {
    int t = blockIdx.x*blockDim.x + threadIdx.x;
    int d = t & 63, n = t >> 6;
    if (n >= NPTS) return;
    float a = g_aA[(size_t)n*64+d];
    const int* ir = g_idx + n*KNB;
    float m = 0.f;
    #pragma unroll
    for (int k = 0; k < KNB; k++) m = fmaxf(m, a + g_aB[(size_t)ir[k]*64 + d]);
    out[(size_t)n*ldo + d] = m;
}

// ------------------------- TF32 tensor-core GEMM -------------------------
__device__ __forceinline__ float to_tf32(float x) {
    uint32_t u;
    asm("cvt.rna.tf32.f32 %0, %1;" : "=r"(u) : "f"(x));
    return __uint_as_float(u);
}

__device__ __forceinline__ void mma_tf32(float* c, const uint32_t* a, const uint32_t* b) {
    asm volatile(
        "mma.sync.aligned.m16n8k8.row.col.f32.tf32.tf32.f32 "
        "{%0,%1,%2,%3}, {%4,%5,%6,%7}, {%8,%9}, {%0,%1,%2,%3};\n"
        : "+f"(c[0]), "+f"(c[1]), "+f"(c[2]), "+f"(c[3])
        : "r"(a[0]), "r"(a[1]), "r"(a[2]), "r"(a[3]), "r"(b[0]), "r"(b[1]));
}

#define SM_BUF   4608
#define SM_MMA3  (4*SM_BUF*4)
#define SM_MMA1  (2*SM_BUF*4)

// Block tile 128x128, 8 warps (2M x 4N), warp tile 64x32, k-stage 32.
// Register-prefetch double buffering.
// SPLIT=3: 3xTF32 (~fp32); SPLIT=1: single-pass tf32.
// MINB: min blocks/SM for launch_bounds (2 for SPLIT=1 kernels -> 2 CTA/SM occupancy;
//       1 for SPLIT=3 whose register demand would spill at 128).
// GATHER: A rows are edge rows relu(g_aA[n] + g_aB[g_idx[row]]) (K=64).
// EPI: 0 = bias(+rowadd)+ReLU store; 1 = bias+ReLU+per-batch col max (atomicMax);
//      2 = SYMMETRIC pairwise: triangular grid, mirrored tile via smem transpose;
//      3 = gather edge: bias+ReLU, per-point (row/20) atomicMax into out (stride Nd).
template<int EPI, int SPLIT, bool GATHER, int MINB>
__global__ void __launch_bounds__(256, MINB) k_mma(const float* __restrict__ A, int lda,
                                             const float* __restrict__ B, int ldb,
                                             const float* __restrict__ bias,
                                             const float* __restrict__ rowadd,
                                             float* __restrict__ out,
                                             int Kd, int Nd) {
    extern __shared__ float dynsm[];
    float* Ab = dynsm;
    float* Al = dynsm + SM_BUF;                          // SPLIT==3 only
    float* Bb = dynsm + (SPLIT == 3 ? 2 : 1)*SM_BUF;
    float* Bl = dynsm + 3*SM_BUF;                        // SPLIT==3 only
    int m0, n0;
    bool diag = false;
    if (EPI == 2) {
        int tb = blockIdx.x;
        int by = (int)((sqrtf(8.f*tb + 1.f) - 1.f)*0.5f);
        while ((by + 1)*(by + 2)/2 <= tb) by++;
        while (by*(by + 1)/2 > tb) by--;
        int bx = tb - by*(by + 1)/2;
        m0 = by*128; n0 = bx*128;
        diag = (bx == by);
    } else {
        m0 = blockIdx.y*128; n0 = blockIdx.x*128;
    }
    int tid = threadIdx.x;
    int w = tid >> 5, lane = tid & 31;
    int wm = w & 1, wn = w >> 1;
    int g = lane >> 2, t = lane & 3;
    size_t rowbase = (EPI == 2) ? (size_t)blockIdx.z*NPT : 0;

    int a_r  = tid >> 3, a_c4 = (tid & 7)*4;
    int bw_r = tid >> 5, bw_c4 = (tid & 31)*4;

    float4 pA[4], pB[4];

    auto loadA = [&](int kk) {
        #pragma unroll
        for (int i = 0; i < 4; i++) {
            int r = a_r + i*32;
            if (GATHER) {
                unsigned gr = m0 + r;
                unsigned n = gr / 20u;
                int j = g_idx[gr];
                float4 va = *(const float4*)(g_aA + (size_t)n*64 + kk + a_c4);
                float4 vb = *(const float4*)(g_aB + (size_t)j*64 + kk + a_c4);
                pA[i].x = fmaxf(va.x + vb.x, 0.f);
                pA[i].y = fmaxf(va.y + vb.y, 0.f);
                pA[i].z = fmaxf(va.z + vb.z, 0.f);
                pA[i].w = fmaxf(va.w + vb.w, 0.f);
            } else {
                pA[i] = *(const float4*)(A + (rowbase + m0 + r)*lda + kk + a_c4);
            }
        }
    };
    auto loadB = [&](int kk) {
        #pragma unroll
        for (int i = 0; i < 4; i++) {
            if (EPI == 2) {
                int r = a_r + i*32;
                pB[i] = *(const float4*)(B + (rowbase + n0 + r)*ldb + kk + a_c4);
            } else {
                int r = bw_r + i*8;
                pB[i] = *(const float4*)(B + (size_t)(kk + r)*ldb + n0 + bw_c4);
            }
        }
    };

    float acc[4][4][4];
    #pragma unroll
    for (int mt = 0; mt < 4; mt++)
        #pragma unroll
        for (int nt = 0; nt < 4; nt++)
            #pragma unroll
            for (int r = 0; r < 4; r++) acc[mt][nt][r] = 0.f;

    loadA(0);
    loadB(0);

    for (int kk = 0; kk < Kd; kk += 32) {
        // stage prefetched A
        #pragma unroll
        for (int i = 0; i < 4; i++) {
            int r = a_r + i*32;
            float4 v = pA[i];
            float bx = to_tf32(v.x), by = to_tf32(v.y), bz = to_tf32(v.z), bw = to_tf32(v.w);
            float* db = &Ab[r*36 + a_c4];
            db[0] = bx; db[1] = by; db[2] = bz; db[3] = bw;
            if (SPLIT == 3) {
                float* dl = &Al[r*36 + a_c4];
                dl[0] = to_tf32(v.x - bx); dl[1] = to_tf32(v.y - by);
                dl[2] = to_tf32(v.z - bz); dl[3] = to_tf32(v.w - bw);
            }
        }
        // stage prefetched B
        #pragma unroll
        for (int i = 0; i < 4; i++) {
            float4 v = pB[i];
            float bx = to_tf32(v.x), by = to_tf32(v.y), bz = to_tf32(v.z), bw = to_tf32(v.w);
            if (EPI == 2) {
                int r = a_r + i*32;
                float* db = &Bb[r*36 + a_c4];
                db[0] = bx; db[1] = by; db[2] = bz; db[3] = bw;
                if (SPLIT == 3) {
                    float* dl = &Bl[r*36 + a_c4];
                    dl[0] = to_tf32(v.x - bx); dl[1] = to_tf32(v.y - by);
                    dl[2] = to_tf32(v.z - bz); dl[3] = to_tf32(v.w - bw);
                }
            } else {
                int r = bw_r + i*8;
                float* db = &Bb[r*136 + bw_c4];
                db[0] = bx; db[1] = by; db[2] = bz; db[3] = bw;
                if (SPLIT == 3) {
                    float* dl = &Bl[r*136 + bw_c4];
                    dl[0] = to_tf32(v.x - bx); dl[1] = to_tf32(v.y - by);
                    dl[2] = to_tf32(v.z - bz); dl[3] = to_tf32(v.w - bw);
                }
            }
        }
        __syncthreads();
        // prefetch next tile (overlaps with MMA below)
        if (kk + 32 < Kd) { loadA(kk + 32); loadB(kk + 32); }

        #pragma unroll
        for (int k8 = 0; k8 < 4; k8++) {
            uint32_t afb[4][4], afl[4][4];
            #pragma unroll
            for (int mt = 0; mt < 4; mt++) {
                int off = (wm*64 + mt*16 + g)*36 + k8*8 + t;
                afb[mt][0] = __float_as_uint(Ab[off]);
                afb[mt][1] = __float_as_uint(Ab[off + 8*36]);
                afb[mt][2] = __float_as_uint(Ab[off + 4]);
                afb[mt][3] = __float_as_uint(Ab[off + 8*36 + 4]);
                if (SPLIT == 3) {
                    afl[mt][0] = __float_as_uint(Al[off]);
                    afl[mt][1] = __float_as_uint(Al[off + 8*36]);
                    afl[mt][2] = __float_as_uint(Al[off + 4]);
                    afl[mt][3] = __float_as_uint(Al[off + 8*36 + 4]);
                }
            }
            uint32_t bfb[4][2], bfl[4][2];
            #pragma unroll
            for (int nt = 0; nt < 4; nt++) {
                if (EPI == 2) {
                    int off = (wn*32 + nt*8 + g)*36 + k8*8 + t;
                    bfb[nt][0] = __float_as_uint(Bb[off]);
                    bfb[nt][1] = __float_as_uint(Bb[off + 4]);
                    if (SPLIT == 3) {
                        bfl[nt][0] = __float_as_uint(Bl[off]);
                        bfl[nt][1] = __float_as_uint(Bl[off + 4]);
                    }
                } else {
                    int off = (k8*8 + t)*136 + wn*32 + nt*8 + g;
                    bfb[nt][0] = __float_as_uint(Bb[off]);
                    bfb[nt][1] = __float_as_uint(Bb[off + 4*136]);
                    if (SPLIT == 3) {
                        bfl[nt][0] = __float_as_uint(Bl[off]);
                        bfl[nt][1] = __float_as_uint(Bl[off + 4*136]);
                    }
                }
            }
            #pragma unroll
            for (int mt = 0; mt < 4; mt++)
                #pragma unroll
                for (int nt = 0; nt < 4; nt++) {
                    if (SPLIT == 3) {
                        mma_tf32(acc[mt][nt], afb[mt], bfl[nt]);
                        mma_tf32(acc[mt][nt], afl[mt], bfb[nt]);
                    }
                    mma_tf32(acc[mt][nt], afb[mt], bfb[nt]);
                }
        }
        __syncthreads();
    }

    if (EPI == 2) {
        int b = blockIdx.z;
        float* tile = dynsm;   // reuse: 128 x 132 transpose stage
        #pragma unroll
        for (int mt = 0; mt < 4; mt++) {
            int mA = wm*64 + mt*16 + g;
            int mB = mA + 8;
            float sqm  = g_sq[(size_t)b*NPT + m0 + mA];
            float sqm8 = g_sq[(size_t)b*NPT + m0 + mB];
            float* r0 = g_pd + ((size_t)b*NPT + m0 + mA)*NPT;
            float* r1 = g_pd + ((size_t)b*NPT + m0 + mB)*NPT;
            #pragma unroll
            for (int nt = 0; nt < 4; nt++) {
                int nl = wn*32 + nt*8 + t*2;
                float sqn  = g_sq[(size_t)b*NPT + n0 + nl];
                float sqn1 = g_sq[(size_t)b*NPT + n0 + nl + 1];
                float d00 = 2.f*acc[mt][nt][0] - sqm  - sqn;
                float d01 = 2.f*acc[mt][nt][1] - sqm  - sqn1;
                float d10 = 2.f*acc[mt][nt][2] - sqm8 - sqn;
                float d11 = 2.f*acc[mt][nt][3] - sqm8 - sqn1;
                *(float2*)(r0 + n0 + nl) = make_float2(d00, d01);
                *(float2*)(r1 + n0 + nl) = make_float2(d10, d11);
                if (!diag) {
                    tile[(nl  )*132 + mA] = d00;
                    tile[(nl+1)*132 + mA] = d01;
                    tile[(nl  )*132 + mB] = d10;
                    tile[(nl+1)*132 + mB] = d11;
                }
            }
        }
        if (!diag) {
            __syncthreads();
            #pragma unroll
            for (int i = 0; i < 16; i++) {
                int idx = tid + i*256;
                int r = idx >> 5, c4 = (idx & 31)*4;
                float4 v = *(float4*)&tile[r*132 + c4];
                *(float4*)(g_pd + ((size_t)b*NPT + n0 + r)*NPT + m0 + c4) = v;
            }
        }
    } else if (EPI == 0) {
        int b = m0 >> 12;
        #pragma unroll
        for (int mt = 0; mt < 4; mt++) {
            int m = m0 + wm*64 + mt*16 + g;
            #pragma unroll
            for (int nt = 0; nt < 4; nt++) {
                int n = n0 + wn*32 + nt*8 + t*2;
                float add0 = 0.f, add1 = 0.f;
                if (bias)   { add0 += bias[n]; add1 += bias[n+1]; }
                if (rowadd) { add0 += rowadd[b*Nd + n]; add1 += rowadd[b*Nd + n + 1]; }
                float2 v0, v1;
                v0.x = fmaxf(acc[mt][nt][0] + add0, 0.f);
                v0.y = fmaxf(acc[mt][nt][1] + add1, 0.f);
                v1.x = fmaxf(acc[mt][nt][2] + add0, 0.f);
                v1.y = fmaxf(acc[mt][nt][3] + add1, 0.f);
                *(float2*)(out + (size_t)m*Nd + n) = v0;
                *(float2*)(out + (size_t)(m+8)*Nd + n) = v1;
            }
        }
    } else if (EPI == 1) {
        int b = m0 >> 12;
        #pragma unroll
        for (int nt = 0; nt < 4; nt++) {
            int n = n0 + wn*32 + nt*8 + t*2;
            float m0v = NEGINF, m1v = NEGINF;
            #pragma unroll
            for (int mt = 0; mt < 4; mt++) {
                m0v = fmaxf(m0v, fmaxf(acc[mt][nt][0], acc[mt][nt][2]));
                m1v = fmaxf(m1v, fmaxf(acc[mt][nt][1], acc[mt][nt][3]));
            }
            m0v = fmaxf(m0v + bias[n], 0.f);
            m1v = fmaxf(m1v + bias[n+1], 0.f);
            #pragma unroll
            for (int off = 4; off < 32; off <<= 1) {
                m0v = fmaxf(m0v, __shfl_xor_sync(0xffffffffu, m0v, off));
                m1v = fmaxf(m1v, __shfl_xor_sync(0xffffffffu, m1v, off));
            }
            if (g == 0) {
                atomicMax((int*)out + (size_t)b*Nd + n,     __float_as_int(m0v));
                atomicMax((int*)out + (size_t)b*Nd + n + 1, __float_as_int(m1v));
            }
        }
    } else {
        // EPI == 3: gather-edge fused k-max. out stride = Nd, point = row/20.
        #pragma unroll
        for (int mt = 0; mt < 4; mt++) {
            int m = m0 + wm*64 + mt*16 + g;
            unsigned p0 = (unsigned)m / 20u;
            unsigned p1 = (unsigned)(m + 8) / 20u;
            #pragma unroll
            for (int nt = 0; nt < 4; nt++) {
                int n = n0 + wn*32 + nt*8 + t*2;
                float b0 = bias[n], b1 = bias[n+1];
                float v00 = fmaxf(acc[mt][nt][0] + b0, 0.f);
                float v01 = fmaxf(acc[mt][nt][1] + b1, 0.f);
                float v10 = fmaxf(acc[mt][nt][2] + b0, 0.f);
                float v11 = fmaxf(acc[mt][nt][3] + b1, 0.f);
                if (p0 == p1) {
                    atomicMax((int*)out + (size_t)p0*Nd + n,     __float_as_int(fmaxf(v00, v10)));
                    atomicMax((int*)out + (size_t)p0*Nd + n + 1, __float_as_int(fmaxf(v01, v11)));
                } else {
                    atomicMax((int*)out + (size_t)p0*Nd + n,     __float_as_int(v00));
                    atomicMax((int*)out + (size_t)p0*Nd + n + 1, __float_as_int(v01));
                    atomicMax((int*)out + (size_t)p1*Nd + n,     __float_as_int(v10));
                    atomicMax((int*)out + (size_t)p1*Nd + n + 1, __float_as_int(v11));
                }
            }
        }
    }
}

// ------------- edge GEMM, N=64 tile (gathered A, 3xTF32, fused k-max) -------------
#define SM_E64 ((2*4608 + 2*2304)*4)
__global__ void __launch_bounds__(256, 2) k_mma_e64(const float* __restrict__ W,
                                                 const float* __restrict__ bias,
                                                 float* __restrict__ out, int ldo) {
    extern __shared__ float dynsm[];
    float* Ab = dynsm;                 // [128][36]
    float* Al = dynsm + 4608;
    float* Bb = dynsm + 2*4608;        // [32][72]
    float* Bl = dynsm + 2*4608 + 2304;
    int m0 = blockIdx.y*128;
    int tid = threadIdx.x;
    int w = tid >> 5, lane = tid & 31;
    int wm = w & 3, wn = w >> 2;
    int g = lane >> 2, t = lane & 3;

    int a_r  = tid >> 3, a_c4 = (tid & 7)*4;
    int bw_r = tid >> 4, bw_c4 = (tid & 15)*4;

    float4 pA[4], pB[2];

    auto loadA = [&](int kk) {
        #pragma unroll
        for (int i = 0; i < 4; i++) {
            int r = a_r + i*32;
            unsigned gr = m0 + r;
            unsigned n = gr / 20u;
            int j = g_idx[gr];
            float4 va = *(const float4*)(g_aA + (size_t)n*64 + kk + a_c4);
            float4 vb = *(const float4*)(g_aB + (size_t)j*64 + kk + a_c4);
            pA[i].x = fmaxf(va.x + vb.x, 0.f);
            pA[i].y = fmaxf(va.y + vb.y, 0.f);
            pA[i].z = fmaxf(va.z + vb.z, 0.f);
            pA[i].w = fmaxf(va.w + vb.w, 0.f);
        }
    };
    auto loadB = [&](int kk) {
        #pragma unroll
        for (int i = 0; i < 2; i++) {
            int r = bw_r + i*16;
            pB[i] = *(const float4*)(W + (size_t)(kk + r)*64 + bw_c4);
        }
    };

    float acc[2][4][4];
    #pragma unroll
    for (int mt = 0; mt < 2; mt++)
        #pragma unroll
        for (int nt = 0; nt < 4; nt++)
            #pragma unroll
            for (int r = 0; r < 4; r++) acc[mt][nt][r] = 0.f;

    loadA(0);
    loadB(0);

    for (int kk = 0; kk < 64; kk += 32) {
        #pragma unroll
        for (int i = 0; i < 4; i++) {
            int r = a_r + i*32;
            float4 v = pA[i];
            float bx = to_tf32(v.x), by = to_tf32(v.y), bz = to_tf32(v.z), bw = to_tf32(v.w);
            float* db = &Ab[r*36 + a_c4];
            float* dl = &Al[r*36 + a_c4];
            db[0] = bx; db[1] = by; db[2] = bz; db[3] = bw;
            dl[0] = to_tf32(v.x - bx); dl[1] = to_tf32(v.y - by);
            dl[2] = to_tf32(v.z - bz); dl[3] = to_tf32(v.w - bw);
        }
        #pragma unroll
        for (int i = 0; i < 2; i++) {
            int r = bw_r + i*16;
            float4 v = pB[i];
            float bx = to_tf32(v.x), by = to_tf32(v.y), bz = to_tf32(v.z), bw = to_tf32(v.w);
            float* db = &Bb[r*72 + bw_c4];
            float* dl = &Bl[r*72 + bw_c4];
            db[0] = bx; db[1] = by; db[2] = bz; db[3] = bw;
            dl[0] = to_tf32(v.x - bx); dl[1] = to_tf32(v.y - by);
            dl[2] = to_tf32(v.z - bz); dl[3] = to_tf32(v.w - bw);
        }
        __syncthreads();
        if (kk + 32 < 64) { loadA(kk + 32); loadB(kk + 32); }

        #pragma unroll
        for (int k8 = 0; k8 < 4; k8++) {
            uint32_t afb[2][4], afl[2][4];
            #pragma unroll
            for (int mt = 0; mt < 2; mt++) {
                int off = (wm*32 + mt*16 + g)*36 + k8*8 + t;
                afb[mt][0] = __float_as_uint(Ab[off]);
                afb[mt][1] = __float_as_uint(Ab[off + 8*36]);
                afb[mt][2] = __float_as_uint(Ab[off + 4]);
                afb[mt][3] = __float_as_uint(Ab[off + 8*36 + 4]);
                afl[mt][0] = __float_as_uint(Al[off]);
                afl[mt][1] = __float_as_uint(Al[off + 8*36]);
                afl[mt][2] = __float_as_uint(Al[off + 4]);
                afl[mt][3] = __float_as_uint(Al[off + 8*36 + 4]);
            }
            uint32_t bfb[4][2], bfl[4][2];
            #pragma unroll
            for (int nt = 0; nt < 4; nt++) {
                int off = (k8*8 + t)*72 + wn*32 + nt*8 + g;
                bfb[nt][0] = __float_as_uint(Bb[off]);
                bfb[nt][1] = __float_as_uint(Bb[off + 4*72]);
                bfl[nt][0] = __float_as_uint(Bl[off]);
                bfl[nt][1] = __float_as_uint(Bl[off + 4*72]);
            }
            #pragma unroll
            for (int mt = 0; mt < 2; mt++)
                #pragma unroll
                for (int nt = 0; nt < 4; nt++) {
                    mma_tf32(acc[mt][nt], afb[mt], bfl[nt]);
                    mma_tf32(acc[mt][nt], afl[mt], bfb[nt]);
                    mma_tf32(acc[mt][nt], afb[mt], bfb[nt]);
                }
        }
        __syncthreads();
    }

    #pragma unroll
    for (int mt = 0; mt < 2; mt++) {
        int m = m0 + wm*32 + mt*16 + g;
        unsigned p0 = (unsigned)m / 20u;
        unsigned p1 = (unsigned)(m + 8) / 20u;
        #pragma unroll
        for (int nt = 0; nt < 4; nt++) {
            int c = wn*32 + nt*8 + t*2;
            float b0 = bias[c], b1 = bias[c+1];
            float v00 = fmaxf(acc[mt][nt][0] + b0, 0.f);
            float v01 = fmaxf(acc[mt][nt][1] + b1, 0.f);
            float v10 = fmaxf(acc[mt][nt][2] + b0, 0.f);
            float v11 = fmaxf(acc[mt][nt][3] + b1, 0.f);
            if (p0 == p1) {
                atomicMax((int*)out + (size_t)p0*ldo + c,     __float_as_int(fmaxf(v00, v10)));
                atomicMax((int*)out + (size_t)p0*ldo + c + 1, __float_as_int(fmaxf(v01, v11)));
            } else {
                atomicMax((int*)out + (size_t)p0*ldo + c,     __float_as_int(v00));
                atomicMax((int*)out + (size_t)p0*ldo + c + 1, __float_as_int(v01));
                atomicMax((int*)out + (size_t)p1*ldo + c,     __float_as_int(v10));
                atomicMax((int*)out + (size_t)p1*ldo + c + 1, __float_as_int(v11));
            }
        }
    }
}

// ------------------------- small FC (M=4) -------------------------
__global__ void k_fc(const float* __restrict__ A, const float* __restrict__ W, int ldw,
                     const float* __restrict__ bias, float* __restrict__ out,
                     int Kd, int Nd, int relu) {
    int t = blockIdx.x*blockDim.x + threadIdx.x;
    if (t >= BBATCH*Nd) return;
    int b = t / Nd, d = t - b*Nd;
    const float* ar = A + (size_t)b*Kd;
    float s0 = 0.f, s1 = 0.f, s2 = 0.f, s3 = 0.f;
    for (int c = 0; c < Kd; c += 4) {
        s0 += ar[c+0]*W[(size_t)(c+0)*ldw + d];
        s1 += ar[c+1]*W[(size_t)(c+1)*ldw + d];
        s2 += ar[c+2]*W[(size_t)(c+2)*ldw + d];
        s3 += ar[c+3]*W[(size_t)(c+3)*ldw + d];
    }
    float acc = bias[d] + (s0+s1) + (s2+s3);
    if (relu) acc = fmaxf(acc, 0.f);
    out[(size_t)b*Nd + d] = acc;
}

// ------------------------- final 256->2 -------------------------
__global__ void k_c4(const float* __restrict__ W, const float* __restrict__ bias,
                     float* __restrict__ out) {
    int gt = blockIdx.x*blockDim.x + threadIdx.x;
    int w = gt >> 5, lane = gt & 31;
    if (w >= NPTS) return;
    const float* a = g_c3 + (size_t)w*256;
    float s0 = 0.f, s1 = 0.f;
    #pragma unroll
    for (int t = 0; t < 8; t++) {
        int c = lane + 32*t;
        float v = a[c];
        s0 += v*W[c*2+0];
        s1 += v*W[c*2+1];
    }
    #pragma unroll
    for (int off = 16; off; off >>= 1) {
        s0 += __shfl_down_sync(0xffffffffu, s0, off);
        s1 += __shfl_down_sync(0xffffffffu, s1, off);
    }
    if (lane == 0) { out[w*2+0] = s0 + bias[0]; out[w*2+1] = s1 + bias[1]; }
}

// ------------------------- host orchestration -------------------------
static float* symaddr(const void* sym) {
    void* p = nullptr;
    cudaGetSymbolAddress(&p, sym);
    return (float*)p;
}

extern "C" void kernel_launch(void* const* d_in, const int* in_sizes, int n_in,
                              void* d_out, int out_size) {
    const float* x    = (const float*)d_in[0];
    const float* tw1  = (const float*)d_in[1];
    const float* tb1  = (const float*)d_in[2];
    const float* tw2  = (const float*)d_in[3];
    const float* tb2  = (const float*)d_in[4];
    const float* tw3  = (const float*)d_in[5];
    const float* tb3  = (const float*)d_in[6];
    const float* tfw1 = (const float*)d_in[7];
    const float* tfb1 = (const float*)d_in[8];
    const float* tfw2 = (const float*)d_in[9];
    const float* tfb2 = (const float*)d_in[10];
    const float* txw  = (const float*)d_in[11];
    const float* txb  = (const float*)d_in[12];
    const float* e1w1 = (const float*)d_in[13];
    const float* e1b1 = (const float*)d_in[14];
    const float* e1w2 = (const float*)d_in[15];
    const float* e1b2 = (const float*)d_in[16];
    const float* e2w1 = (const float*)d_in[17];
    const float* e2b1 = (const float*)d_in[18];
    const float* e2w2 = (const float*)d_in[19];
    const float* e2b2 = (const float*)d_in[20];
    const float* e3w1 = (const float*)d_in[21];
    const float* e3b1 = (const float*)d_in[22];
    const float* c1w  = (const float*)d_in[23];
    const float* c1b  = (const float*)d_in[24];
    const float* c2w  = (const float*)d_in[25];
    const float* c2b  = (const float*)d_in[26];
    const float* c3w  = (const float*)d_in[27];
    const float* c3b  = (const float*)d_in[28];
    const float* c4w  = (const float*)d_in[29];
    const float* c4b  = (const float*)d_in[30];
    float* out = (float*)d_out;

    float4* p_pts4  = (float4*)symaddr(g_pts4);
    float4* p_p4    = (float4*)symaddr(g_p4);
    float*  p_t     = symaddr(g_t);
    float*  p_cat   = symaddr(g_cat192);
    float*  p_c2    = symaddr(g_c2);
    float*  p_c3    = symaddr(g_c3);
    float*  p_tvec  = symaddr(g_tvec);
    float*  p_gvec  = symaddr(g_gvec);
    float*  p_fc1   = symaddr(g_fc1);
    float*  p_fc2   = symaddr(g_fc2);
    float*  p_xf    = symaddr(g_xf);
    float*  p_gterm = symaddr(g_gterm);

    const int SM3D = NPT*16 + KNN_WPB*KCAP*8;   // 98304
    const int SMPD = KNN_WPB*KCAP*8;            // 32768
    cudaFuncSetAttribute(k_knn<false>, cudaFuncAttributeMaxDynamicSharedMemorySize, SM3D);
    cudaFuncSetAttribute(k_knn<true>,  cudaFuncAttributeMaxDynamicSharedMemorySize, SMPD);
    cudaFuncSetAttribute((const void*)k_mma<3,1,true,2>,  cudaFuncAttributeMaxDynamicSharedMemorySize, SM_MMA1);
    cudaFuncSetAttribute((const void*)k_mma<2,3,false,1>, cudaFuncAttributeMaxDynamicSharedMemorySize, SM_MMA3);
    cudaFuncSetAttribute((const void*)k_mma_e64,          cudaFuncAttributeMaxDynamicSharedMemorySize, SM_E64);

    const int NTRI = (NPT/128)*((NPT/128) + 1)/2;   // 528 triangle blocks
    dim3 pwgrid(NTRI, 1, BBATCH);
    const int EDGE_GY = NPTS*KNB/128;   // 2560

    // ---- knn(pts) + tnet (tnet GEMMs 1xTF32: output only enters via near-identity xf) ----
    k_pts_sq<<<NPTS/256, 256>>>(x);
    k_knn<false><<<NPTS/KNN_WPB, 512, SM3D>>>(p_pts4);
    k_prep_ab<3><<<NPTS*64/256, 256>>>((const float*)p_pts4, 4, tw1, tb1);
    cudaMemsetAsync(p_t,    0, (size_t)NPTS*128*sizeof(float));
    cudaMemsetAsync(p_tvec, 0, (size_t)BBATCH*1024*sizeof(float));
    cudaMemsetAsync(p_gvec, 0, (size_t)BBATCH*1024*sizeof(float));
    k_mma<3,1,true,2><<<dim3(1, EDGE_GY), 256, SM_MMA1>>>(nullptr, 0, tw2, 128, tb2, nullptr, p_t, 64, 128);
    k_mma<1,1,false,2><<<dim3(1024/128, NPTS/128), 256, SM_MMA1>>>(p_t, 128, tw3, 1024, tb3, nullptr, p_tvec, 128, 1024);
    k_fc<<<(BBATCH*512 + 127)/128, 128>>>(p_tvec, tfw1, 512, tfb1, p_fc1, 1024, 512, 1);
    k_fc<<<(BBATCH*256 + 127)/128, 128>>>(p_fc1, tfw2, 256, tfb2, p_fc2, 512, 256, 1);
    k_fc<<<1, 128>>>(p_fc2, txw, 9, txb, p_xf, 256, 9, 0);
    k_transform<<<NPTS/256, 256>>>();

    // ---- knn(p) + e1 -> x1 ----
    k_knn<false><<<NPTS/KNN_WPB, 512, SM3D>>>(p_p4);
    k_prep_ab<3><<<NPTS*64/256, 256>>>((const float*)p_p4, 4, e1w1, e1b1);
    cudaMemsetAsync(p_cat, 0, (size_t)NPTS*192*sizeof(float));
    k_mma_e64<<<dim3(1, EDGE_GY), 256, SM_E64>>>(e1w2, e1b2, p_cat + 0, 192);

    // ---- knn(x1) + e2 -> x2 ----
    k_sq64<<<NPTS*32/256, 256>>>(p_cat + 0, 192);
    k_mma<2,3,false,1><<<pwgrid, 256, SM_MMA3>>>(p_cat + 0, 192, p_cat + 0, 192, nullptr, nullptr, nullptr, 64, NPT);
    k_knn<true><<<NPTS/KNN_WPB, 512, SMPD>>>(nullptr);
    k_prep_ab<64><<<NPTS*64/256, 256>>>(p_cat + 0, 192, e2w1, e2b1);
    k_mma_e64<<<dim3(1, EDGE_GY), 256, SM_E64>>>(e2w2, e2b2, p_cat + 64, 192);

    // ---- knn(x2) + e3 -> x3 ----
    k_sq64<<<NPTS*32/256, 256>>>(p_cat + 64, 192);
    k_mma<2,3,false,1><<<pwgrid, 256, SM_MMA3>>>(p_cat + 64, 192, p_cat + 64, 192, nullptr, nullptr, nullptr, 64, NPT);
    k_knn<true><<<NPTS/KNN_WPB, 512, SMPD>>>(nullptr);
    k_prep_ab<64><<<NPTS*64/256, 256>>>(p_cat + 64, 192, e3w1, e3b1);
    k_edge_e3<<<NPTS*64/256, 256>>>(p_cat + 128, 192);

    // ---- classifier (no knn downstream -> 1xTF32, 2 CTAs/SM) ----
    k_mma<1,1,false,2><<<dim3(1024/128, NPTS/128), 256, SM_MMA1>>>(p_cat, 192, c1w, 1024, c1b, nullptr, p_gvec, 192, 1024);
    k_fc<<<(BBATCH*512 + 127)/128, 128>>>(p_gvec, c2w, 512, c2b, p_gterm, 1024, 512, 0);
    k_mma<0,1,false,2><<<dim3(512/128, NPTS/128), 256, SM_MMA1>>>(p_cat, 192, c2w + (size_t)1024*512, 512, nullptr, p_gterm, p_c2, 192, 512);
    k_mma<0,1,false,2><<<dim3(256/128, NPTS/128), 256, SM_MMA1>>>(p_c2, 512, c3w, 256, c3b, nullptr, p_c3, 512, 256);
    k_c4<<<NPTS*32/256, 256>>>(c4w, c4b, out);
}

// round 16
// speedup vs baseline: 1.1474x; 1.0322x over previous
#include <cuda_runtime.h>
#include <cstdint>
#include <cstddef>

#define NPT    4096
#define BBATCH 4
#define NPTS   (BBATCH*NPT)
#define KNB    20
#define NEGINF (-3.4e38f)
#define KCAP   256
#define KNN_WPB 16

// ------------------------- device scratch -------------------------
__device__ float  g_pd[(size_t)BBATCH*NPT*NPT];   // pairwise (64-dim KNNs)
__device__ int    g_idx[NPTS*KNB];
__device__ float4 g_pts4[NPTS];
__device__ float4 g_p4[NPTS];
__device__ float  g_sq[NPTS];
__device__ float  g_aA[NPTS*64];
__device__ float  g_aB[NPTS*64];
__device__ float  g_t[(size_t)NPTS*128];
__device__ float  g_cat192[(size_t)NPTS*192];     // x1|x2|x3
__device__ float  g_c2[(size_t)NPTS*512];
__device__ float  g_c3[(size_t)NPTS*256];
__device__ float  g_tvec[BBATCH*1024];
__device__ float  g_gvec[BBATCH*1024];
__device__ float  g_fc1[BBATCH*512];
__device__ float  g_fc2[BBATCH*256];
__device__ float  g_xf[BBATCH*9];
__device__ float  g_gterm[BBATCH*512];

// ------------------------- small kernels -------------------------
__global__ void k_pts_sq(const float* __restrict__ x) {
    int i = blockIdx.x*blockDim.x + threadIdx.x;
    if (i >= NPTS) return;
    float a = x[i*6+0], b = x[i*6+1], c = x[i*6+2];
    g_pts4[i] = make_float4(a, b, c, a*a + b*b + c*c);
}

__global__ void k_transform() {
    int n = blockIdx.x*blockDim.x + threadIdx.x;
    if (n >= NPTS) return;
    int b = n >> 12;
    float4 q = g_pts4[n];
    const float* f = g_xf + b*9;
    float p0 = q.x*f[0] + q.y*f[3] + q.z*f[6];
    float p1 = q.x*f[1] + q.y*f[4] + q.z*f[7];
    float p2 = q.x*f[2] + q.y*f[5] + q.z*f[8];
    g_p4[n] = make_float4(p0, p1, p2, p0*p0 + p1*p1 + p2*p2);
}

__global__ void k_sq64(const float* __restrict__ src, int ld) {
    int gt = blockIdx.x*blockDim.x + threadIdx.x;
    int w = gt >> 5, lane = gt & 31;
    if (w >= NPTS) return;
    const float* r = src + (size_t)w*ld;
    float s = r[lane]*r[lane] + r[lane+32]*r[lane+32];
    #pragma unroll
    for (int off = 16; off; off >>= 1) s += __shfl_down_sync(0xffffffffu, s, off);
    if (lane == 0) g_sq[w] = s;
}

// ------------------------- fast exact KNN (K=20) -------------------------
template<bool PD>
__global__ void __launch_bounds__(512) k_knn(const float4* __restrict__ P4) {
    extern __shared__ float dyn[];
    int w = threadIdx.x >> 5, lane = threadIdx.x & 31;
    int row = blockIdx.x*KNN_WPB + w;
    int b = row >> 12, i = row & (NPT-1);

    float4* stash = (float4*)dyn;
    float*  bufv;
    int*    bufj;
    if (PD) { bufv = dyn + w*2*KCAP; }
    else    { bufv = dyn + NPT*4 + w*2*KCAP; }
    bufj = (int*)(bufv + KCAP);

    float xi2 = 0.f, yi2 = 0.f, zi2 = 0.f, ci = 0.f;
    const float4* pr = nullptr;
    if (!PD) {
        const float4* src = P4 + (size_t)b*NPT;
        for (int t = threadIdx.x; t < NPT; t += 512) stash[t] = src[t];
        __syncthreads();
        float4 pi = stash[i];
        xi2 = 2.f*pi.x; yi2 = 2.f*pi.y; zi2 = 2.f*pi.z; ci = -pi.w;
    } else {
        pr = (const float4*)(g_pd + (size_t)row*NPT);
    }

    float mx = NEGINF;
    if (!PD) {
        for (int t = 0; t < 128; t++) {
            float4 pj = stash[lane + t*32];
            float d = fmaf(xi2, pj.x, fmaf(yi2, pj.y, fmaf(zi2, pj.z, ci - pj.w)));
            mx = fmaxf(mx, d);
        }
    } else {
        for (int t = 0; t < 32; t++) {
            float4 v = pr[lane + t*32];
            mx = fmaxf(mx, fmaxf(fmaxf(v.x, v.y), fmaxf(v.z, v.w)));
        }
    }

    float tau = NEGINF;
    float tv = mx;
    #pragma unroll
    for (int r = 0; r < 20; r++) {
        float bv = tv;
        #pragma unroll
        for (int off = 16; off; off >>= 1)
            bv = fmaxf(bv, __shfl_xor_sync(0xffffffffu, bv, off));
        unsigned m = __ballot_sync(0xffffffffu, tv == bv);
        if (lane == (__ffs(m) - 1)) tv = NEGINF;
        tau = bv;
    }

    unsigned lmask = (1u << lane) - 1u;
    int total = 0;
    if (!PD) {
        for (int t = 0; t < 128; t++) {
            int j = lane + t*32;
            float4 pj = stash[j];
            float d = fmaf(xi2, pj.x, fmaf(yi2, pj.y, fmaf(zi2, pj.z, ci - pj.w)));
            bool keep = (d >= tau);
            unsigned mk = __ballot_sync(0xffffffffu, keep);
            if (keep) {
                int pos = total + __popc(mk & lmask);
                if (pos < KCAP) { bufv[pos] = d; bufj[pos] = j; }
            }
            total += __popc(mk);
        }
    } else {
        for (int t = 0; t < 32; t++) {
            int c = lane + t*32;
            float4 v = pr[c];
            float vals[4] = {v.x, v.y, v.z, v.w};
            #pragma unroll
            for (int e = 0; e < 4; e++) {
                bool keep = (vals[e] >= tau);
                unsigned mk = __ballot_sync(0xffffffffu, keep);
                if (keep) {
                    int pos = total + __popc(mk & lmask);
                    if (pos < KCAP) { bufv[pos] = vals[e]; bufj[pos] = c*4 + e; }
                }
                total += __popc(mk);
            }
        }
    }

    int* orow = g_idx + row*KNB;

    if (total <= KCAP) {
        int nq = (total + 31) >> 5;
        for (int r = 0; r < KNB; r++) {
            float bv = NEGINF; int bj = 0x7fffffff; int bs = -1;
            for (int q = 0; q < nq; q++) {
                int idx = lane + (q << 5);
                if (idx < total) {
                    float v = bufv[idx]; int j = bufj[idx];
                    if (v > bv || (v == bv && j < bj)) { bv = v; bj = j; bs = idx; }
                }
            }
            float lv0 = bv; int lj0 = bj;
            #pragma unroll
            for (int off = 16; off; off >>= 1) {
                float ov = __shfl_xor_sync(0xffffffffu, bv, off);
                int   oj = __shfl_xor_sync(0xffffffffu, bj, off);
                if (ov > bv || (ov == bv && oj < bj)) { bv = ov; bj = oj; }
            }
            if (lj0 == bj && lv0 == bv && bs >= 0) bufv[bs] = NEGINF;
            if (lane == 0) orow[r] = bj + (b << 12);
        }
    } else {
        float lv[KNB]; int li[KNB];
        #pragma unroll
        for (int q = 0; q < KNB; q++) { lv[q] = NEGINF; li[q] = 0x7fffffff; }
        if (!PD) {
            for (int t = 0; t < 128; t++) {
                int j = lane + t*32;
                float4 pj = stash[j];
                float val = fmaf(xi2, pj.x, fmaf(yi2, pj.y, fmaf(zi2, pj.z, ci - pj.w)));
                if (val > lv[KNB-1]) {
                    #pragma unroll
                    for (int p = KNB-1; p > 0; --p) {
                        bool below = (lv[p] >= val);
                        bool shift = (lv[p-1] < val);
                        float nl = below ? lv[p] : (shift ? lv[p-1] : val);
                        int   ni = below ? li[p] : (shift ? li[p-1] : j);
                        lv[p] = nl; li[p] = ni;
                    }
                    if (lv[0] < val) { lv[0] = val; li[0] = j; }
                }
            }
        } else {
            for (int t = 0; t < 32; t++) {
                int c = lane + t*32;
                float4 v = pr[c];
                float vals[4] = {v.x, v.y, v.z, v.w};
                #pragma unroll
                for (int e = 0; e < 4; e++) {
                    float val = vals[e]; int j = c*4 + e;
                    if (val > lv[KNB-1]) {
                        #pragma unroll
                        for (int p = KNB-1; p > 0; --p) {
                            bool below = (lv[p] >= val);
                            bool shift = (lv[p-1] < val);
                            float nl = below ? lv[p] : (shift ? lv[p-1] : val);
                            int   ni = below ? li[p] : (shift ? li[p-1] : j);
                            lv[p] = nl; li[p] = ni;
                        }
                        if (lv[0] < val) { lv[0] = val; li[0] = j; }
                    }
                }
            }
        }
        for (int r = 0; r < KNB; r++) {
            float bv = lv[0]; int bj = li[0];
            float lv0 = bv; int lj0 = bj;
            #pragma unroll
            for (int off = 16; off; off >>= 1) {
                float ov = __shfl_xor_sync(0xffffffffu, bv, off);
                int   oj = __shfl_xor_sync(0xffffffffu, bj, off);
                if (ov > bv || (ov == bv && oj < bj)) { bv = ov; bj = oj; }
            }
            if (lj0 == bj && lv0 == bv) {
                #pragma unroll
                for (int p = 0; p < KNB-1; p++) { lv[p] = lv[p+1]; li[p] = li[p+1]; }
                lv[KNB-1] = NEGINF; li[KNB-1] = 0x7fffffff;
            }
            if (lane == 0) orow[r] = bj + (b << 12);
        }
    }
}

// ------------------------- edge-conv prep -------------------------
template<int C>
__global__ void k_prep_ab(const float* __restrict__ src, int ld,
                          const float* __restrict__ W, const float* __restrict__ bias) {
    __shared__ float Ws[2*C*64];
    for (int e = threadIdx.x; e < 2*C*64; e += blockDim.x) Ws[e] = W[e];
    __syncthreads();
    int t = blockIdx.x*blockDim.x + threadIdx.x;
    int d = t & 63, n = t >> 6;
    if (n >= NPTS) return;
    const float* xr = src + (size_t)n*ld;
    float a = bias[d], bb = 0.f;
    #pragma unroll
    for (int c = 0; c < C; c++) {
        float xv = xr[c];
        float wt = Ws[c*64+d], wb = Ws[(C+c)*64+d];
        a  += xv*(wt - wb);
        bb += xv*wb;
    }
    g_aA[(size_t)n*64+d] = a;
    g_aB[(size_t)n*64+d] = bb;
}

// e3: out[n,d] = max_k relu(a[n,d] + bnb[idx[n,k],d])
__global__ void k_edge_e3(float* __restrict__ out, int ldo) {
    int t = blockIdx.x*blockDim.x + threadIdx.x;
    int d = t & 63, n = t >> 6;
    if (n >= NPTS) return;
    float a = g_aA[(size_t)n*64+d];
    const int* ir = g_idx + n*KNB;
    float m = 0.f;
    #pragma unroll
    for (int k = 0; k < KNB; k++) m = fmaxf(m, a + g_aB[(size_t)ir[k]*64 + d]);
    out[(size_t)n*ldo + d] = m;
}

// ------------------------- TF32 tensor-core GEMM -------------------------
__device__ __forceinline__ float to_tf32(float x) {
    uint32_t u;
    asm("cvt.rna.tf32.f32 %0, %1;" : "=r"(u) : "f"(x));
    return __uint_as_float(u);
}

__device__ __forceinline__ void mma_tf32(float* c, const uint32_t* a, const uint32_t* b) {
    asm volatile(
        "mma.sync.aligned.m16n8k8.row.col.f32.tf32.tf32.f32 "
        "{%0,%1,%2,%3}, {%4,%5,%6,%7}, {%8,%9}, {%0,%1,%2,%3};\n"
        : "+f"(c[0]), "+f"(c[1]), "+f"(c[2]), "+f"(c[3])
        : "r"(a[0]), "r"(a[1]), "r"(a[2]), "r"(a[3]), "r"(b[0]), "r"(b[1]));
}

#define SM_BUF   4608
#define SM_MMA3  (4*SM_BUF*4)
#define SM_MMA1  (2*SM_BUF*4)

// Block tile 128x128, 8 warps (2M x 4N), warp tile 64x32, k-stage 32.
// PREF: register-prefetch double buffering (costs ~32 regs). For SPLIT=3 pairwise
//       we disable it and set MINB=2: 2 CTAs/SM beats one-tile prefetch at Kd=64
//       (R15 measured 2-CTA occupancy worth ~27% on the gather kernel).
// SPLIT=3: 3xTF32 (~fp32); SPLIT=1: single-pass tf32.
// MINB: min blocks/SM for launch_bounds.
// GATHER: A rows are edge rows relu(g_aA[n] + g_aB[g_idx[row]]) (K=64).
// EPI: 0 = bias(+rowadd)+ReLU store; 1 = bias+ReLU+per-batch col max (atomicMax);
//      2 = SYMMETRIC pairwise: triangular grid, mirrored tile via smem transpose;
//      3 = gather edge: bias+ReLU, per-point (row/20) atomicMax into out (stride Nd).
template<int EPI, int SPLIT, bool GATHER, int MINB, bool PREF>
__global__ void __launch_bounds__(256, MINB) k_mma(const float* __restrict__ A, int lda,
                                             const float* __restrict__ B, int ldb,
                                             const float* __restrict__ bias,
                                             const float* __restrict__ rowadd,
                                             float* __restrict__ out,
                                             int Kd, int Nd) {
    extern __shared__ float dynsm[];
    float* Ab = dynsm;
    float* Al = dynsm + SM_BUF;                          // SPLIT==3 only
    float* Bb = dynsm + (SPLIT == 3 ? 2 : 1)*SM_BUF;
    float* Bl = dynsm + 3*SM_BUF;                        // SPLIT==3 only
    int m0, n0;
    bool diag = false;
    if (EPI == 2) {
        int tb = blockIdx.x;
        int by = (int)((sqrtf(8.f*tb + 1.f) - 1.f)*0.5f);
        while ((by + 1)*(by + 2)/2 <= tb) by++;
        while (by*(by + 1)/2 > tb) by--;
        int bx = tb - by*(by + 1)/2;
        m0 = by*128; n0 = bx*128;
        diag = (bx == by);
    } else {
        m0 = blockIdx.y*128; n0 = blockIdx.x*128;
    }
    int tid = threadIdx.x;
    int w = tid >> 5, lane = tid & 31;
    int wm = w & 1, wn = w >> 1;
    int g = lane >> 2, t = lane & 3;
    size_t rowbase = (EPI == 2) ? (size_t)blockIdx.z*NPT : 0;

    int a_r  = tid >> 3, a_c4 = (tid & 7)*4;
    int bw_r = tid >> 5, bw_c4 = (tid & 31)*4;

    float4 pA[4], pB[4];

    auto loadA = [&](int kk) {
        #pragma unroll
        for (int i = 0; i < 4; i++) {
            int r = a_r + i*32;
            if (GATHER) {
                unsigned gr = m0 + r;
                unsigned n = gr / 20u;
                int j = g_idx[gr];
                float4 va = *(const float4*)(g_aA + (size_t)n*64 + kk + a_c4);
                float4 vb = *(const float4*)(g_aB + (size_t)j*64 + kk + a_c4);
                pA[i].x = fmaxf(va.x + vb.x, 0.f);
                pA[i].y = fmaxf(va.y + vb.y, 0.f);
                pA[i].z = fmaxf(va.z + vb.z, 0.f);
                pA[i].w = fmaxf(va.w + vb.w, 0.f);
            } else {
                pA[i] = *(const float4*)(A + (rowbase + m0 + r)*lda + kk + a_c4);
            }
        }
    };
    auto loadB = [&](int kk) {
        #pragma unroll
        for (int i = 0; i < 4; i++) {
            if (EPI == 2) {
                int r = a_r + i*32;
                pB[i] = *(const float4*)(B + (rowbase + n0 + r)*ldb + kk + a_c4);
            } else {
                int r = bw_r + i*8;
                pB[i] = *(const float4*)(B + (size_t)(kk + r)*ldb + n0 + bw_c4);
            }
        }
    };

    float acc[4][4][4];
    #pragma unroll
    for (int mt = 0; mt < 4; mt++)
        #pragma unroll
        for (int nt = 0; nt < 4; nt++)
            #pragma unroll
            for (int r = 0; r < 4; r++) acc[mt][nt][r] = 0.f;

    if (PREF) { loadA(0); loadB(0); }

    for (int kk = 0; kk < Kd; kk += 32) {
        if (!PREF) { loadA(kk); loadB(kk); }
        // stage A
        #pragma unroll
        for (int i = 0; i < 4; i++) {
            int r = a_r + i*32;
            float4 v = pA[i];
            float bx = to_tf32(v.x), by = to_tf32(v.y), bz = to_tf32(v.z), bw = to_tf32(v.w);
            float* db = &Ab[r*36 + a_c4];
            db[0] = bx; db[1] = by; db[2] = bz; db[3] = bw;
            if (SPLIT == 3) {
                float* dl = &Al[r*36 + a_c4];
                dl[0] = to_tf32(v.x - bx); dl[1] = to_tf32(v.y - by);
                dl[2] = to_tf32(v.z - bz); dl[3] = to_tf32(v.w - bw);
            }
        }
        // stage B
        #pragma unroll
        for (int i = 0; i < 4; i++) {
            float4 v = pB[i];
            float bx = to_tf32(v.x), by = to_tf32(v.y), bz = to_tf32(v.z), bw = to_tf32(v.w);
            if (EPI == 2) {
                int r = a_r + i*32;
                float* db = &Bb[r*36 + a_c4];
                db[0] = bx; db[1] = by; db[2] = bz; db[3] = bw;
                if (SPLIT == 3) {
                    float* dl = &Bl[r*36 + a_c4];
                    dl[0] = to_tf32(v.x - bx); dl[1] = to_tf32(v.y - by);
                    dl[2] = to_tf32(v.z - bz); dl[3] = to_tf32(v.w - bw);
                }
            } else {
                int r = bw_r + i*8;
                float* db = &Bb[r*136 + bw_c4];
                db[0] = bx; db[1] = by; db[2] = bz; db[3] = bw;
                if (SPLIT == 3) {
                    float* dl = &Bl[r*136 + bw_c4];
                    dl[0] = to_tf32(v.x - bx); dl[1] = to_tf32(v.y - by);
                    dl[2] = to_tf32(v.z - bz); dl[3] = to_tf32(v.w - bw);
                }
            }
        }
        __syncthreads();
        // prefetch next tile (overlaps with MMA below)
        if (PREF && kk + 32 < Kd) { loadA(kk + 32); loadB(kk + 32); }

        #pragma unroll
        for (int k8 = 0; k8 < 4; k8++) {
            uint32_t afb[4][4], afl[4][4];
            #pragma unroll
            for (int mt = 0; mt < 4; mt++) {
                int off = (wm*64 + mt*16 + g)*36 + k8*8 + t;
                afb[mt][0] = __float_as_uint(Ab[off]);
                afb[mt][1] = __float_as_uint(Ab[off + 8*36]);
                afb[mt][2] = __float_as_uint(Ab[off + 4]);
                afb[mt][3] = __float_as_uint(Ab[off + 8*36 + 4]);
                if (SPLIT == 3) {
                    afl[mt][0] = __float_as_uint(Al[off]);
                    afl[mt][1] = __float_as_uint(Al[off + 8*36]);
                    afl[mt][2] = __float_as_uint(Al[off + 4]);
                    afl[mt][3] = __float_as_uint(Al[off + 8*36 + 4]);
                }
            }
            uint32_t bfb[4][2], bfl[4][2];
            #pragma unroll
            for (int nt = 0; nt < 4; nt++) {
                if (EPI == 2) {
                    int off = (wn*32 + nt*8 + g)*36 + k8*8 + t;
                    bfb[nt][0] = __float_as_uint(Bb[off]);
                    bfb[nt][1] = __float_as_uint(Bb[off + 4]);
                    if (SPLIT == 3) {
                        bfl[nt][0] = __float_as_uint(Bl[off]);
                        bfl[nt][1] = __float_as_uint(Bl[off + 4]);
                    }
                } else {
                    int off = (k8*8 + t)*136 + wn*32 + nt*8 + g;
                    bfb[nt][0] = __float_as_uint(Bb[off]);
                    bfb[nt][1] = __float_as_uint(Bb[off + 4*136]);
                    if (SPLIT == 3) {
                        bfl[nt][0] = __float_as_uint(Bl[off]);
                        bfl[nt][1] = __float_as_uint(Bl[off + 4*136]);
                    }
                }
            }
            #pragma unroll
            for (int mt = 0; mt < 4; mt++)
                #pragma unroll
                for (int nt = 0; nt < 4; nt++) {
                    if (SPLIT == 3) {
                        mma_tf32(acc[mt][nt], afb[mt], bfl[nt]);
                        mma_tf32(acc[mt][nt], afl[mt], bfb[nt]);
                    }
                    mma_tf32(acc[mt][nt], afb[mt], bfb[nt]);
                }
        }
        __syncthreads();
    }

    if (EPI == 2) {
        int b = blockIdx.z;
        float* tile = dynsm;   // reuse: 128 x 132 transpose stage
        #pragma unroll
        for (int mt = 0; mt < 4; mt++) {
            int mA = wm*64 + mt*16 + g;
            int mB = mA + 8;
            float sqm  = g_sq[(size_t)b*NPT + m0 + mA];
            float sqm8 = g_sq[(size_t)b*NPT + m0 + mB];
            float* r0 = g_pd + ((size_t)b*NPT + m0 + mA)*NPT;
            float* r1 = g_pd + ((size_t)b*NPT + m0 + mB)*NPT;
            #pragma unroll
            for (int nt = 0; nt < 4; nt++) {
                int nl = wn*32 + nt*8 + t*2;
                float sqn  = g_sq[(size_t)b*NPT + n0 + nl];
                float sqn1 = g_sq[(size_t)b*NPT + n0 + nl + 1];
                float d00 = 2.f*acc[mt][nt][0] - sqm  - sqn;
                float d01 = 2.f*acc[mt][nt][1] - sqm  - sqn1;
                float d10 = 2.f*acc[mt][nt][2] - sqm8 - sqn;
                float d11 = 2.f*acc[mt][nt][3] - sqm8 - sqn1;
                *(float2*)(r0 + n0 + nl) = make_float2(d00, d01);
                *(float2*)(r1 + n0 + nl) = make_float2(d10, d11);
                if (!diag) {
                    tile[(nl  )*132 + mA] = d00;
                    tile[(nl+1)*132 + mA] = d01;
                    tile[(nl  )*132 + mB] = d10;
                    tile[(nl+1)*132 + mB] = d11;
                }
            }
        }
        if (!diag) {
            __syncthreads();
            #pragma unroll
            for (int i = 0; i < 16; i++) {
                int idx = tid + i*256;
                int r = idx >> 5, c4 = (idx & 31)*4;
                float4 v = *(float4*)&tile[r*132 + c4];
                *(float4*)(g_pd + ((size_t)b*NPT + n0 + r)*NPT + m0 + c4) = v;
            }
        }
    } else if (EPI == 0) {
        int b = m0 >> 12;
        #pragma unroll
        for (int mt = 0; mt < 4; mt++) {
            int m = m0 + wm*64 + mt*16 + g;
            #pragma unroll
            for (int nt = 0; nt < 4; nt++) {
                int n = n0 + wn*32 + nt*8 + t*2;
                float add0 = 0.f, add1 = 0.f;
                if (bias)   { add0 += bias[n]; add1 += bias[n+1]; }
                if (rowadd) { add0 += rowadd[b*Nd + n]; add1 += rowadd[b*Nd + n + 1]; }
                float2 v0, v1;
                v0.x = fmaxf(acc[mt][nt][0] + add0, 0.f);
                v0.y = fmaxf(acc[mt][nt][1] + add1, 0.f);
                v1.x = fmaxf(acc[mt][nt][2] + add0, 0.f);
                v1.y = fmaxf(acc[mt][nt][3] + add1, 0.f);
                *(float2*)(out + (size_t)m*Nd + n) = v0;
                *(float2*)(out + (size_t)(m+8)*Nd + n) = v1;
            }
        }
    } else if (EPI == 1) {
        int b = m0 >> 12;
        #pragma unroll
        for (int nt = 0; nt < 4; nt++) {
            int n = n0 + wn*32 + nt*8 + t*2;
            float m0v = NEGINF, m1v = NEGINF;
            #pragma unroll
            for (int mt = 0; mt < 4; mt++) {
                m0v = fmaxf(m0v, fmaxf(acc[mt][nt][0], acc[mt][nt][2]));
                m1v = fmaxf(m1v, fmaxf(acc[mt][nt][1], acc[mt][nt][3]));
            }
            m0v = fmaxf(m0v + bias[n], 0.f);
            m1v = fmaxf(m1v + bias[n+1], 0.f);
            #pragma unroll
            for (int off = 4; off < 32; off <<= 1) {
                m0v = fmaxf(m0v, __shfl_xor_sync(0xffffffffu, m0v, off));
                m1v = fmaxf(m1v, __shfl_xor_sync(0xffffffffu, m1v, off));
            }
            if (g == 0) {
                atomicMax((int*)out + (size_t)b*Nd + n,     __float_as_int(m0v));
                atomicMax((int*)out + (size_t)b*Nd + n + 1, __float_as_int(m1v));
            }
        }
    } else {
        // EPI == 3: gather-edge fused k-max. out stride = Nd, point = row/20.
        #pragma unroll
        for (int mt = 0; mt < 4; mt++) {
            int m = m0 + wm*64 + mt*16 + g;
            unsigned p0 = (unsigned)m / 20u;
            unsigned p1 = (unsigned)(m + 8) / 20u;
            #pragma unroll
            for (int nt = 0; nt < 4; nt++) {
                int n = n0 + wn*32 + nt*8 + t*2;
                float b0 = bias[n], b1 = bias[n+1];
                float v00 = fmaxf(acc[mt][nt][0] + b0, 0.f);
                float v01 = fmaxf(acc[mt][nt][1] + b1, 0.f);
                float v10 = fmaxf(acc[mt][nt][2] + b0, 0.f);
                float v11 = fmaxf(acc[mt][nt][3] + b1, 0.f);
                if (p0 == p1) {
                    atomicMax((int*)out + (size_t)p0*Nd + n,     __float_as_int(fmaxf(v00, v10)));
                    atomicMax((int*)out + (size_t)p0*Nd + n + 1, __float_as_int(fmaxf(v01, v11)));
                } else {
                    atomicMax((int*)out + (size_t)p0*Nd + n,     __float_as_int(v00));
                    atomicMax((int*)out + (size_t)p0*Nd + n + 1, __float_as_int(v01));
                    atomicMax((int*)out + (size_t)p1*Nd + n,     __float_as_int(v10));
                    atomicMax((int*)out + (size_t)p1*Nd + n + 1, __float_as_int(v11));
                }
            }
        }
    }
}

// ------------- edge GEMM, N=64 tile (gathered A, 3xTF32, fused k-max) -------------
#define SM_E64 ((2*4608 + 2*2304)*4)
__global__ void __launch_bounds__(256, 2) k_mma_e64(const float* __restrict__ W,
                                                 const float* __restrict__ bias,
                                                 float* __restrict__ out, int ldo) {
    extern __shared__ float dynsm[];
    float* Ab = dynsm;                 // [128][36]
    float* Al = dynsm + 4608;
    float* Bb = dynsm + 2*4608;        // [32][72]
    float* Bl = dynsm + 2*4608 + 2304;
    int m0 = blockIdx.y*128;
    int tid = threadIdx.x;
    int w = tid >> 5, lane = tid & 31;
    int wm = w & 3, wn = w >> 2;
    int g = lane >> 2, t = lane & 3;

    int a_r  = tid >> 3, a_c4 = (tid & 7)*4;
    int bw_r = tid >> 4, bw_c4 = (tid & 15)*4;

    float4 pA[4], pB[2];

    auto loadA = [&](int kk) {
        #pragma unroll
        for (int i = 0; i < 4; i++) {
            int r = a_r + i*32;
            unsigned gr = m0 + r;
            unsigned n = gr / 20u;
            int j = g_idx[gr];
            float4 va = *(const float4*)(g_aA + (size_t)n*64 + kk + a_c4);
            float4 vb = *(const float4*)(g_aB + (size_t)j*64 + kk + a_c4);
            pA[i].x = fmaxf(va.x + vb.x, 0.f);
            pA[i].y = fmaxf(va.y + vb.y, 0.f);
            pA[i].z = fmaxf(va.z + vb.z, 0.f);
            pA[i].w = fmaxf(va.w + vb.w, 0.f);
        }
    };
    auto loadB = [&](int kk) {
        #pragma unroll
        for (int i = 0; i < 2; i++) {
            int r = bw_r + i*16;
            pB[i] = *(const float4*)(W + (size_t)(kk + r)*64 + bw_c4);
        }
    };

    float acc[2][4][4];
    #pragma unroll
    for (int mt = 0; mt < 2; mt++)
        #pragma unroll
        for (int nt = 0; nt < 4; nt++)
            #pragma unroll
            for (int r = 0; r < 4; r++) acc[mt][nt][r] = 0.f;

    loadA(0);
    loadB(0);

    for (int kk = 0; kk < 64; kk += 32) {
        #pragma unroll
        for (int i = 0; i < 4; i++) {
            int r = a_r + i*32;
            float4 v = pA[i];
            float bx = to_tf32(v.x), by = to_tf32(v.y), bz = to_tf32(v.z), bw = to_tf32(v.w);
            float* db = &Ab[r*36 + a_c4];
            float* dl = &Al[r*36 + a_c4];
            db[0] = bx; db[1] = by; db[2] = bz; db[3] = bw;
            dl[0] = to_tf32(v.x - bx); dl[1] = to_tf32(v.y - by);
            dl[2] = to_tf32(v.z - bz); dl[3] = to_tf32(v.w - bw);
        }
        #pragma unroll
        for (int i = 0; i < 2; i++) {
            int r = bw_r + i*16;
            float4 v = pB[i];
            float bx = to_tf32(v.x), by = to_tf32(v.y), bz = to_tf32(v.z), bw = to_tf32(v.w);
            float* db = &Bb[r*72 + bw_c4];
            float* dl = &Bl[r*72 + bw_c4];
            db[0] = bx; db[1] = by; db[2] = bz; db[3] = bw;
            dl[0] = to_tf32(v.x - bx); dl[1] = to_tf32(v.y - by);
            dl[2] = to_tf32(v.z - bz); dl[3] = to_tf32(v.w - bw);
        }
        __syncthreads();
        if (kk + 32 < 64) { loadA(kk + 32); loadB(kk + 32); }

        #pragma unroll
        for (int k8 = 0; k8 < 4; k8++) {
            uint32_t afb[2][4], afl[2][4];
            #pragma unroll
            for (int mt = 0; mt < 2; mt++) {
                int off = (wm*32 + mt*16 + g)*36 + k8*8 + t;
                afb[mt][0] = __float_as_uint(Ab[off]);
                afb[mt][1] = __float_as_uint(Ab[off + 8*36]);
                afb[mt][2] = __float_as_uint(Ab[off + 4]);
                afb[mt][3] = __float_as_uint(Ab[off + 8*36 + 4]);
                afl[mt][0] = __float_as_uint(Al[off]);
                afl[mt][1] = __float_as_uint(Al[off + 8*36]);
                afl[mt][2] = __float_as_uint(Al[off + 4]);
                afl[mt][3] = __float_as_uint(Al[off + 8*36 + 4]);
            }
            uint32_t bfb[4][2], bfl[4][2];
            #pragma unroll
            for (int nt = 0; nt < 4; nt++) {
                int off = (k8*8 + t)*72 + wn*32 + nt*8 + g;
                bfb[nt][0] = __float_as_uint(Bb[off]);
                bfb[nt][1] = __float_as_uint(Bb[off + 4*72]);
                bfl[nt][0] = __float_as_uint(Bl[off]);
                bfl[nt][1] = __float_as_uint(Bl[off + 4*72]);
            }
            #pragma unroll
            for (int mt = 0; mt < 2; mt++)
                #pragma unroll
                for (int nt = 0; nt < 4; nt++) {
                    mma_tf32(acc[mt][nt], afb[mt], bfl[nt]);
                    mma_tf32(acc[mt][nt], afl[mt], bfb[nt]);
                    mma_tf32(acc[mt][nt], afb[mt], bfb[nt]);
                }
        }
        __syncthreads();
    }

    #pragma unroll
    for (int mt = 0; mt < 2; mt++) {
        int m = m0 + wm*32 + mt*16 + g;
        unsigned p0 = (unsigned)m / 20u;
        unsigned p1 = (unsigned)(m + 8) / 20u;
        #pragma unroll
        for (int nt = 0; nt < 4; nt++) {
            int c = wn*32 + nt*8 + t*2;
            float b0 = bias[c], b1 = bias[c+1];
            float v00 = fmaxf(acc[mt][nt][0] + b0, 0.f);
            float v01 = fmaxf(acc[mt][nt][1] + b1, 0.f);
            float v10 = fmaxf(acc[mt][nt][2] + b0, 0.f);
            float v11 = fmaxf(acc[mt][nt][3] + b1, 0.f);
            if (p0 == p1) {
                atomicMax((int*)out + (size_t)p0*ldo + c,     __float_as_int(fmaxf(v00, v10)));
                atomicMax((int*)out + (size_t)p0*ldo + c + 1, __float_as_int(fmaxf(v01, v11)));
            } else {
                atomicMax((int*)out + (size_t)p0*ldo + c,     __float_as_int(v00));
                atomicMax((int*)out + (size_t)p0*ldo + c + 1, __float_as_int(v01));
                atomicMax((int*)out + (size_t)p1*ldo + c,     __float_as_int(v10));
                atomicMax((int*)out + (size_t)p1*ldo + c + 1, __float_as_int(v11));
            }
        }
    }
}

// ------------------------- small FC (M=4) -------------------------
__global__ void k_fc(const float* __restrict__ A, const float* __restrict__ W, int ldw,
                     const float* __restrict__ bias, float* __restrict__ out,
                     int Kd, int Nd, int relu) {
    int t = blockIdx.x*blockDim.x + threadIdx.x;
    if (t >= BBATCH*Nd) return;
    int b = t / Nd, d = t - b*Nd;
    const float* ar = A + (size_t)b*Kd;
    float s0 = 0.f, s1 = 0.f, s2 = 0.f, s3 = 0.f;
    for (int c = 0; c < Kd; c += 4) {
        s0 += ar[c+0]*W[(size_t)(c+0)*ldw + d];
        s1 += ar[c+1]*W[(size_t)(c+1)*ldw + d];
        s2 += ar[c+2]*W[(size_t)(c+2)*ldw + d];
        s3 += ar[c+3]*W[(size_t)(c+3)*ldw + d];
    }
    float acc = bias[d] + (s0+s1) + (s2+s3);
    if (relu) acc = fmaxf(acc, 0.f);
    out[(size_t)b*Nd + d] = acc;
}

// ------------------------- final 256->2 -------------------------
__global__ void k_c4(const float* __restrict__ W, const float* __restrict__ bias,
                     float* __restrict__ out) {
    int gt = blockIdx.x*blockDim.x + threadIdx.x;
    int w = gt >> 5, lane = gt & 31;
    if (w >= NPTS) return;
    const float* a = g_c3 + (size_t)w*256;
    float s0 = 0.f, s1 = 0.f;
    #pragma unroll
    for (int t = 0; t < 8; t++) {
        int c = lane + 32*t;
        float v = a[c];
        s0 += v*W[c*2+0];
        s1 += v*W[c*2+1];
    }
    #pragma unroll
    for (int off = 16; off; off >>= 1) {
        s0 += __shfl_down_sync(0xffffffffu, s0, off);
        s1 += __shfl_down_sync(0xffffffffu, s1, off);
    }
    if (lane == 0) { out[w*2+0] = s0 + bias[0]; out[w*2+1] = s1 + bias[1]; }
}

// ------------------------- host orchestration -------------------------
static float* symaddr(const void* sym) {
    void* p = nullptr;
    cudaGetSymbolAddress(&p, sym);
    return (float*)p;
}

extern "C" void kernel_launch(void* const* d_in, const int* in_sizes, int n_in,
                              void* d_out, int out_size) {
    const float* x    = (const float*)d_in[0];
    const float* tw1  = (const float*)d_in[1];
    const float* tb1  = (const float*)d_in[2];
    const float* tw2  = (const float*)d_in[3];
    const float* tb2  = (const float*)d_in[4];
    const float* tw3  = (const float*)d_in[5];
    const float* tb3  = (const float*)d_in[6];
    const float* tfw1 = (const float*)d_in[7];
    const float* tfb1 = (const float*)d_in[8];
    const float* tfw2 = (const float*)d_in[9];
    const float* tfb2 = (const float*)d_in[10];
    const float* txw  = (const float*)d_in[11];
    const float* txb  = (const float*)d_in[12];
    const float* e1w1 = (const float*)d_in[13];
    const float* e1b1 = (const float*)d_in[14];
    const float* e1w2 = (const float*)d_in[15];
    const float* e1b2 = (const float*)d_in[16];
    const float* e2w1 = (const float*)d_in[17];
    const float* e2b1 = (const float*)d_in[18];
    const float* e2w2 = (const float*)d_in[19];
    const float* e2b2 = (const float*)d_in[20];
    const float* e3w1 = (const float*)d_in[21];
    const float* e3b1 = (const float*)d_in[22];
    const float* c1w  = (const float*)d_in[23];
    const float* c1b  = (const float*)d_in[24];
    const float* c2w  = (const float*)d_in[25];
    const float* c2b  = (const float*)d_in[26];
    const float* c3w  = (const float*)d_in[27];
    const float* c3b  = (const float*)d_in[28];
    const float* c4w  = (const float*)d_in[29];
    const float* c4b  = (const float*)d_in[30];
    float* out = (float*)d_out;

    float4* p_pts4  = (float4*)symaddr(g_pts4);
    float4* p_p4    = (float4*)symaddr(g_p4);
    float*  p_t     = symaddr(g_t);
    float*  p_cat   = symaddr(g_cat192);
    float*  p_c2    = symaddr(g_c2);
    float*  p_c3    = symaddr(g_c3);
    float*  p_tvec  = symaddr(g_tvec);
    float*  p_gvec  = symaddr(g_gvec);
    float*  p_fc1   = symaddr(g_fc1);
    float*  p_fc2   = symaddr(g_fc2);
    float*  p_xf    = symaddr(g_xf);
    float*  p_gterm = symaddr(g_gterm);

    const int SM3D = NPT*16 + KNN_WPB*KCAP*8;   // 98304
    const int SMPD = KNN_WPB*KCAP*8;            // 32768
    cudaFuncSetAttribute(k_knn<false>, cudaFuncAttributeMaxDynamicSharedMemorySize, SM3D);
    cudaFuncSetAttribute(k_knn<true>,  cudaFuncAttributeMaxDynamicSharedMemorySize, SMPD);
    cudaFuncSetAttribute((const void*)k_mma<3,1,true,2,true>,   cudaFuncAttributeMaxDynamicSharedMemorySize, SM_MMA1);
    cudaFuncSetAttribute((const void*)k_mma<2,3,false,2,false>, cudaFuncAttributeMaxDynamicSharedMemorySize, SM_MMA3);
    cudaFuncSetAttribute((const void*)k_mma_e64,                cudaFuncAttributeMaxDynamicSharedMemorySize, SM_E64);

    const int NTRI = (NPT/128)*((NPT/128) + 1)/2;   // 528 triangle blocks
    dim3 pwgrid(NTRI, 1, BBATCH);
    const int EDGE_GY = NPTS*KNB/128;   // 2560

    // ---- knn(pts) + tnet (tnet GEMMs 1xTF32: output only enters via near-identity xf) ----
    k_pts_sq<<<NPTS/256, 256>>>(x);
    k_knn<false><<<NPTS/KNN_WPB, 512, SM3D>>>(p_pts4);
    k_prep_ab<3><<<NPTS*64/256, 256>>>((const float*)p_pts4, 4, tw1, tb1);
    cudaMemsetAsync(p_t,    0, (size_t)NPTS*128*sizeof(float));
    cudaMemsetAsync(p_tvec, 0, (size_t)BBATCH*1024*sizeof(float));
    cudaMemsetAsync(p_gvec, 0, (size_t)BBATCH*1024*sizeof(float));
    k_mma<3,1,true,2,true><<<dim3(1, EDGE_GY), 256, SM_MMA1>>>(nullptr, 0, tw2, 128, tb2, nullptr, p_t, 64, 128);
    k_mma<1,1,false,2,true><<<dim3(1024/128, NPTS/128), 256, SM_MMA1>>>(p_t, 128, tw3, 1024, tb3, nullptr, p_tvec, 128, 1024);
    k_fc<<<(BBATCH*512 + 127)/128, 128>>>(p_tvec, tfw1, 512, tfb1, p_fc1, 1024, 512, 1);
    k_fc<<<(BBATCH*256 + 127)/128, 128>>>(p_fc1, tfw2, 256, tfb2, p_fc2, 512, 256, 1);
    k_fc<<<1, 128>>>(p_fc2, txw, 9, txb, p_xf, 256, 9, 0);
    k_transform<<<NPTS/256, 256>>>();

    // ---- knn(p) + e1 -> x1 ----
    k_knn<false><<<NPTS/KNN_WPB, 512, SM3D>>>(p_p4);
    k_prep_ab<3><<<NPTS*64/256, 256>>>((const float*)p_p4, 4, e1w1, e1b1);
    cudaMemsetAsync(p_cat, 0, (size_t)NPTS*192*sizeof(float));
    k_mma_e64<<<dim3(1, EDGE_GY), 256, SM_E64>>>(e1w2, e1b2, p_cat + 0, 192);

    // ---- knn(x1) + e2 -> x2 ----
    k_sq64<<<NPTS*32/256, 256>>>(p_cat + 0, 192);
    k_mma<2,3,false,2,false><<<pwgrid, 256, SM_MMA3>>>(p_cat + 0, 192, p_cat + 0, 192, nullptr, nullptr, nullptr, 64, NPT);
    k_knn<true><<<NPTS/KNN_WPB, 512, SMPD>>>(nullptr);
    k_prep_ab<64><<<NPTS*64/256, 256>>>(p_cat + 0, 192, e2w1, e2b1);
    k_mma_e64<<<dim3(1, EDGE_GY), 256, SM_E64>>>(e2w2, e2b2, p_cat + 64, 192);

    // ---- knn(x2) + e3 -> x3 ----
    k_sq64<<<NPTS*32/256, 256>>>(p_cat + 64, 192);
    k_mma<2,3,false,2,false><<<pwgrid, 256, SM_MMA3>>>(p_cat + 64, 192, p_cat + 64, 192, nullptr, nullptr, nullptr, 64, NPT);
    k_knn<true><<<NPTS/KNN_WPB, 512, SMPD>>>(nullptr);
    k_prep_ab<64><<<NPTS*64/256, 256>>>(p_cat + 64, 192, e3w1, e3b1);
    k_edge_e3<<<NPTS*64/256, 256>>>(p_cat + 128, 192);

    // ---- classifier (no knn downstream -> 1xTF32, 2 CTAs/SM) ----
    k_mma<1,1,false,2,true><<<dim3(1024/128, NPTS/128), 256, SM_MMA1>>>(p_cat, 192, c1w, 1024, c1b, nullptr, p_gvec, 192, 1024);
    k_fc<<<(BBATCH*512 + 127)/128, 128>>>(p_gvec, c2w, 512, c2b, p_gterm, 1024, 512, 0);
    k_mma<0,1,false,2,true><<<dim3(512/128, NPTS/128), 256, SM_MMA1>>>(p_cat, 192, c2w + (size_t)1024*512, 512, nullptr, p_gterm, p_c2, 192, 512);
    k_mma<0,1,false,2,true><<<dim3(256/128, NPTS/128), 256, SM_MMA1>>>(p_c2, 512, c3w, 256, c3b, nullptr, p_c3, 512, 256);
    k_c4<<<NPTS*32/256, 256>>>(c4w, c4b, out);
}